// round 3
// baseline (speedup 1.0000x reference)
#include <cuda_runtime.h>
#include <math.h>

#define BATCH 8
#define NSEQ  1024
#define CDIM  768
#define HDIM  12
#define DDIM  64
#define MDIM  128
#define BNTOK (BATCH*NSEQ)          // 8192

// ---------------- scratch (device globals; no allocation allowed) ----------
__device__ float g_qkv[BNTOK * 3 * CDIM];                     // 75.5 MB
__device__ float g_qf [BATCH * HDIM * NSEQ * MDIM];           // 50.3 MB
__device__ float g_kf [BATCH * HDIM * NSEQ * MDIM];           // 50.3 MB
__device__ float g_kv [BATCH * HDIM * (MDIM * DDIM + MDIM)];  // 3.2 MB (KV + S)
__device__ float g_o  [BNTOK * CDIM];                         // 25.2 MB

// ---------------------------------------------------------------------------
// SGEMM: C[M,N] = A[M,K] @ Bw[N,K]^T (+bias). 128x128 tile, BK=8, 256 thr,
// 8x8 per-thread microtile. Requires M,N % 128 == 0, K % 8 == 0 (holds for
// all shapes here: 8192x2304x768 and 8192x768x768).
// ---------------------------------------------------------------------------
template<bool ADD_BIAS>
__global__ __launch_bounds__(256) void sgemm_tn(
    const float* __restrict__ A, const float* __restrict__ Bw,
    const float* __restrict__ bias, float* __restrict__ C,
    int Nd, int Kd)
{
    __shared__ float As[8][128];
    __shared__ float Bs[8][128];
    const int tid  = threadIdx.x;
    const int tx   = tid & 15;
    const int ty   = tid >> 4;
    const int lrow = tid >> 1;
    const int lk   = (tid & 1) * 4;

    const float* Ap = A  + (size_t)(blockIdx.y * 128 + lrow) * Kd + lk;
    const float* Bp = Bw + (size_t)(blockIdx.x * 128 + lrow) * Kd + lk;

    float acc[8][8];
    #pragma unroll
    for (int i = 0; i < 8; i++)
        #pragma unroll
        for (int j = 0; j < 8; j++) acc[i][j] = 0.0f;

    for (int k0 = 0; k0 < Kd; k0 += 8) {
        float4 a4 = *reinterpret_cast<const float4*>(Ap + k0);
        float4 b4 = *reinterpret_cast<const float4*>(Bp + k0);
        __syncthreads();
        As[lk + 0][lrow] = a4.x; As[lk + 1][lrow] = a4.y;
        As[lk + 2][lrow] = a4.z; As[lk + 3][lrow] = a4.w;
        Bs[lk + 0][lrow] = b4.x; Bs[lk + 1][lrow] = b4.y;
        Bs[lk + 2][lrow] = b4.z; Bs[lk + 3][lrow] = b4.w;
        __syncthreads();
        #pragma unroll
        for (int kk = 0; kk < 8; kk++) {
            float a[8], b[8];
            *(float4*)(a)     = *(const float4*)&As[kk][ty * 8];
            *(float4*)(a + 4) = *(const float4*)&As[kk][ty * 8 + 4];
            *(float4*)(b)     = *(const float4*)&Bs[kk][tx * 8];
            *(float4*)(b + 4) = *(const float4*)&Bs[kk][tx * 8 + 4];
            #pragma unroll
            for (int i = 0; i < 8; i++)
                #pragma unroll
                for (int j = 0; j < 8; j++)
                    acc[i][j] += a[i] * b[j];
        }
    }

    #pragma unroll
    for (int i = 0; i < 8; i++) {
        const int row = blockIdx.y * 128 + ty * 8 + i;
        #pragma unroll
        for (int j = 0; j < 8; j += 4) {
            const int col = blockIdx.x * 128 + tx * 8 + j;
            float4 v = make_float4(acc[i][j], acc[i][j+1], acc[i][j+2], acc[i][j+3]);
            if (ADD_BIAS) {
                v.x += bias[col];     v.y += bias[col + 1];
                v.z += bias[col + 2]; v.w += bias[col + 3];
            }
            *reinterpret_cast<float4*>(&C[(size_t)row * Nd + col]) = v;
        }
    }
}

// ---------------------------------------------------------------------------
// Feature map for q AND k: phi = exp(z@R - 0.5*||z||^2) * M^-0.5, z = q*sq.
// Block: 128 threads (one per m). Grid: (B*H, NSEQ/64).
// ---------------------------------------------------------------------------
__global__ __launch_bounds__(128) void feat_kernel(const float* __restrict__ R)
{
    const int bh = blockIdx.x;
    const int b  = bh / HDIM, h = bh % HDIM;
    const int n0 = blockIdx.y * 64;
    const int t  = threadIdx.x;

    __shared__ float Rs[DDIM][MDIM];   // 32 KB
    __shared__ float zq[DDIM], zk[DDIM];

    for (int i = t; i < DDIM * MDIM; i += 128)
        Rs[i >> 7][i & 127] = R[h * DDIM * MDIM + i];

    const float sq   = 0.3535533905932738f;    // 64^-0.25 (sqrt(scale))
    const float minv = 0.08838834764831845f;   // 128^-0.5

    for (int r = 0; r < 64; r++) {
        const int n = n0 + r;
        const size_t base = (size_t)(b * NSEQ + n) * (3 * CDIM) + h * DDIM;
        __syncthreads();   // Rs ready (r==0) / previous-iter z reads done
        if (t < 64) zq[t]      = g_qkv[base + t] * sq;
        else        zk[t - 64] = g_qkv[base + CDIM + (t - 64)] * sq;
        __syncthreads();

        float aq = 0.f, ak = 0.f, sqq = 0.f, sqk = 0.f;
        #pragma unroll 8
        for (int d = 0; d < DDIM; d++) {
            const float qv = zq[d], kv = zk[d], rv = Rs[d][t];
            aq  += qv * rv;  ak  += kv * rv;
            sqq += qv * qv;  sqk += kv * kv;
        }
        const size_t o = ((size_t)bh * NSEQ + n) * MDIM + t;
        g_qf[o] = expf(aq - 0.5f * sqq) * minv;
        g_kf[o] = expf(ak - 0.5f * sqk) * minv;
    }
}

// ---------------------------------------------------------------------------
// KV[m,d] = sum_n kf[n,m]*v[n,d];  S[m] = sum_n kf[n,m].  One block per (b,h).
// 256 threads, each computes 8(m) x 4(d) outputs.
// ---------------------------------------------------------------------------
__global__ __launch_bounds__(256) void kv_kernel()
{
    const int bh = blockIdx.x;
    const int b  = bh / HDIM, h = bh % HDIM;
    const int tm = threadIdx.x >> 4;   // 0..15 -> m rows tm*8..
    const int td = threadIdx.x & 15;   // 0..15 -> d cols td*4..

    __shared__ float kfs[32][MDIM];    // 16 KB
    __shared__ float vs [32][DDIM];    // 8 KB

    float acc[8][4];
    float s[8];
    #pragma unroll
    for (int i = 0; i < 8; i++) {
        s[i] = 0.f;
        #pragma unroll
        for (int j = 0; j < 4; j++) acc[i][j] = 0.f;
    }

    for (int n0 = 0; n0 < NSEQ; n0 += 32) {
        __syncthreads();
        for (int i = threadIdx.x; i < 32 * MDIM; i += 256) {
            const int nn = i >> 7;
            kfs[nn][i & 127] = g_kf[((size_t)bh * NSEQ + n0 + nn) * MDIM + (i & 127)];
        }
        for (int i = threadIdx.x; i < 32 * DDIM; i += 256) {
            const int nn = i >> 6, d = i & 63;
            vs[nn][d] = g_qkv[(size_t)(b * NSEQ + n0 + nn) * (3 * CDIM) + 2 * CDIM + h * DDIM + d];
        }
        __syncthreads();
        #pragma unroll 4
        for (int nn = 0; nn < 32; nn++) {
            float a[8], bb[4];
            #pragma unroll
            for (int i = 0; i < 8; i++) a[i] = kfs[nn][tm * 8 + i];
            #pragma unroll
            for (int j = 0; j < 4; j++) bb[j] = vs[nn][td * 4 + j];
            #pragma unroll
            for (int i = 0; i < 8; i++) {
                s[i] += a[i];
                #pragma unroll
                for (int j = 0; j < 4; j++) acc[i][j] += a[i] * bb[j];
            }
        }
    }

    float* kvb = g_kv + (size_t)bh * (MDIM * DDIM + MDIM);
    #pragma unroll
    for (int i = 0; i < 8; i++) {
        const int m = tm * 8 + i;
        #pragma unroll
        for (int j = 0; j < 4; j++)
            kvb[m * DDIM + td * 4 + j] = acc[i][j];
        if (td == 0) kvb[MDIM * DDIM + m] = s[i];
    }
}

// ---------------------------------------------------------------------------
// out[n,d] = (qf[n]@KV[:,d]) / max(qf[n]@S, eps), written as [b,n,h*64+d].
// Grid: (B*H, NSEQ/16). 256 threads; thread = (row tr, cols tc*4..tc*4+3).
// ---------------------------------------------------------------------------
__global__ __launch_bounds__(256) void out_kernel()
{
    const int bh = blockIdx.x;
    const int b  = bh / HDIM, h = bh % HDIM;
    const int n0 = blockIdx.y * 16;
    const int tr = threadIdx.x >> 4;
    const int tc = threadIdx.x & 15;

    __shared__ float KVs[MDIM][DDIM];      // 32 KB
    __shared__ float Ss [MDIM];
    __shared__ float qfs[16][MDIM + 1];    // +1 pad: kill column-read conflicts

    const float* kvb = g_kv + (size_t)bh * (MDIM * DDIM + MDIM);
    for (int i = threadIdx.x; i < MDIM * DDIM; i += 256) KVs[i >> 6][i & 63] = kvb[i];
    for (int i = threadIdx.x; i < MDIM;        i += 256) Ss[i] = kvb[MDIM * DDIM + i];
    for (int i = threadIdx.x; i < 16 * MDIM;   i += 256) {
        const int rr = i >> 7;
        qfs[rr][i & 127] = g_qf[((size_t)bh * NSEQ + n0 + rr) * MDIM + (i & 127)];
    }
    __syncthreads();

    float acc0 = 0.f, acc1 = 0.f, acc2 = 0.f, acc3 = 0.f, den = 0.f;
    #pragma unroll 8
    for (int m = 0; m < MDIM; m++) {
        const float a = qfs[tr][m];
        const float4 kv = *reinterpret_cast<const float4*>(&KVs[m][tc * 4]);
        acc0 += a * kv.x; acc1 += a * kv.y; acc2 += a * kv.z; acc3 += a * kv.w;
        den  += a * Ss[m];
    }
    const float inv = 1.0f / fmaxf(den, 1e-12f);
    const int n = n0 + tr;
    float4 res = make_float4(acc0 * inv, acc1 * inv, acc2 * inv, acc3 * inv);
    *reinterpret_cast<float4*>(&g_o[(size_t)(b * NSEQ + n) * CDIM + h * DDIM + tc * 4]) = res;
}

// ---------------------------------------------------------------------------
extern "C" void kernel_launch(void* const* d_in, const int* in_sizes, int n_in,
                              void* d_out, int out_size)
{
    const float* x      = (const float*)d_in[0];
    const float* qkv_w  = (const float*)d_in[1];
    const float* proj_w = (const float*)d_in[2];
    const float* proj_b = (const float*)d_in[3];
    const float* randm  = (const float*)d_in[4];
    float* out = (float*)d_out;

    float *p_qkv, *p_o;
    cudaGetSymbolAddress((void**)&p_qkv, g_qkv);
    cudaGetSymbolAddress((void**)&p_o,   g_o);

    // 1) qkv = x @ qkv_w^T : [8192, 2304]
    {
        dim3 grid(3 * CDIM / 128, BNTOK / 128);
        sgemm_tn<false><<<grid, 256>>>(x, qkv_w, nullptr, p_qkv, 3 * CDIM, CDIM);
    }
    // 2) feature maps qf, kf
    {
        dim3 grid(BATCH * HDIM, NSEQ / 64);
        feat_kernel<<<grid, 128>>>(randm);
    }
    // 3) KV + S reduction
    kv_kernel<<<BATCH * HDIM, 256>>>();
    // 4) normalized output, relayout to [b, n, c]
    {
        dim3 grid(BATCH * HDIM, NSEQ / 16);
        out_kernel<<<grid, 256>>>();
    }
    // 5) final projection + bias -> d_out
    {
        dim3 grid(CDIM / 128, BNTOK / 128);
        sgemm_tn<true><<<grid, 256>>>(p_o, proj_w, proj_b, out, CDIM, CDIM);
    }
}

// round 4
// speedup vs baseline: 1.4297x; 1.4297x over previous
#include <cuda_runtime.h>
#include <math.h>

#define BATCH 8
#define NSEQ  1024
#define CDIM  768
#define HDIM  12
#define DDIM  64
#define MDIM  128
#define BNTOK (BATCH*NSEQ)          // 8192
#define KVSZ  (MDIM*DDIM + MDIM)    // 8320 floats per (b,h): KV + S
#define NSPLIT 8

// ---------------- scratch (device globals; no allocation allowed) ----------
__device__ float g_qkv[BNTOK * 3 * CDIM];                     // 75.5 MB
__device__ float g_qf [BATCH * HDIM * NSEQ * MDIM];           // 50.3 MB
__device__ float g_kf [BATCH * HDIM * NSEQ * MDIM];           // 50.3 MB
__device__ float g_kvp[NSPLIT * BATCH * HDIM * KVSZ];         // 25.5 MB partials
__device__ float g_kv [BATCH * HDIM * KVSZ];                  // 3.2 MB
__device__ float g_o  [BNTOK * CDIM];                         // 25.2 MB

// ---------------------------------------------------------------------------
// SGEMM: C[M,N] = A[M,K] @ Bw[N,K]^T (+bias). 128x128 tile, BK=8, 256 thr,
// 8x8 microtile, 2-stage smem double buffering (1 __syncthreads per k-step).
// ---------------------------------------------------------------------------
template<bool ADD_BIAS>
__global__ __launch_bounds__(256) void sgemm_tn(
    const float* __restrict__ A, const float* __restrict__ Bw,
    const float* __restrict__ bias, float* __restrict__ C,
    int Nd, int Kd)
{
    __shared__ float As[2][8][128];
    __shared__ float Bs[2][8][128];
    const int tid  = threadIdx.x;
    const int tx   = tid & 15;
    const int ty   = tid >> 4;
    const int lrow = tid >> 1;
    const int lk   = (tid & 1) * 4;

    const float* Ap = A  + (size_t)(blockIdx.y * 128 + lrow) * Kd + lk;
    const float* Bp = Bw + (size_t)(blockIdx.x * 128 + lrow) * Kd + lk;

    float acc[8][8];
    #pragma unroll
    for (int i = 0; i < 8; i++)
        #pragma unroll
        for (int j = 0; j < 8; j++) acc[i][j] = 0.0f;

    float4 a4 = *reinterpret_cast<const float4*>(Ap);
    float4 b4 = *reinterpret_cast<const float4*>(Bp);
    As[0][lk+0][lrow] = a4.x; As[0][lk+1][lrow] = a4.y;
    As[0][lk+2][lrow] = a4.z; As[0][lk+3][lrow] = a4.w;
    Bs[0][lk+0][lrow] = b4.x; Bs[0][lk+1][lrow] = b4.y;
    Bs[0][lk+2][lrow] = b4.z; Bs[0][lk+3][lrow] = b4.w;
    __syncthreads();

    int buf = 0;
    for (int k0 = 8; k0 < Kd + 8; k0 += 8) {
        if (k0 < Kd) {
            a4 = *reinterpret_cast<const float4*>(Ap + k0);
            b4 = *reinterpret_cast<const float4*>(Bp + k0);
        }
        #pragma unroll
        for (int kk = 0; kk < 8; kk++) {
            float a[8], b[8];
            *(float4*)(a)     = *(const float4*)&As[buf][kk][ty * 8];
            *(float4*)(a + 4) = *(const float4*)&As[buf][kk][ty * 8 + 4];
            *(float4*)(b)     = *(const float4*)&Bs[buf][kk][tx * 8];
            *(float4*)(b + 4) = *(const float4*)&Bs[buf][kk][tx * 8 + 4];
            #pragma unroll
            for (int i = 0; i < 8; i++)
                #pragma unroll
                for (int j = 0; j < 8; j++)
                    acc[i][j] += a[i] * b[j];
        }
        if (k0 < Kd) {
            buf ^= 1;
            As[buf][lk+0][lrow] = a4.x; As[buf][lk+1][lrow] = a4.y;
            As[buf][lk+2][lrow] = a4.z; As[buf][lk+3][lrow] = a4.w;
            Bs[buf][lk+0][lrow] = b4.x; Bs[buf][lk+1][lrow] = b4.y;
            Bs[buf][lk+2][lrow] = b4.z; Bs[buf][lk+3][lrow] = b4.w;
            __syncthreads();
        }
    }

    #pragma unroll
    for (int i = 0; i < 8; i++) {
        const int row = blockIdx.y * 128 + ty * 8 + i;
        #pragma unroll
        for (int j = 0; j < 8; j += 4) {
            const int col = blockIdx.x * 128 + tx * 8 + j;
            float4 v = make_float4(acc[i][j], acc[i][j+1], acc[i][j+2], acc[i][j+3]);
            if (ADD_BIAS) {
                v.x += bias[col];     v.y += bias[col + 1];
                v.z += bias[col + 2]; v.w += bias[col + 3];
            }
            *reinterpret_cast<float4*>(&C[(size_t)row * Nd + col]) = v;
        }
    }
}

// ---------------------------------------------------------------------------
// Feature map q AND k: phi = exp(z@R - 0.5*||z||^2) * M^-0.5, z = q*sq.
// 256 threads, 16 rows staged per block, 2x4 microtile, one sync.
// Grid: (B*H, NSEQ/16).
// ---------------------------------------------------------------------------
__global__ __launch_bounds__(256) void feat_kernel(const float* __restrict__ R)
{
    const int bh = blockIdx.x;
    const int b  = bh / HDIM, h = bh % HDIM;
    const int n0 = blockIdx.y * 16;
    const int tid  = threadIdx.x;
    const int lane = tid & 31;       // m-group: cols lane*4 .. +3
    const int wrp  = tid >> 5;       // row-group: rows wrp*2, wrp*2+1

    __shared__ float Rs[DDIM][MDIM];     // 32 KB
    __shared__ float zq[16][DDIM];       // 4 KB
    __shared__ float zk[16][DDIM];       // 4 KB

    const float sq   = 0.3535533905932738f;    // 64^-0.25
    const float minv = 0.08838834764831845f;   // 128^-0.5

    // load R (8 float4 per thread)
    #pragma unroll
    for (int i = tid; i < DDIM * MDIM / 4; i += 256) {
        float4 r4 = *reinterpret_cast<const float4*>(&R[h * DDIM * MDIM + i * 4]);
        *reinterpret_cast<float4*>(&Rs[0][0] + i * 4) = r4;
    }
    // load z tiles: 16 rows x 16 float4 for q and k (1 f4 each per thread)
    {
        const int r = tid >> 4, d4 = (tid & 15) * 4;
        const size_t base = (size_t)(b * NSEQ + n0 + r) * (3 * CDIM) + h * DDIM + d4;
        float4 q4 = *reinterpret_cast<const float4*>(&g_qkv[base]);
        float4 k4 = *reinterpret_cast<const float4*>(&g_qkv[base + CDIM]);
        q4.x *= sq; q4.y *= sq; q4.z *= sq; q4.w *= sq;
        k4.x *= sq; k4.y *= sq; k4.z *= sq; k4.w *= sq;
        *reinterpret_cast<float4*>(&zq[r][d4]) = q4;
        *reinterpret_cast<float4*>(&zk[r][d4]) = k4;
    }
    __syncthreads();

    float aq[2][4], ak[2][4], nq[2], nk[2];
    #pragma unroll
    for (int i = 0; i < 2; i++) {
        nq[i] = 0.f; nk[i] = 0.f;
        #pragma unroll
        for (int j = 0; j < 4; j++) { aq[i][j] = 0.f; ak[i][j] = 0.f; }
    }

    #pragma unroll 8
    for (int d = 0; d < DDIM; d++) {
        const float4 r4 = *reinterpret_cast<const float4*>(&Rs[d][lane * 4]);
        #pragma unroll
        for (int i = 0; i < 2; i++) {
            const float qv = zq[wrp * 2 + i][d];
            const float kv = zk[wrp * 2 + i][d];
            aq[i][0] += qv * r4.x; aq[i][1] += qv * r4.y;
            aq[i][2] += qv * r4.z; aq[i][3] += qv * r4.w;
            ak[i][0] += kv * r4.x; ak[i][1] += kv * r4.y;
            ak[i][2] += kv * r4.z; ak[i][3] += kv * r4.w;
            nq[i] += qv * qv;      nk[i] += kv * kv;
        }
    }

    #pragma unroll
    for (int i = 0; i < 2; i++) {
        const int n = n0 + wrp * 2 + i;
        const size_t o = ((size_t)bh * NSEQ + n) * MDIM + lane * 4;
        const float hq = 0.5f * nq[i], hk = 0.5f * nk[i];
        float4 fq = make_float4(expf(aq[i][0]-hq)*minv, expf(aq[i][1]-hq)*minv,
                                expf(aq[i][2]-hq)*minv, expf(aq[i][3]-hq)*minv);
        float4 fk = make_float4(expf(ak[i][0]-hk)*minv, expf(ak[i][1]-hk)*minv,
                                expf(ak[i][2]-hk)*minv, expf(ak[i][3]-hk)*minv);
        *reinterpret_cast<float4*>(&g_qf[o]) = fq;
        *reinterpret_cast<float4*>(&g_kf[o]) = fk;
    }
}

// ---------------------------------------------------------------------------
// Partial KV[m,d] = sum_n kf[n,m]*v[n,d]; S[m] = sum_n kf[n,m].
// Grid: (B*H, NSPLIT); each block reduces 128 sequence rows.
// ---------------------------------------------------------------------------
__global__ __launch_bounds__(256) void kv_kernel()
{
    const int bh = blockIdx.x;
    const int b  = bh / HDIM, h = bh % HDIM;
    const int p  = blockIdx.y;
    const int tm = threadIdx.x >> 4;
    const int td = threadIdx.x & 15;

    __shared__ float kfs[32][MDIM];    // 16 KB
    __shared__ float vs [32][DDIM];    // 8 KB

    float acc[8][4];
    float s[8];
    #pragma unroll
    for (int i = 0; i < 8; i++) {
        s[i] = 0.f;
        #pragma unroll
        for (int j = 0; j < 4; j++) acc[i][j] = 0.f;
    }

    const int nbase = p * (NSEQ / NSPLIT);
    for (int n0 = nbase; n0 < nbase + NSEQ / NSPLIT; n0 += 32) {
        __syncthreads();
        #pragma unroll
        for (int i = threadIdx.x; i < 32 * MDIM / 4; i += 256) {
            const int nn = i >> 5, m4 = (i & 31) * 4;
            *reinterpret_cast<float4*>(&kfs[nn][m4]) =
                *reinterpret_cast<const float4*>(&g_kf[((size_t)bh * NSEQ + n0 + nn) * MDIM + m4]);
        }
        #pragma unroll
        for (int i = threadIdx.x; i < 32 * DDIM / 4; i += 256) {
            const int nn = i >> 4, d4 = (i & 15) * 4;
            *reinterpret_cast<float4*>(&vs[nn][d4]) =
                *reinterpret_cast<const float4*>(
                    &g_qkv[(size_t)(b * NSEQ + n0 + nn) * (3 * CDIM) + 2 * CDIM + h * DDIM + d4]);
        }
        __syncthreads();
        #pragma unroll 4
        for (int nn = 0; nn < 32; nn++) {
            float a[8], bb[4];
            #pragma unroll
            for (int i = 0; i < 8; i++) a[i] = kfs[nn][tm * 8 + i];
            #pragma unroll
            for (int j = 0; j < 4; j++) bb[j] = vs[nn][td * 4 + j];
            #pragma unroll
            for (int i = 0; i < 8; i++) {
                s[i] += a[i];
                #pragma unroll
                for (int j = 0; j < 4; j++) acc[i][j] += a[i] * bb[j];
            }
        }
    }

    float* kvb = g_kvp + ((size_t)p * (BATCH * HDIM) + bh) * KVSZ;
    #pragma unroll
    for (int i = 0; i < 8; i++) {
        const int m = tm * 8 + i;
        *reinterpret_cast<float4*>(&kvb[m * DDIM + td * 4]) =
            make_float4(acc[i][0], acc[i][1], acc[i][2], acc[i][3]);
        if (td == 0) kvb[MDIM * DDIM + m] = s[i];
    }
}

__global__ __launch_bounds__(256) void kv_reduce()
{
    const int i = blockIdx.x * 256 + threadIdx.x;
    if (i < BATCH * HDIM * KVSZ) {
        float s = 0.f;
        #pragma unroll
        for (int pp = 0; pp < NSPLIT; pp++)
            s += g_kvp[(size_t)pp * (BATCH * HDIM * KVSZ) + i];
        g_kv[i] = s;
    }
}

// ---------------------------------------------------------------------------
// out[n,d] = (qf[n]@KV[:,d]) / max(qf[n]@S, eps). 64 rows x 64 cols per block,
// 4x4 microtile, dynamic smem (KV 32K + S + padded qf tile).
// Grid: (B*H, NSEQ/64).
// ---------------------------------------------------------------------------
#define QF_PITCH 132
#define OUT_SMEM_FLOATS (KVSZ + 64 * QF_PITCH)

__global__ __launch_bounds__(256) void out_kernel()
{
    extern __shared__ float osm[];   // [0,8192): KV  [8192,8320): S  [8320,..): qf
    const int bh = blockIdx.x;
    const int b  = bh / HDIM, h = bh % HDIM;
    const int n0 = blockIdx.y * 64;
    const int tr = threadIdx.x >> 4;   // rows tr*4 .. +3
    const int tc = threadIdx.x & 15;   // cols tc*4 .. +3

    const float* kvb = g_kv + (size_t)bh * KVSZ;
    #pragma unroll
    for (int i = threadIdx.x; i < KVSZ / 4; i += 256)
        *reinterpret_cast<float4*>(&osm[i * 4]) =
            *reinterpret_cast<const float4*>(&kvb[i * 4]);
    #pragma unroll
    for (int i = threadIdx.x; i < 64 * 32; i += 256) {
        const int r = i >> 5, d4 = (i & 31) * 4;
        *reinterpret_cast<float4*>(&osm[KVSZ + r * QF_PITCH + d4]) =
            *reinterpret_cast<const float4*>(&g_qf[((size_t)bh * NSEQ + n0 + r) * MDIM + d4]);
    }
    __syncthreads();

    float acc[4][4], den[4];
    #pragma unroll
    for (int i = 0; i < 4; i++) {
        den[i] = 0.f;
        #pragma unroll
        for (int j = 0; j < 4; j++) acc[i][j] = 0.f;
    }

    #pragma unroll 4
    for (int m = 0; m < MDIM; m++) {
        const float4 kv = *reinterpret_cast<const float4*>(&osm[m * DDIM + tc * 4]);
        const float sv = osm[MDIM * DDIM + m];
        #pragma unroll
        for (int i = 0; i < 4; i++) {
            const float q = osm[KVSZ + (tr * 4 + i) * QF_PITCH + m];
            acc[i][0] += q * kv.x; acc[i][1] += q * kv.y;
            acc[i][2] += q * kv.z; acc[i][3] += q * kv.w;
            den[i]    += q * sv;
        }
    }

    #pragma unroll
    for (int i = 0; i < 4; i++) {
        const float inv = 1.0f / fmaxf(den[i], 1e-12f);
        const int n = n0 + tr * 4 + i;
        float4 res = make_float4(acc[i][0]*inv, acc[i][1]*inv, acc[i][2]*inv, acc[i][3]*inv);
        *reinterpret_cast<float4*>(&g_o[(size_t)(b * NSEQ + n) * CDIM + h * DDIM + tc * 4]) = res;
    }
}

// ---------------------------------------------------------------------------
extern "C" void kernel_launch(void* const* d_in, const int* in_sizes, int n_in,
                              void* d_out, int out_size)
{
    const float* x      = (const float*)d_in[0];
    const float* qkv_w  = (const float*)d_in[1];
    const float* proj_w = (const float*)d_in[2];
    const float* proj_b = (const float*)d_in[3];
    const float* randm  = (const float*)d_in[4];
    float* out = (float*)d_out;

    float *p_qkv, *p_o;
    cudaGetSymbolAddress((void**)&p_qkv, g_qkv);
    cudaGetSymbolAddress((void**)&p_o,   g_o);

    cudaFuncSetAttribute(out_kernel, cudaFuncAttributeMaxDynamicSharedMemorySize,
                         OUT_SMEM_FLOATS * 4);

    // 1) qkv = x @ qkv_w^T : [8192, 2304]
    {
        dim3 grid(3 * CDIM / 128, BNTOK / 128);
        sgemm_tn<false><<<grid, 256>>>(x, qkv_w, nullptr, p_qkv, 3 * CDIM, CDIM);
    }
    // 2) feature maps qf, kf
    {
        dim3 grid(BATCH * HDIM, NSEQ / 16);
        feat_kernel<<<grid, 256>>>(randm);
    }
    // 3) KV + S partial reduction, then merge
    {
        dim3 grid(BATCH * HDIM, NSPLIT);
        kv_kernel<<<grid, 256>>>();
        kv_reduce<<<(BATCH * HDIM * KVSZ + 255) / 256, 256>>>();
    }
    // 4) normalized output, relayout to [b, n, c]
    {
        dim3 grid(BATCH * HDIM, NSEQ / 64);
        out_kernel<<<grid, 256, OUT_SMEM_FLOATS * 4>>>();
    }
    // 5) final projection + bias -> d_out
    {
        dim3 grid(CDIM / 128, BNTOK / 128);
        sgemm_tn<true><<<grid, 256>>>(p_o, proj_w, proj_b, out, CDIM, CDIM);
    }
}

// round 6
// speedup vs baseline: 1.4752x; 1.0318x over previous
#include <cuda_runtime.h>
#include <math.h>

#define BATCH 8
#define NSEQ  1024
#define CDIM  768
#define HDIM  12
#define DDIM  64
#define MDIM  128
#define BNTOK (BATCH*NSEQ)          // 8192
#define KVSZ  (MDIM*DDIM + MDIM)    // 8320 floats per (b,h): KV + S
#define NSPLIT 8

typedef unsigned long long ull;

// ---- packed fp32x2 helpers (Blackwell FFMA2: 2x fp32 FMA throughput) ------
__device__ __forceinline__ ull pack_dup(float x) {
    ull r; asm("mov.b64 %0, {%1, %1};" : "=l"(r) : "f"(x)); return r;
}
__device__ __forceinline__ void ffma2(ull& acc, ull a, ull b) {
    asm("fma.rn.f32x2 %0, %1, %2, %0;" : "+l"(acc) : "l"(a), "l"(b));
}
__device__ __forceinline__ float2 unpack2(ull v) {
    float2 r; asm("mov.b64 {%0, %1}, %2;" : "=f"(r.x), "=f"(r.y) : "l"(v)); return r;
}

// ---------------- scratch (device globals; no allocation allowed) ----------
__device__ float g_qkv[BNTOK * 3 * CDIM];                     // 75.5 MB
__device__ float g_qf [BATCH * HDIM * NSEQ * MDIM];           // 50.3 MB
__device__ float g_kf [BATCH * HDIM * NSEQ * MDIM];           // 50.3 MB
__device__ float g_kvp[NSPLIT * BATCH * HDIM * KVSZ];         // 25.5 MB partials
__device__ float g_kv [BATCH * HDIM * KVSZ];                  // 3.2 MB
__device__ float g_o  [BNTOK * CDIM];                         // 25.2 MB

// ---------------------------------------------------------------------------
// SGEMM: C[M,N] = A[M,K] @ Bw[N,K]^T (+bias). 128x128 tile, BK=8, 256 thr,
// 8x8 microtile computed as 4x8 packed f32x2 row-pairs, double-buffered smem.
// ---------------------------------------------------------------------------
template<bool ADD_BIAS>
__global__ __launch_bounds__(256) void sgemm_tn(
    const float* __restrict__ A, const float* __restrict__ Bw,
    const float* __restrict__ bias, float* __restrict__ C,
    int Nd, int Kd)
{
    __shared__ float As[2][8][128];
    __shared__ float Bs[2][8][128];
    const int tid  = threadIdx.x;
    const int tx   = tid & 15;
    const int ty   = tid >> 4;
    const int lrow = tid >> 1;
    const int lk   = (tid & 1) * 4;

    const float* Ap = A  + (size_t)(blockIdx.y * 128 + lrow) * Kd + lk;
    const float* Bp = Bw + (size_t)(blockIdx.x * 128 + lrow) * Kd + lk;

    ull acc[4][8];                     // row-pairs (2 rows) x 8 cols
    #pragma unroll
    for (int i = 0; i < 4; i++)
        #pragma unroll
        for (int j = 0; j < 8; j++) acc[i][j] = 0ULL;

    float4 a4 = *reinterpret_cast<const float4*>(Ap);
    float4 b4 = *reinterpret_cast<const float4*>(Bp);
    As[0][lk+0][lrow] = a4.x; As[0][lk+1][lrow] = a4.y;
    As[0][lk+2][lrow] = a4.z; As[0][lk+3][lrow] = a4.w;
    Bs[0][lk+0][lrow] = b4.x; Bs[0][lk+1][lrow] = b4.y;
    Bs[0][lk+2][lrow] = b4.z; Bs[0][lk+3][lrow] = b4.w;
    __syncthreads();

    int buf = 0;
    for (int k0 = 8; k0 < Kd + 8; k0 += 8) {
        if (k0 < Kd) {
            a4 = *reinterpret_cast<const float4*>(Ap + k0);
            b4 = *reinterpret_cast<const float4*>(Bp + k0);
        }
        #pragma unroll
        for (int kk = 0; kk < 8; kk++) {
            // A row-pairs: 4 native 64-bit pairs (2x LDS.128 underneath)
            longlong2 apA = *reinterpret_cast<const longlong2*>(&As[buf][kk][ty * 8]);
            longlong2 apB = *reinterpret_cast<const longlong2*>(&As[buf][kk][ty * 8 + 4]);
            ull ap[4] = { (ull)apA.x, (ull)apA.y, (ull)apB.x, (ull)apB.y };
            float b[8];
            *(float4*)(b)     = *(const float4*)&Bs[buf][kk][tx * 8];
            *(float4*)(b + 4) = *(const float4*)&Bs[buf][kk][tx * 8 + 4];
            ull bd[8];
            #pragma unroll
            for (int j = 0; j < 8; j++) bd[j] = pack_dup(b[j]);
            #pragma unroll
            for (int i = 0; i < 4; i++)
                #pragma unroll
                for (int j = 0; j < 8; j++)
                    ffma2(acc[i][j], ap[i], bd[j]);
        }
        if (k0 < Kd) {
            buf ^= 1;
            As[buf][lk+0][lrow] = a4.x; As[buf][lk+1][lrow] = a4.y;
            As[buf][lk+2][lrow] = a4.z; As[buf][lk+3][lrow] = a4.w;
            Bs[buf][lk+0][lrow] = b4.x; Bs[buf][lk+1][lrow] = b4.y;
            Bs[buf][lk+2][lrow] = b4.z; Bs[buf][lk+3][lrow] = b4.w;
            __syncthreads();
        }
    }

    #pragma unroll
    for (int i2 = 0; i2 < 4; i2++) {
        #pragma unroll
        for (int half = 0; half < 2; half++) {
            const int row = blockIdx.y * 128 + ty * 8 + i2 * 2 + half;
            #pragma unroll
            for (int j = 0; j < 8; j += 4) {
                const int col = blockIdx.x * 128 + tx * 8 + j;
                float2 p0 = unpack2(acc[i2][j]);
                float2 p1 = unpack2(acc[i2][j+1]);
                float2 p2 = unpack2(acc[i2][j+2]);
                float2 p3 = unpack2(acc[i2][j+3]);
                float4 v = half
                    ? make_float4(p0.y, p1.y, p2.y, p3.y)
                    : make_float4(p0.x, p1.x, p2.x, p3.x);
                if (ADD_BIAS) {
                    v.x += bias[col];     v.y += bias[col + 1];
                    v.z += bias[col + 2]; v.w += bias[col + 3];
                }
                *reinterpret_cast<float4*>(&C[(size_t)row * Nd + col]) = v;
            }
        }
    }
}

// ---------------------------------------------------------------------------
// Feature map q AND k: phi = exp(z@R - 0.5*||z||^2) * M^-0.5, z = q*sq.
// 256 threads, 16 rows staged, 2x4 microtile (f32x2 over m), one sync.
// Grid: (B*H, NSEQ/16).
// ---------------------------------------------------------------------------
__global__ __launch_bounds__(256) void feat_kernel(const float* __restrict__ R)
{
    const int bh = blockIdx.x;
    const int b  = bh / HDIM, h = bh % HDIM;
    const int n0 = blockIdx.y * 16;
    const int tid  = threadIdx.x;
    const int lane = tid & 31;       // m-group: cols lane*4 .. +3
    const int wrp  = tid >> 5;       // row-group: rows wrp*2, wrp*2+1

    __shared__ float Rs[DDIM][MDIM];     // 32 KB
    __shared__ float zq[16][DDIM];
    __shared__ float zk[16][DDIM];

    const float sq   = 0.3535533905932738f;    // 64^-0.25
    const float minv = 0.08838834764831845f;   // 128^-0.5

    #pragma unroll
    for (int i = tid; i < DDIM * MDIM / 4; i += 256) {
        float4 r4 = *reinterpret_cast<const float4*>(&R[h * DDIM * MDIM + i * 4]);
        *reinterpret_cast<float4*>(&Rs[0][0] + i * 4) = r4;
    }
    {
        const int r = tid >> 4, d4 = (tid & 15) * 4;
        const size_t base = (size_t)(b * NSEQ + n0 + r) * (3 * CDIM) + h * DDIM + d4;
        float4 q4 = *reinterpret_cast<const float4*>(&g_qkv[base]);
        float4 k4 = *reinterpret_cast<const float4*>(&g_qkv[base + CDIM]);
        q4.x *= sq; q4.y *= sq; q4.z *= sq; q4.w *= sq;
        k4.x *= sq; k4.y *= sq; k4.z *= sq; k4.w *= sq;
        *reinterpret_cast<float4*>(&zq[r][d4]) = q4;
        *reinterpret_cast<float4*>(&zk[r][d4]) = k4;
    }
    __syncthreads();

    ull aq[2][2], ak[2][2];            // [row][m-pair]
    float nq[2], nk[2];
    #pragma unroll
    for (int i = 0; i < 2; i++) {
        nq[i] = 0.f; nk[i] = 0.f;
        aq[i][0] = aq[i][1] = 0ULL;
        ak[i][0] = ak[i][1] = 0ULL;
    }

    #pragma unroll 8
    for (int d = 0; d < DDIM; d++) {
        longlong2 rp = *reinterpret_cast<const longlong2*>(&Rs[d][lane * 4]);
        #pragma unroll
        for (int i = 0; i < 2; i++) {
            const float qv = zq[wrp * 2 + i][d];
            const float kv = zk[wrp * 2 + i][d];
            const ull qd = pack_dup(qv), kd = pack_dup(kv);
            ffma2(aq[i][0], qd, (ull)rp.x); ffma2(aq[i][1], qd, (ull)rp.y);
            ffma2(ak[i][0], kd, (ull)rp.x); ffma2(ak[i][1], kd, (ull)rp.y);
            nq[i] += qv * qv;           nk[i] += kv * kv;
        }
    }

    #pragma unroll
    for (int i = 0; i < 2; i++) {
        const int n = n0 + wrp * 2 + i;
        const size_t o = ((size_t)bh * NSEQ + n) * MDIM + lane * 4;
        const float hq = 0.5f * nq[i], hk = 0.5f * nk[i];
        float2 q0 = unpack2(aq[i][0]), q1 = unpack2(aq[i][1]);
        float2 k0 = unpack2(ak[i][0]), k1 = unpack2(ak[i][1]);
        float4 fq = make_float4(expf(q0.x-hq)*minv, expf(q0.y-hq)*minv,
                                expf(q1.x-hq)*minv, expf(q1.y-hq)*minv);
        float4 fk = make_float4(expf(k0.x-hk)*minv, expf(k0.y-hk)*minv,
                                expf(k1.x-hk)*minv, expf(k1.y-hk)*minv);
        *reinterpret_cast<float4*>(&g_qf[o]) = fq;
        *reinterpret_cast<float4*>(&g_kf[o]) = fk;
    }
}

// ---------------------------------------------------------------------------
// Partial KV[m,d] = sum_n kf[n,m]*v[n,d]; S[m] = sum_n kf[n,m].
// Grid: (B*H, NSPLIT); each block reduces 128 sequence rows.
// ---------------------------------------------------------------------------
__global__ __launch_bounds__(256) void kv_kernel()
{
    const int bh = blockIdx.x;
    const int b  = bh / HDIM, h = bh % HDIM;
    const int p  = blockIdx.y;
    const int tm = threadIdx.x >> 4;
    const int td = threadIdx.x & 15;

    __shared__ float kfs[32][MDIM];    // 16 KB
    __shared__ float vs [32][DDIM];    // 8 KB

    ull acc[8][2];                     // 8 m-rows x 2 d-pairs
    float s[8];
    #pragma unroll
    for (int i = 0; i < 8; i++) { s[i] = 0.f; acc[i][0] = acc[i][1] = 0ULL; }

    const int nbase = p * (NSEQ / NSPLIT);
    for (int n0 = nbase; n0 < nbase + NSEQ / NSPLIT; n0 += 32) {
        __syncthreads();
        #pragma unroll
        for (int i = threadIdx.x; i < 32 * MDIM / 4; i += 256) {
            const int nn = i >> 5, m4 = (i & 31) * 4;
            *reinterpret_cast<float4*>(&kfs[nn][m4]) =
                *reinterpret_cast<const float4*>(&g_kf[((size_t)bh * NSEQ + n0 + nn) * MDIM + m4]);
        }
        #pragma unroll
        for (int i = threadIdx.x; i < 32 * DDIM / 4; i += 256) {
            const int nn = i >> 4, d4 = (i & 15) * 4;
            *reinterpret_cast<float4*>(&vs[nn][d4]) =
                *reinterpret_cast<const float4*>(
                    &g_qkv[(size_t)(b * NSEQ + n0 + nn) * (3 * CDIM) + 2 * CDIM + h * DDIM + d4]);
        }
        __syncthreads();
        #pragma unroll 4
        for (int nn = 0; nn < 32; nn++) {
            float a[8];
            #pragma unroll
            for (int i = 0; i < 8; i++) a[i] = kfs[nn][tm * 8 + i];
            longlong2 bp = *reinterpret_cast<const longlong2*>(&vs[nn][td * 4]);
            #pragma unroll
            for (int i = 0; i < 8; i++) {
                const ull ad = pack_dup(a[i]);
                ffma2(acc[i][0], ad, (ull)bp.x);
                ffma2(acc[i][1], ad, (ull)bp.y);
                s[i] += a[i];
            }
        }
    }

    float* kvb = g_kvp + ((size_t)p * (BATCH * HDIM) + bh) * KVSZ;
    #pragma unroll
    for (int i = 0; i < 8; i++) {
        const int m = tm * 8 + i;
        float2 p0 = unpack2(acc[i][0]), p1 = unpack2(acc[i][1]);
        *reinterpret_cast<float4*>(&kvb[m * DDIM + td * 4]) =
            make_float4(p0.x, p0.y, p1.x, p1.y);
        if (td == 0) kvb[MDIM * DDIM + m] = s[i];
    }
}

__global__ __launch_bounds__(256) void kv_reduce()
{
    const int i = blockIdx.x * 256 + threadIdx.x;
    if (i < BATCH * HDIM * KVSZ) {
        float s = 0.f;
        #pragma unroll
        for (int pp = 0; pp < NSPLIT; pp++)
            s += g_kvp[(size_t)pp * (BATCH * HDIM * KVSZ) + i];
        g_kv[i] = s;
    }
}

// ---------------------------------------------------------------------------
// out[n,d] = (qf[n]@KV[:,d]) / max(qf[n]@S, eps). 64 rows x 64 cols per block,
// 4x4 microtile (f32x2 over d), dynamic smem.
// Grid: (B*H, NSEQ/64).
// ---------------------------------------------------------------------------
#define QF_PITCH 132
#define OUT_SMEM_FLOATS (KVSZ + 64 * QF_PITCH)

__global__ __launch_bounds__(256) void out_kernel()
{
    extern __shared__ float osm[];   // [0,8192): KV  [8192,8320): S  [8320,..): qf
    const int bh = blockIdx.x;
    const int b  = bh / HDIM, h = bh % HDIM;
    const int n0 = blockIdx.y * 64;
    const int tr = threadIdx.x >> 4;   // rows tr*4 .. +3
    const int tc = threadIdx.x & 15;   // cols tc*4 .. +3

    const float* kvb = g_kv + (size_t)bh * KVSZ;
    #pragma unroll
    for (int i = threadIdx.x; i < KVSZ / 4; i += 256)
        *reinterpret_cast<float4*>(&osm[i * 4]) =
            *reinterpret_cast<const float4*>(&kvb[i * 4]);
    #pragma unroll
    for (int i = threadIdx.x; i < 64 * 32; i += 256) {
        const int r = i >> 5, d4 = (i & 31) * 4;
        *reinterpret_cast<float4*>(&osm[KVSZ + r * QF_PITCH + d4]) =
            *reinterpret_cast<const float4*>(&g_qf[((size_t)bh * NSEQ + n0 + r) * MDIM + d4]);
    }
    __syncthreads();

    ull acc[4][2];                     // 4 rows x 2 d-pairs
    float den[4];
    #pragma unroll
    for (int i = 0; i < 4; i++) { den[i] = 0.f; acc[i][0] = acc[i][1] = 0ULL; }

    #pragma unroll 4
    for (int m = 0; m < MDIM; m++) {
        longlong2 kvp = *reinterpret_cast<const longlong2*>(&osm[m * DDIM + tc * 4]);
        const float sv = osm[MDIM * DDIM + m];
        #pragma unroll
        for (int i = 0; i < 4; i++) {
            const float q = osm[KVSZ + (tr * 4 + i) * QF_PITCH + m];
            const ull qd = pack_dup(q);
            ffma2(acc[i][0], qd, (ull)kvp.x);
            ffma2(acc[i][1], qd, (ull)kvp.y);
            den[i] += q * sv;
        }
    }

    #pragma unroll
    for (int i = 0; i < 4; i++) {
        const float inv = 1.0f / fmaxf(den[i], 1e-12f);
        const int n = n0 + tr * 4 + i;
        float2 p0 = unpack2(acc[i][0]), p1 = unpack2(acc[i][1]);
        float4 res = make_float4(p0.x*inv, p0.y*inv, p1.x*inv, p1.y*inv);
        *reinterpret_cast<float4*>(&g_o[(size_t)(b * NSEQ + n) * CDIM + h * DDIM + tc * 4]) = res;
    }
}

// ---------------------------------------------------------------------------
extern "C" void kernel_launch(void* const* d_in, const int* in_sizes, int n_in,
                              void* d_out, int out_size)
{
    const float* x      = (const float*)d_in[0];
    const float* qkv_w  = (const float*)d_in[1];
    const float* proj_w = (const float*)d_in[2];
    const float* proj_b = (const float*)d_in[3];
    const float* randm  = (const float*)d_in[4];
    float* out = (float*)d_out;

    float *p_qkv, *p_o;
    cudaGetSymbolAddress((void**)&p_qkv, g_qkv);
    cudaGetSymbolAddress((void**)&p_o,   g_o);

    cudaFuncSetAttribute(out_kernel, cudaFuncAttributeMaxDynamicSharedMemorySize,
                         OUT_SMEM_FLOATS * 4);

    // 1) qkv = x @ qkv_w^T : [8192, 2304]
    {
        dim3 grid(3 * CDIM / 128, BNTOK / 128);
        sgemm_tn<false><<<grid, 256>>>(x, qkv_w, nullptr, p_qkv, 3 * CDIM, CDIM);
    }
    // 2) feature maps qf, kf
    {
        dim3 grid(BATCH * HDIM, NSEQ / 16);
        feat_kernel<<<grid, 256>>>(randm);
    }
    // 3) KV + S partial reduction, then merge
    {
        dim3 grid(BATCH * HDIM, NSPLIT);
        kv_kernel<<<grid, 256>>>();
        kv_reduce<<<(BATCH * HDIM * KVSZ + 255) / 256, 256>>>();
    }
    // 4) normalized output, relayout to [b, n, c]
    {
        dim3 grid(BATCH * HDIM, NSEQ / 64);
        out_kernel<<<grid, 256, OUT_SMEM_FLOATS * 4>>>();
    }
    // 5) final projection + bias -> d_out
    {
        dim3 grid(CDIM / 128, BNTOK / 128);
        sgemm_tn<true><<<grid, 256>>>(p_o, proj_w, proj_b, out, CDIM, CDIM);
    }
}

// round 11
// speedup vs baseline: 2.6420x; 1.7910x over previous
#include <cuda_runtime.h>
#include <cuda_bf16.h>
#include <math.h>
#include <stdint.h>

#define BATCH 8
#define NSEQ  1024
#define CDIM  768
#define HDIM  12
#define DDIM  64
#define MDIM  128
#define BNTOK (BATCH*NSEQ)          // 8192
#define KVSZ  (MDIM*DDIM + MDIM)    // 8320 floats per (b,h): KV + S
#define NSPLIT 8

typedef unsigned long long ull;

// ---- packed fp32x2 helpers (feat/kv/out kernels) --------------------------
__device__ __forceinline__ ull pack_dup(float x) {
    ull r; asm("mov.b64 %0, {%1, %1};" : "=l"(r) : "f"(x)); return r;
}
__device__ __forceinline__ void ffma2(ull& acc, ull a, ull b) {
    asm("fma.rn.f32x2 %0, %1, %2, %0;" : "+l"(acc) : "l"(a), "l"(b));
}
__device__ __forceinline__ float2 unpack2(ull v) {
    float2 r; asm("mov.b64 {%0, %1}, %2;" : "=f"(r.x), "=f"(r.y) : "l"(v)); return r;
}

// ---- baseline-PTX tensor-core helpers (sm_80+, valid on compute_103) ------
__device__ __forceinline__ uint32_t smem_to_u32(const void* p) {
    uint32_t a;
    asm("{ .reg .u64 t; cvta.to.shared.u64 t, %1; cvt.u32.u64 %0, t; }" : "=r"(a) : "l"(p));
    return a;
}
__device__ __forceinline__ void cp16(uint32_t dst, const void* src) {
    asm volatile("cp.async.cg.shared.global [%0], [%1], 16;" :: "r"(dst), "l"(src));
}
#define CP_COMMIT() asm volatile("cp.async.commit_group;" ::: "memory")
#define CP_WAIT(n)  asm volatile("cp.async.wait_group %0;" :: "n"(n) : "memory")

__device__ __forceinline__ void ldsm4(uint32_t& r0, uint32_t& r1, uint32_t& r2,
                                      uint32_t& r3, uint32_t a) {
    asm volatile("ldmatrix.sync.aligned.m8n8.x4.shared.b16 {%0,%1,%2,%3}, [%4];"
                 : "=r"(r0), "=r"(r1), "=r"(r2), "=r"(r3) : "r"(a));
}
__device__ __forceinline__ void mma16816(float* c, const uint32_t* a, const uint32_t* b) {
    asm volatile("mma.sync.aligned.m16n8k16.row.col.f32.bf16.bf16.f32 "
        "{%0,%1,%2,%3}, {%4,%5,%6,%7}, {%8,%9}, {%0,%1,%2,%3};"
        : "+f"(c[0]), "+f"(c[1]), "+f"(c[2]), "+f"(c[3])
        : "r"(a[0]), "r"(a[1]), "r"(a[2]), "r"(a[3]), "r"(b[0]), "r"(b[1]));
}

// ---- bf16 hi/lo split helpers ---------------------------------------------
__device__ __forceinline__ void split1(float v, unsigned short& h, unsigned short& l) {
    __nv_bfloat16 hb = __float2bfloat16(v);
    float r = v - __bfloat162float(hb);
    __nv_bfloat16 lb = __float2bfloat16(r);
    h = *reinterpret_cast<unsigned short*>(&hb);
    l = *reinterpret_cast<unsigned short*>(&lb);
}

// ---------------- scratch (device globals; no allocation allowed) ----------
__device__ float g_qkv[BNTOK * 3 * CDIM];                     // 75.5 MB
__device__ float g_qf [BATCH * HDIM * NSEQ * MDIM];           // 50.3 MB
__device__ float g_kf [BATCH * HDIM * NSEQ * MDIM];           // 50.3 MB
__device__ float g_kvp[NSPLIT * BATCH * HDIM * KVSZ];         // 25.5 MB
__device__ float g_kv [BATCH * HDIM * KVSZ];                  // 3.2 MB
__device__ __nv_bfloat16 g_xh [BNTOK * CDIM];                 // 12.6 MB
__device__ __nv_bfloat16 g_xl [BNTOK * CDIM];
__device__ __nv_bfloat16 g_qwh[3 * CDIM * CDIM];              // 3.5 MB
__device__ __nv_bfloat16 g_qwl[3 * CDIM * CDIM];
__device__ __nv_bfloat16 g_pwh[CDIM * CDIM];                  // 1.2 MB
__device__ __nv_bfloat16 g_pwl[CDIM * CDIM];
__device__ __nv_bfloat16 g_oh [BNTOK * CDIM];                 // 12.6 MB
__device__ __nv_bfloat16 g_ol [BNTOK * CDIM];

extern __shared__ float dyn_smem[];

// ---------------------------------------------------------------------------
// split fp32 -> bf16 hi/lo, vectorized by 4
// ---------------------------------------------------------------------------
__global__ __launch_bounds__(256) void split_kernel(
    const float4* __restrict__ src, uint32_t* __restrict__ hi,
    uint32_t* __restrict__ lo, int n4)
{
    const int i = blockIdx.x * 256 + threadIdx.x;
    if (i >= n4) return;
    const float4 v = src[i];
    unsigned short h0,h1,h2,h3, l0,l1,l2,l3;
    split1(v.x, h0, l0); split1(v.y, h1, l1);
    split1(v.z, h2, l2); split1(v.w, h3, l3);
    hi[2*i]   = (uint32_t)h0 | ((uint32_t)h1 << 16);
    hi[2*i+1] = (uint32_t)h2 | ((uint32_t)h3 << 16);
    lo[2*i]   = (uint32_t)l0 | ((uint32_t)l1 << 16);
    lo[2*i+1] = (uint32_t)l2 | ((uint32_t)l3 << 16);
}

// ---------------------------------------------------------------------------
// bf16x3 tensor-core GEMM via mma.sync: C[M,N] = A[M,K] @ Bw[N,K]^T (+bias).
// C ~= Ah*Bh + Ah*Bl + Al*Bh, fp32 accumulators.
// 128x128 CTA tile, BK=32, 8 warps (2 x 4), warp tile 64x32, cp.async
// double buffering. Smem tiles padded to 80B pitch (conflict-free ldmatrix).
// ---------------------------------------------------------------------------
#define PITCHB   80                          // bytes per 32-bf16 row in smem
#define TILE_B   (128 * PITCHB)              // 10240 B per operand tile
#define STAGE_B  (4 * TILE_B)                // AH AL BH BL
#define OFF_AH   0
#define OFF_AL   TILE_B
#define OFF_BH   (2 * TILE_B)
#define OFF_BL   (3 * TILE_B)
#define GEMM_DYN_SMEM (2 * STAGE_B)          // 81920 B

__device__ __forceinline__ void stage_tile(uint32_t sdst,
    const __nv_bfloat16* __restrict__ g, int ld, int k0, int tid)
{
    // 128 rows x 32 bf16 = 512 x 16B chunks; 256 threads x 2
    #pragma unroll
    for (int i = 0; i < 2; i++) {
        const int c   = tid + i * 256;
        const int row = c >> 2, c16 = c & 3;
        cp16(sdst + row * PITCHB + c16 * 16,
             g + (size_t)row * ld + k0 + c16 * 8);
    }
}

template<bool ADD_BIAS>
__global__ __launch_bounds__(256) void mma_gemm(
    const __nv_bfloat16* __restrict__ Ah, const __nv_bfloat16* __restrict__ Al,
    const __nv_bfloat16* __restrict__ Bh, const __nv_bfloat16* __restrict__ Bl,
    const float* __restrict__ bias, float* __restrict__ C, int Nd, int Kd)
{
    const uint32_t sb = smem_to_u32(dyn_smem);
    const int tid  = threadIdx.x;
    const int wid  = tid >> 5, lane = tid & 31;
    const int wm   = wid & 1;          // 0..1 -> 64-row slab
    const int wn   = wid >> 1;         // 0..3 -> 32-col slab
    const int row0 = blockIdx.y * 128, col0 = blockIdx.x * 128;

    // ldmatrix per-lane offsets
    const int t8   = lane & 7;
    const int g01  = (lane >> 3) & 1;
    const int g2   = lane >> 4;
    const int mrow = g01 * 8 + t8;               // row within 16
    const int kofw = g2 * 8;                     // k within 16

    const __nv_bfloat16* gAh = Ah + (size_t)row0 * Kd;
    const __nv_bfloat16* gAl = Al + (size_t)row0 * Kd;
    const __nv_bfloat16* gBh = Bh + (size_t)col0 * Kd;
    const __nv_bfloat16* gBl = Bl + (size_t)col0 * Kd;

    float acc[4][4][4];
    #pragma unroll
    for (int i = 0; i < 4; i++)
        #pragma unroll
        for (int j = 0; j < 4; j++)
            #pragma unroll
            for (int r = 0; r < 4; r++) acc[i][j][r] = 0.f;

    const int nchunk = Kd >> 5;   // BK=32

    // preload stage 0
    stage_tile(sb + OFF_AH, gAh, Kd, 0, tid);
    stage_tile(sb + OFF_AL, gAl, Kd, 0, tid);
    stage_tile(sb + OFF_BH, gBh, Kd, 0, tid);
    stage_tile(sb + OFF_BL, gBl, Kd, 0, tid);
    CP_COMMIT();

    for (int c = 0; c < nchunk; c++) {
        if (c + 1 < nchunk) {
            const uint32_t nb = sb + ((c + 1) & 1) * STAGE_B;
            const int k0 = (c + 1) << 5;
            stage_tile(nb + OFF_AH, gAh, Kd, k0, tid);
            stage_tile(nb + OFF_AL, gAl, Kd, k0, tid);
            stage_tile(nb + OFF_BH, gBh, Kd, k0, tid);
            stage_tile(nb + OFF_BL, gBl, Kd, k0, tid);
            CP_COMMIT();
            CP_WAIT(1);
        } else {
            CP_WAIT(0);
        }
        __syncthreads();

        const uint32_t st = sb + (c & 1) * STAGE_B;
        #pragma unroll
        for (int ks = 0; ks < 2; ks++) {
            const uint32_t kb = ks * 32 + kofw * 2;   // byte offset along K
            uint32_t ah[4][4], al[4][4];
            #pragma unroll
            for (int mf = 0; mf < 4; mf++) {
                const uint32_t ra = (wm * 64 + mf * 16 + mrow) * PITCHB + kb;
                ldsm4(ah[mf][0], ah[mf][1], ah[mf][2], ah[mf][3], st + OFF_AH + ra);
                ldsm4(al[mf][0], al[mf][1], al[mf][2], al[mf][3], st + OFF_AL + ra);
            }
            uint32_t bh[4][2], bl[4][2];
            #pragma unroll
            for (int nf2 = 0; nf2 < 2; nf2++) {
                const uint32_t rb = (wn * 32 + nf2 * 16 + mrow) * PITCHB + kb;
                uint32_t r0, r1, r2, r3;
                ldsm4(r0, r1, r2, r3, st + OFF_BH + rb);
                bh[nf2*2][0] = r0; bh[nf2*2+1][0] = r1;
                bh[nf2*2][1] = r2; bh[nf2*2+1][1] = r3;
                ldsm4(r0, r1, r2, r3, st + OFF_BL + rb);
                bl[nf2*2][0] = r0; bl[nf2*2+1][0] = r1;
                bl[nf2*2][1] = r2; bl[nf2*2+1][1] = r3;
            }
            #pragma unroll
            for (int mf = 0; mf < 4; mf++)
                #pragma unroll
                for (int nf = 0; nf < 4; nf++) {
                    mma16816(acc[mf][nf], ah[mf], bh[nf]);   // Ah*Bh
                    mma16816(acc[mf][nf], ah[mf], bl[nf]);   // Ah*Bl
                    mma16816(acc[mf][nf], al[mf], bh[nf]);   // Al*Bh
                }
        }
        __syncthreads();
    }

    // epilogue: fragment layout -> float2 stores
    const int rg = lane >> 2;          // 0..7
    const int cp = (lane & 3) * 2;     // 0,2,4,6
    #pragma unroll
    for (int mf = 0; mf < 4; mf++) {
        #pragma unroll
        for (int nf = 0; nf < 4; nf++) {
            const int col = col0 + wn * 32 + nf * 8 + cp;
            float b0 = 0.f, b1 = 0.f;
            if (ADD_BIAS) { b0 = bias[col]; b1 = bias[col + 1]; }
            const int r0 = row0 + wm * 64 + mf * 16 + rg;
            *reinterpret_cast<float2*>(&C[(size_t)r0 * Nd + col]) =
                make_float2(acc[mf][nf][0] + b0, acc[mf][nf][1] + b1);
            *reinterpret_cast<float2*>(&C[(size_t)(r0 + 8) * Nd + col]) =
                make_float2(acc[mf][nf][2] + b0, acc[mf][nf][3] + b1);
        }
    }
}

// ---------------------------------------------------------------------------
// Feature map q AND k (unchanged)
// ---------------------------------------------------------------------------
__global__ __launch_bounds__(256) void feat_kernel(const float* __restrict__ R)
{
    const int bh = blockIdx.x;
    const int b  = bh / HDIM, h = bh % HDIM;
    const int n0 = blockIdx.y * 16;
    const int tid  = threadIdx.x;
    const int lane = tid & 31;
    const int wrp  = tid >> 5;

    __shared__ float Rs[DDIM][MDIM];
    __shared__ float zq[16][DDIM];
    __shared__ float zk[16][DDIM];

    const float sq   = 0.3535533905932738f;
    const float minv = 0.08838834764831845f;

    #pragma unroll
    for (int i = tid; i < DDIM * MDIM / 4; i += 256) {
        float4 r4 = *reinterpret_cast<const float4*>(&R[h * DDIM * MDIM + i * 4]);
        *reinterpret_cast<float4*>(&Rs[0][0] + i * 4) = r4;
    }
    {
        const int r = tid >> 4, d4 = (tid & 15) * 4;
        const size_t base = (size_t)(b * NSEQ + n0 + r) * (3 * CDIM) + h * DDIM + d4;
        float4 q4 = *reinterpret_cast<const float4*>(&g_qkv[base]);
        float4 k4 = *reinterpret_cast<const float4*>(&g_qkv[base + CDIM]);
        q4.x *= sq; q4.y *= sq; q4.z *= sq; q4.w *= sq;
        k4.x *= sq; k4.y *= sq; k4.z *= sq; k4.w *= sq;
        *reinterpret_cast<float4*>(&zq[r][d4]) = q4;
        *reinterpret_cast<float4*>(&zk[r][d4]) = k4;
    }
    __syncthreads();

    ull aq[2][2], ak[2][2];
    float nq[2], nk[2];
    #pragma unroll
    for (int i = 0; i < 2; i++) {
        nq[i] = 0.f; nk[i] = 0.f;
        aq[i][0] = aq[i][1] = 0ULL;
        ak[i][0] = ak[i][1] = 0ULL;
    }

    #pragma unroll 8
    for (int d = 0; d < DDIM; d++) {
        longlong2 rp = *reinterpret_cast<const longlong2*>(&Rs[d][lane * 4]);
        #pragma unroll
        for (int i = 0; i < 2; i++) {
            const float qv = zq[wrp * 2 + i][d];
            const float kv = zk[wrp * 2 + i][d];
            const ull qd = pack_dup(qv), kd = pack_dup(kv);
            ffma2(aq[i][0], qd, (ull)rp.x); ffma2(aq[i][1], qd, (ull)rp.y);
            ffma2(ak[i][0], kd, (ull)rp.x); ffma2(ak[i][1], kd, (ull)rp.y);
            nq[i] += qv * qv;           nk[i] += kv * kv;
        }
    }

    #pragma unroll
    for (int i = 0; i < 2; i++) {
        const int n = n0 + wrp * 2 + i;
        const size_t o = ((size_t)bh * NSEQ + n) * MDIM + lane * 4;
        const float hq = 0.5f * nq[i], hk = 0.5f * nk[i];
        float2 q0 = unpack2(aq[i][0]), q1 = unpack2(aq[i][1]);
        float2 k0 = unpack2(ak[i][0]), k1 = unpack2(ak[i][1]);
        float4 fq = make_float4(expf(q0.x-hq)*minv, expf(q0.y-hq)*minv,
                                expf(q1.x-hq)*minv, expf(q1.y-hq)*minv);
        float4 fk = make_float4(expf(k0.x-hk)*minv, expf(k0.y-hk)*minv,
                                expf(k1.x-hk)*minv, expf(k1.y-hk)*minv);
        *reinterpret_cast<float4*>(&g_qf[o]) = fq;
        *reinterpret_cast<float4*>(&g_kf[o]) = fk;
    }
}

// ---------------------------------------------------------------------------
// Partial KV + S (unchanged)
// ---------------------------------------------------------------------------
__global__ __launch_bounds__(256) void kv_kernel()
{
    const int bh = blockIdx.x;
    const int b  = bh / HDIM, h = bh % HDIM;
    const int p  = blockIdx.y;
    const int tm = threadIdx.x >> 4;
    const int td = threadIdx.x & 15;

    __shared__ float kfs[32][MDIM];
    __shared__ float vs [32][DDIM];

    ull acc[8][2];
    float s[8];
    #pragma unroll
    for (int i = 0; i < 8; i++) { s[i] = 0.f; acc[i][0] = acc[i][1] = 0ULL; }

    const int nbase = p * (NSEQ / NSPLIT);
    for (int n0 = nbase; n0 < nbase + NSEQ / NSPLIT; n0 += 32) {
        __syncthreads();
        #pragma unroll
        for (int i = threadIdx.x; i < 32 * MDIM / 4; i += 256) {
            const int nn = i >> 5, m4 = (i & 31) * 4;
            *reinterpret_cast<float4*>(&kfs[nn][m4]) =
                *reinterpret_cast<const float4*>(&g_kf[((size_t)bh * NSEQ + n0 + nn) * MDIM + m4]);
        }
        #pragma unroll
        for (int i = threadIdx.x; i < 32 * DDIM / 4; i += 256) {
            const int nn = i >> 4, d4 = (i & 15) * 4;
            *reinterpret_cast<float4*>(&vs[nn][d4]) =
                *reinterpret_cast<const float4*>(
                    &g_qkv[(size_t)(b * NSEQ + n0 + nn) * (3 * CDIM) + 2 * CDIM + h * DDIM + d4]);
        }
        __syncthreads();
        #pragma unroll 4
        for (int nn = 0; nn < 32; nn++) {
            float a[8];
            #pragma unroll
            for (int i = 0; i < 8; i++) a[i] = kfs[nn][tm * 8 + i];
            longlong2 bp = *reinterpret_cast<const longlong2*>(&vs[nn][td * 4]);
            #pragma unroll
            for (int i = 0; i < 8; i++) {
                const ull ad = pack_dup(a[i]);
                ffma2(acc[i][0], ad, (ull)bp.x);
                ffma2(acc[i][1], ad, (ull)bp.y);
                s[i] += a[i];
            }
        }
    }

    float* kvb = g_kvp + ((size_t)p * (BATCH * HDIM) + bh) * KVSZ;
    #pragma unroll
    for (int i = 0; i < 8; i++) {
        const int m = tm * 8 + i;
        float2 p0 = unpack2(acc[i][0]), p1 = unpack2(acc[i][1]);
        *reinterpret_cast<float4*>(&kvb[m * DDIM + td * 4]) =
            make_float4(p0.x, p0.y, p1.x, p1.y);
        if (td == 0) kvb[MDIM * DDIM + m] = s[i];
    }
}

__global__ __launch_bounds__(256) void kv_reduce()
{
    const int i = blockIdx.x * 256 + threadIdx.x;
    if (i < BATCH * HDIM * KVSZ) {
        float s = 0.f;
        #pragma unroll
        for (int pp = 0; pp < NSPLIT; pp++)
            s += g_kvp[(size_t)pp * (BATCH * HDIM * KVSZ) + i];
        g_kv[i] = s;
    }
}

// ---------------------------------------------------------------------------
// out kernel: writes bf16 hi/lo directly (feeds proj GEMM)
// ---------------------------------------------------------------------------
#define QF_PITCH 132
#define OUT_SMEM_FLOATS (KVSZ + 64 * QF_PITCH)

__global__ __launch_bounds__(256) void out_kernel()
{
    float* osm = dyn_smem;   // [0,8192): KV  [8192,8320): S  [8320,..): qf
    const int bh = blockIdx.x;
    const int b  = bh / HDIM, h = bh % HDIM;
    const int n0 = blockIdx.y * 64;
    const int tr = threadIdx.x >> 4;
    const int tc = threadIdx.x & 15;

    const float* kvb = g_kv + (size_t)bh * KVSZ;
    #pragma unroll
    for (int i = threadIdx.x; i < KVSZ / 4; i += 256)
        *reinterpret_cast<float4*>(&osm[i * 4]) =
            *reinterpret_cast<const float4*>(&kvb[i * 4]);
    #pragma unroll
    for (int i = threadIdx.x; i < 64 * 32; i += 256) {
        const int r = i >> 5, d4 = (i & 31) * 4;
        *reinterpret_cast<float4*>(&osm[KVSZ + r * QF_PITCH + d4]) =
            *reinterpret_cast<const float4*>(&g_qf[((size_t)bh * NSEQ + n0 + r) * MDIM + d4]);
    }
    __syncthreads();

    ull acc[4][2];
    float den[4];
    #pragma unroll
    for (int i = 0; i < 4; i++) { den[i] = 0.f; acc[i][0] = acc[i][1] = 0ULL; }

    #pragma unroll 4
    for (int m = 0; m < MDIM; m++) {
        longlong2 kvp = *reinterpret_cast<const longlong2*>(&osm[m * DDIM + tc * 4]);
        const float sv = osm[MDIM * DDIM + m];
        #pragma unroll
        for (int i = 0; i < 4; i++) {
            const float q = osm[KVSZ + (tr * 4 + i) * QF_PITCH + m];
            const ull qd = pack_dup(q);
            ffma2(acc[i][0], qd, (ull)kvp.x);
            ffma2(acc[i][1], qd, (ull)kvp.y);
            den[i] += q * sv;
        }
    }

    #pragma unroll
    for (int i = 0; i < 4; i++) {
        const float inv = 1.0f / fmaxf(den[i], 1e-12f);
        const int n = n0 + tr * 4 + i;
        float2 p0 = unpack2(acc[i][0]), p1 = unpack2(acc[i][1]);
        const float r0 = p0.x*inv, r1 = p0.y*inv, r2 = p1.x*inv, r3 = p1.y*inv;
        unsigned short h0,h1,h2,h3, l0,l1,l2,l3;
        split1(r0, h0, l0); split1(r1, h1, l1);
        split1(r2, h2, l2); split1(r3, h3, l3);
        const size_t o = (size_t)(b * NSEQ + n) * CDIM + h * DDIM + tc * 4;
        uint32_t* oh = reinterpret_cast<uint32_t*>(&g_oh[o]);
        uint32_t* ol = reinterpret_cast<uint32_t*>(&g_ol[o]);
        oh[0] = (uint32_t)h0 | ((uint32_t)h1 << 16);
        oh[1] = (uint32_t)h2 | ((uint32_t)h3 << 16);
        ol[0] = (uint32_t)l0 | ((uint32_t)l1 << 16);
        ol[1] = (uint32_t)l2 | ((uint32_t)l3 << 16);
    }
}

// ---------------------------------------------------------------------------
extern "C" void kernel_launch(void* const* d_in, const int* in_sizes, int n_in,
                              void* d_out, int out_size)
{
    const float* x      = (const float*)d_in[0];
    const float* qkv_w  = (const float*)d_in[1];
    const float* proj_w = (const float*)d_in[2];
    const float* proj_b = (const float*)d_in[3];
    const float* randm  = (const float*)d_in[4];
    float* out = (float*)d_out;

    float *p_qkv;
    cudaGetSymbolAddress((void**)&p_qkv, g_qkv);
    __nv_bfloat16 *p_xh, *p_xl, *p_qwh, *p_qwl, *p_pwh, *p_pwl, *p_oh, *p_ol;
    cudaGetSymbolAddress((void**)&p_xh,  g_xh);
    cudaGetSymbolAddress((void**)&p_xl,  g_xl);
    cudaGetSymbolAddress((void**)&p_qwh, g_qwh);
    cudaGetSymbolAddress((void**)&p_qwl, g_qwl);
    cudaGetSymbolAddress((void**)&p_pwh, g_pwh);
    cudaGetSymbolAddress((void**)&p_pwl, g_pwl);
    cudaGetSymbolAddress((void**)&p_oh,  g_oh);
    cudaGetSymbolAddress((void**)&p_ol,  g_ol);

    cudaFuncSetAttribute(out_kernel, cudaFuncAttributeMaxDynamicSharedMemorySize,
                         OUT_SMEM_FLOATS * 4);
    cudaFuncSetAttribute(mma_gemm<false>, cudaFuncAttributeMaxDynamicSharedMemorySize,
                         GEMM_DYN_SMEM);
    cudaFuncSetAttribute(mma_gemm<true>, cudaFuncAttributeMaxDynamicSharedMemorySize,
                         GEMM_DYN_SMEM);

    // 0) hi/lo splits
    {
        const int n4x = BNTOK * CDIM / 4;
        split_kernel<<<(n4x + 255) / 256, 256>>>(
            (const float4*)x, (uint32_t*)p_xh, (uint32_t*)p_xl, n4x);
        const int n4q = 3 * CDIM * CDIM / 4;
        split_kernel<<<(n4q + 255) / 256, 256>>>(
            (const float4*)qkv_w, (uint32_t*)p_qwh, (uint32_t*)p_qwl, n4q);
        const int n4p = CDIM * CDIM / 4;
        split_kernel<<<(n4p + 255) / 256, 256>>>(
            (const float4*)proj_w, (uint32_t*)p_pwh, (uint32_t*)p_pwl, n4p);
    }
    // 1) qkv = x @ qkv_w^T : [8192, 2304] via bf16x3 mma.sync
    {
        dim3 grid(3 * CDIM / 128, BNTOK / 128);
        mma_gemm<false><<<grid, 256, GEMM_DYN_SMEM>>>(
            p_xh, p_xl, p_qwh, p_qwl, nullptr, p_qkv, 3 * CDIM, CDIM);
    }
    // 2) feature maps qf, kf
    {
        dim3 grid(BATCH * HDIM, NSEQ / 16);
        feat_kernel<<<grid, 256>>>(randm);
    }
    // 3) KV + S partial reduction, then merge
    {
        dim3 grid(BATCH * HDIM, NSPLIT);
        kv_kernel<<<grid, 256>>>();
        kv_reduce<<<(BATCH * HDIM * KVSZ + 255) / 256, 256>>>();
    }
    // 4) normalized output -> bf16 hi/lo [b, n, c]
    {
        dim3 grid(BATCH * HDIM, NSEQ / 64);
        out_kernel<<<grid, 256, OUT_SMEM_FLOATS * 4>>>();
    }
    // 5) final projection + bias -> d_out via bf16x3 mma.sync
    {
        dim3 grid(CDIM / 128, BNTOK / 128);
        mma_gemm<true><<<grid, 256, GEMM_DYN_SMEM>>>(
            p_oh, p_ol, p_pwh, p_pwl, proj_b, out, CDIM, CDIM);
    }
}

// round 12
// speedup vs baseline: 2.6624x; 1.0077x over previous
#include <cuda_runtime.h>
#include <cuda_bf16.h>
#include <math.h>
#include <stdint.h>

#define BATCH 8
#define NSEQ  1024
#define CDIM  768
#define HDIM  12
#define DDIM  64
#define MDIM  128
#define BNTOK (BATCH*NSEQ)          // 8192
#define KVSZ  (MDIM*DDIM + MDIM)    // 8320 floats per (b,h): KV + S
#define NSPLIT 8

typedef unsigned long long ull;

// ---- packed fp32x2 helpers (feat/kv/out kernels) --------------------------
__device__ __forceinline__ ull pack_dup(float x) {
    ull r; asm("mov.b64 %0, {%1, %1};" : "=l"(r) : "f"(x)); return r;
}
__device__ __forceinline__ void ffma2(ull& acc, ull a, ull b) {
    asm("fma.rn.f32x2 %0, %1, %2, %0;" : "+l"(acc) : "l"(a), "l"(b));
}
__device__ __forceinline__ float2 unpack2(ull v) {
    float2 r; asm("mov.b64 {%0, %1}, %2;" : "=f"(r.x), "=f"(r.y) : "l"(v)); return r;
}

// ---- baseline-PTX tensor-core helpers (sm_80+, valid on compute_103) ------
__device__ __forceinline__ uint32_t smem_to_u32(const void* p) {
    uint32_t a;
    asm("{ .reg .u64 t; cvta.to.shared.u64 t, %1; cvt.u32.u64 %0, t; }" : "=r"(a) : "l"(p));
    return a;
}
__device__ __forceinline__ void cp16(uint32_t dst, const void* src) {
    asm volatile("cp.async.cg.shared.global [%0], [%1], 16;" :: "r"(dst), "l"(src));
}
#define CP_COMMIT() asm volatile("cp.async.commit_group;" ::: "memory")
#define CP_WAIT(n)  asm volatile("cp.async.wait_group %0;" :: "n"(n) : "memory")

__device__ __forceinline__ void ldsm4(uint32_t& r0, uint32_t& r1, uint32_t& r2,
                                      uint32_t& r3, uint32_t a) {
    asm volatile("ldmatrix.sync.aligned.m8n8.x4.shared.b16 {%0,%1,%2,%3}, [%4];"
                 : "=r"(r0), "=r"(r1), "=r"(r2), "=r"(r3) : "r"(a));
}
__device__ __forceinline__ void mma16816(float* c, const uint32_t* a, const uint32_t* b) {
    asm volatile("mma.sync.aligned.m16n8k16.row.col.f32.bf16.bf16.f32 "
        "{%0,%1,%2,%3}, {%4,%5,%6,%7}, {%8,%9}, {%0,%1,%2,%3};"
        : "+f"(c[0]), "+f"(c[1]), "+f"(c[2]), "+f"(c[3])
        : "r"(a[0]), "r"(a[1]), "r"(a[2]), "r"(a[3]), "r"(b[0]), "r"(b[1]));
}

// ---- bf16 hi/lo split helpers ---------------------------------------------
__device__ __forceinline__ void split1(float v, unsigned short& h, unsigned short& l) {
    __nv_bfloat16 hb = __float2bfloat16(v);
    float r = v - __bfloat162float(hb);
    __nv_bfloat16 lb = __float2bfloat16(r);
    h = *reinterpret_cast<unsigned short*>(&hb);
    l = *reinterpret_cast<unsigned short*>(&lb);
}

// ---------------- scratch (device globals; no allocation allowed) ----------
__device__ float g_qkv[BNTOK * 3 * CDIM];                     // 75.5 MB
__device__ float g_qf [BATCH * HDIM * NSEQ * MDIM];           // 50.3 MB
__device__ float g_kf [BATCH * HDIM * NSEQ * MDIM];           // 50.3 MB
__device__ float g_kvp[NSPLIT * BATCH * HDIM * KVSZ];         // 25.5 MB
__device__ float g_kv [BATCH * HDIM * KVSZ];                  // 3.2 MB
__device__ __nv_bfloat16 g_xh [BNTOK * CDIM];                 // 12.6 MB
__device__ __nv_bfloat16 g_xl [BNTOK * CDIM];
__device__ __nv_bfloat16 g_qwh[3 * CDIM * CDIM];              // 3.5 MB
__device__ __nv_bfloat16 g_qwl[3 * CDIM * CDIM];
__device__ __nv_bfloat16 g_pwh[CDIM * CDIM];                  // 1.2 MB
__device__ __nv_bfloat16 g_pwl[CDIM * CDIM];
__device__ __nv_bfloat16 g_oh [BNTOK * CDIM];                 // 12.6 MB
__device__ __nv_bfloat16 g_ol [BNTOK * CDIM];

extern __shared__ float dyn_smem[];

// ---------------------------------------------------------------------------
// split fp32 -> bf16 hi/lo, vectorized by 4
// ---------------------------------------------------------------------------
__global__ __launch_bounds__(256) void split_kernel(
    const float4* __restrict__ src, uint32_t* __restrict__ hi,
    uint32_t* __restrict__ lo, int n4)
{
    const int i = blockIdx.x * 256 + threadIdx.x;
    if (i >= n4) return;
    const float4 v = src[i];
    unsigned short h0,h1,h2,h3, l0,l1,l2,l3;
    split1(v.x, h0, l0); split1(v.y, h1, l1);
    split1(v.z, h2, l2); split1(v.w, h3, l3);
    hi[2*i]   = (uint32_t)h0 | ((uint32_t)h1 << 16);
    hi[2*i+1] = (uint32_t)h2 | ((uint32_t)h3 << 16);
    lo[2*i]   = (uint32_t)l0 | ((uint32_t)l1 << 16);
    lo[2*i+1] = (uint32_t)l2 | ((uint32_t)l3 << 16);
}

// ---------------------------------------------------------------------------
// bf16x3 tensor-core GEMM via mma.sync: C[M,N] = A[M,K] @ Bw[N,K]^T (+bias).
// C ~= Ah*Bh + Ah*Bl + Al*Bh, fp32 accumulators.
// 128x128 CTA tile, BK=32, 8 warps (2 x 4), warp tile 64x32, cp.async
// double buffering with ONE __syncthreads per k-chunk.
// ---------------------------------------------------------------------------
#define PITCHB   80                          // bytes per 32-bf16 row in smem
#define TILE_B   (128 * PITCHB)              // 10240 B per operand tile
#define STAGE_B  (4 * TILE_B)                // AH AL BH BL
#define OFF_AH   0
#define OFF_AL   TILE_B
#define OFF_BH   (2 * TILE_B)
#define OFF_BL   (3 * TILE_B)
#define GEMM_DYN_SMEM (2 * STAGE_B)          // 81920 B

__device__ __forceinline__ void stage_tile(uint32_t sdst,
    const __nv_bfloat16* __restrict__ g, int ld, int k0, int tid)
{
    // 128 rows x 32 bf16 = 512 x 16B chunks; 256 threads x 2
    #pragma unroll
    for (int i = 0; i < 2; i++) {
        const int c   = tid + i * 256;
        const int row = c >> 2, c16 = c & 3;
        cp16(sdst + row * PITCHB + c16 * 16,
             g + (size_t)row * ld + k0 + c16 * 8);
    }
}

template<bool ADD_BIAS>
__global__ __launch_bounds__(256) void mma_gemm(
    const __nv_bfloat16* __restrict__ Ah, const __nv_bfloat16* __restrict__ Al,
    const __nv_bfloat16* __restrict__ Bh, const __nv_bfloat16* __restrict__ Bl,
    const float* __restrict__ bias, float* __restrict__ C, int Nd, int Kd)
{
    const uint32_t sb = smem_to_u32(dyn_smem);
    const int tid  = threadIdx.x;
    const int wid  = tid >> 5, lane = tid & 31;
    const int wm   = wid & 1;          // 0..1 -> 64-row slab
    const int wn   = wid >> 1;         // 0..3 -> 32-col slab
    const int row0 = blockIdx.y * 128, col0 = blockIdx.x * 128;

    // ldmatrix per-lane offsets
    const int t8   = lane & 7;
    const int g01  = (lane >> 3) & 1;
    const int g2   = lane >> 4;
    const int mrow = g01 * 8 + t8;               // row within 16
    const int kofw = g2 * 8;                     // k within 16

    const __nv_bfloat16* gAh = Ah + (size_t)row0 * Kd;
    const __nv_bfloat16* gAl = Al + (size_t)row0 * Kd;
    const __nv_bfloat16* gBh = Bh + (size_t)col0 * Kd;
    const __nv_bfloat16* gBl = Bl + (size_t)col0 * Kd;

    float acc[4][4][4];
    #pragma unroll
    for (int i = 0; i < 4; i++)
        #pragma unroll
        for (int j = 0; j < 4; j++)
            #pragma unroll
            for (int r = 0; r < 4; r++) acc[i][j][r] = 0.f;

    const int nchunk = Kd >> 5;   // BK=32

    // preload stage 0
    stage_tile(sb + OFF_AH, gAh, Kd, 0, tid);
    stage_tile(sb + OFF_AL, gAl, Kd, 0, tid);
    stage_tile(sb + OFF_BH, gBh, Kd, 0, tid);
    stage_tile(sb + OFF_BL, gBl, Kd, 0, tid);
    CP_COMMIT();

    for (int c = 0; c < nchunk; c++) {
        CP_WAIT(0);          // stage c resident
        __syncthreads();     // all warps see it; all finished chunk c-1
        if (c + 1 < nchunk) {
            // prefetch c+1 into the other buffer, overlapped with compute c
            const uint32_t nb = sb + ((c + 1) & 1) * STAGE_B;
            const int k0 = (c + 1) << 5;
            stage_tile(nb + OFF_AH, gAh, Kd, k0, tid);
            stage_tile(nb + OFF_AL, gAl, Kd, k0, tid);
            stage_tile(nb + OFF_BH, gBh, Kd, k0, tid);
            stage_tile(nb + OFF_BL, gBl, Kd, k0, tid);
            CP_COMMIT();
        }

        const uint32_t st = sb + (c & 1) * STAGE_B;
        #pragma unroll
        for (int ks = 0; ks < 2; ks++) {
            const uint32_t kb = ks * 32 + kofw * 2;   // byte offset along K
            uint32_t ah[4][4], al[4][4];
            #pragma unroll
            for (int mf = 0; mf < 4; mf++) {
                const uint32_t ra = (wm * 64 + mf * 16 + mrow) * PITCHB + kb;
                ldsm4(ah[mf][0], ah[mf][1], ah[mf][2], ah[mf][3], st + OFF_AH + ra);
                ldsm4(al[mf][0], al[mf][1], al[mf][2], al[mf][3], st + OFF_AL + ra);
            }
            uint32_t bh[4][2], bl[4][2];
            #pragma unroll
            for (int nf2 = 0; nf2 < 2; nf2++) {
                const uint32_t rb = (wn * 32 + nf2 * 16 + mrow) * PITCHB + kb;
                uint32_t r0, r1, r2, r3;
                ldsm4(r0, r1, r2, r3, st + OFF_BH + rb);
                bh[nf2*2][0] = r0; bh[nf2*2+1][0] = r1;
                bh[nf2*2][1] = r2; bh[nf2*2+1][1] = r3;
                ldsm4(r0, r1, r2, r3, st + OFF_BL + rb);
                bl[nf2*2][0] = r0; bl[nf2*2+1][0] = r1;
                bl[nf2*2][1] = r2; bl[nf2*2+1][1] = r3;
            }
            #pragma unroll
            for (int mf = 0; mf < 4; mf++)
                #pragma unroll
                for (int nf = 0; nf < 4; nf++) {
                    mma16816(acc[mf][nf], ah[mf], bh[nf]);   // Ah*Bh
                    mma16816(acc[mf][nf], ah[mf], bl[nf]);   // Ah*Bl
                    mma16816(acc[mf][nf], al[mf], bh[nf]);   // Al*Bh
                }
        }
    }

    // epilogue: fragment layout -> float2 stores
    const int rg = lane >> 2;          // 0..7
    const int cp = (lane & 3) * 2;     // 0,2,4,6
    #pragma unroll
    for (int mf = 0; mf < 4; mf++) {
        #pragma unroll
        for (int nf = 0; nf < 4; nf++) {
            const int col = col0 + wn * 32 + nf * 8 + cp;
            float b0 = 0.f, b1 = 0.f;
            if (ADD_BIAS) { b0 = bias[col]; b1 = bias[col + 1]; }
            const int r0 = row0 + wm * 64 + mf * 16 + rg;
            *reinterpret_cast<float2*>(&C[(size_t)r0 * Nd + col]) =
                make_float2(acc[mf][nf][0] + b0, acc[mf][nf][1] + b1);
            *reinterpret_cast<float2*>(&C[(size_t)(r0 + 8) * Nd + col]) =
                make_float2(acc[mf][nf][2] + b0, acc[mf][nf][3] + b1);
        }
    }
}

// ---------------------------------------------------------------------------
// Feature map q AND k (unchanged)
// ---------------------------------------------------------------------------
__global__ __launch_bounds__(256) void feat_kernel(const float* __restrict__ R)
{
    const int bh = blockIdx.x;
    const int b  = bh / HDIM, h = bh % HDIM;
    const int n0 = blockIdx.y * 16;
    const int tid  = threadIdx.x;
    const int lane = tid & 31;
    const int wrp  = tid >> 5;

    __shared__ float Rs[DDIM][MDIM];
    __shared__ float zq[16][DDIM];
    __shared__ float zk[16][DDIM];

    const float sq   = 0.3535533905932738f;
    const float minv = 0.08838834764831845f;

    #pragma unroll
    for (int i = tid; i < DDIM * MDIM / 4; i += 256) {
        float4 r4 = *reinterpret_cast<const float4*>(&R[h * DDIM * MDIM + i * 4]);
        *reinterpret_cast<float4*>(&Rs[0][0] + i * 4) = r4;
    }
    {
        const int r = tid >> 4, d4 = (tid & 15) * 4;
        const size_t base = (size_t)(b * NSEQ + n0 + r) * (3 * CDIM) + h * DDIM + d4;
        float4 q4 = *reinterpret_cast<const float4*>(&g_qkv[base]);
        float4 k4 = *reinterpret_cast<const float4*>(&g_qkv[base + CDIM]);
        q4.x *= sq; q4.y *= sq; q4.z *= sq; q4.w *= sq;
        k4.x *= sq; k4.y *= sq; k4.z *= sq; k4.w *= sq;
        *reinterpret_cast<float4*>(&zq[r][d4]) = q4;
        *reinterpret_cast<float4*>(&zk[r][d4]) = k4;
    }
    __syncthreads();

    ull aq[2][2], ak[2][2];
    float nq[2], nk[2];
    #pragma unroll
    for (int i = 0; i < 2; i++) {
        nq[i] = 0.f; nk[i] = 0.f;
        aq[i][0] = aq[i][1] = 0ULL;
        ak[i][0] = ak[i][1] = 0ULL;
    }

    #pragma unroll 8
    for (int d = 0; d < DDIM; d++) {
        longlong2 rp = *reinterpret_cast<const longlong2*>(&Rs[d][lane * 4]);
        #pragma unroll
        for (int i = 0; i < 2; i++) {
            const float qv = zq[wrp * 2 + i][d];
            const float kv = zk[wrp * 2 + i][d];
            const ull qd = pack_dup(qv), kd = pack_dup(kv);
            ffma2(aq[i][0], qd, (ull)rp.x); ffma2(aq[i][1], qd, (ull)rp.y);
            ffma2(ak[i][0], kd, (ull)rp.x); ffma2(ak[i][1], kd, (ull)rp.y);
            nq[i] += qv * qv;           nk[i] += kv * kv;
        }
    }

    #pragma unroll
    for (int i = 0; i < 2; i++) {
        const int n = n0 + wrp * 2 + i;
        const size_t o = ((size_t)bh * NSEQ + n) * MDIM + lane * 4;
        const float hq = 0.5f * nq[i], hk = 0.5f * nk[i];
        float2 q0 = unpack2(aq[i][0]), q1 = unpack2(aq[i][1]);
        float2 k0 = unpack2(ak[i][0]), k1 = unpack2(ak[i][1]);
        float4 fq = make_float4(expf(q0.x-hq)*minv, expf(q0.y-hq)*minv,
                                expf(q1.x-hq)*minv, expf(q1.y-hq)*minv);
        float4 fk = make_float4(expf(k0.x-hk)*minv, expf(k0.y-hk)*minv,
                                expf(k1.x-hk)*minv, expf(k1.y-hk)*minv);
        *reinterpret_cast<float4*>(&g_qf[o]) = fq;
        *reinterpret_cast<float4*>(&g_kf[o]) = fk;
    }
}

// ---------------------------------------------------------------------------
// Partial KV + S (unchanged)
// ---------------------------------------------------------------------------
__global__ __launch_bounds__(256) void kv_kernel()
{
    const int bh = blockIdx.x;
    const int b  = bh / HDIM, h = bh % HDIM;
    const int p  = blockIdx.y;
    const int tm = threadIdx.x >> 4;
    const int td = threadIdx.x & 15;

    __shared__ float kfs[32][MDIM];
    __shared__ float vs [32][DDIM];

    ull acc[8][2];
    float s[8];
    #pragma unroll
    for (int i = 0; i < 8; i++) { s[i] = 0.f; acc[i][0] = acc[i][1] = 0ULL; }

    const int nbase = p * (NSEQ / NSPLIT);
    for (int n0 = nbase; n0 < nbase + NSEQ / NSPLIT; n0 += 32) {
        __syncthreads();
        #pragma unroll
        for (int i = threadIdx.x; i < 32 * MDIM / 4; i += 256) {
            const int nn = i >> 5, m4 = (i & 31) * 4;
            *reinterpret_cast<float4*>(&kfs[nn][m4]) =
                *reinterpret_cast<const float4*>(&g_kf[((size_t)bh * NSEQ + n0 + nn) * MDIM + m4]);
        }
        #pragma unroll
        for (int i = threadIdx.x; i < 32 * DDIM / 4; i += 256) {
            const int nn = i >> 4, d4 = (i & 15) * 4;
            *reinterpret_cast<float4*>(&vs[nn][d4]) =
                *reinterpret_cast<const float4*>(
                    &g_qkv[(size_t)(b * NSEQ + n0 + nn) * (3 * CDIM) + 2 * CDIM + h * DDIM + d4]);
        }
        __syncthreads();
        #pragma unroll 4
        for (int nn = 0; nn < 32; nn++) {
            float a[8];
            #pragma unroll
            for (int i = 0; i < 8; i++) a[i] = kfs[nn][tm * 8 + i];
            longlong2 bp = *reinterpret_cast<const longlong2*>(&vs[nn][td * 4]);
            #pragma unroll
            for (int i = 0; i < 8; i++) {
                const ull ad = pack_dup(a[i]);
                ffma2(acc[i][0], ad, (ull)bp.x);
                ffma2(acc[i][1], ad, (ull)bp.y);
                s[i] += a[i];
            }
        }
    }

    float* kvb = g_kvp + ((size_t)p * (BATCH * HDIM) + bh) * KVSZ;
    #pragma unroll
    for (int i = 0; i < 8; i++) {
        const int m = tm * 8 + i;
        float2 p0 = unpack2(acc[i][0]), p1 = unpack2(acc[i][1]);
        *reinterpret_cast<float4*>(&kvb[m * DDIM + td * 4]) =
            make_float4(p0.x, p0.y, p1.x, p1.y);
        if (td == 0) kvb[MDIM * DDIM + m] = s[i];
    }
}

__global__ __launch_bounds__(256) void kv_reduce()
{
    const int i = blockIdx.x * 256 + threadIdx.x;
    if (i < BATCH * HDIM * KVSZ) {
        float s = 0.f;
        #pragma unroll
        for (int pp = 0; pp < NSPLIT; pp++)
            s += g_kvp[(size_t)pp * (BATCH * HDIM * KVSZ) + i];
        g_kv[i] = s;
    }
}

// ---------------------------------------------------------------------------
// out kernel: writes bf16 hi/lo directly (feeds proj GEMM)
// ---------------------------------------------------------------------------
#define QF_PITCH 132
#define OUT_SMEM_FLOATS (KVSZ + 64 * QF_PITCH)

__global__ __launch_bounds__(256) void out_kernel()
{
    float* osm = dyn_smem;   // [0,8192): KV  [8192,8320): S  [8320,..): qf
    const int bh = blockIdx.x;
    const int b  = bh / HDIM, h = bh % HDIM;
    const int n0 = blockIdx.y * 64;
    const int tr = threadIdx.x >> 4;
    const int tc = threadIdx.x & 15;

    const float* kvb = g_kv + (size_t)bh * KVSZ;
    #pragma unroll
    for (int i = threadIdx.x; i < KVSZ / 4; i += 256)
        *reinterpret_cast<float4*>(&osm[i * 4]) =
            *reinterpret_cast<const float4*>(&kvb[i * 4]);
    #pragma unroll
    for (int i = threadIdx.x; i < 64 * 32; i += 256) {
        const int r = i >> 5, d4 = (i & 31) * 4;
        *reinterpret_cast<float4*>(&osm[KVSZ + r * QF_PITCH + d4]) =
            *reinterpret_cast<const float4*>(&g_qf[((size_t)bh * NSEQ + n0 + r) * MDIM + d4]);
    }
    __syncthreads();

    ull acc[4][2];
    float den[4];
    #pragma unroll
    for (int i = 0; i < 4; i++) { den[i] = 0.f; acc[i][0] = acc[i][1] = 0ULL; }

    #pragma unroll 4
    for (int m = 0; m < MDIM; m++) {
        longlong2 kvp = *reinterpret_cast<const longlong2*>(&osm[m * DDIM + tc * 4]);
        const float sv = osm[MDIM * DDIM + m];
        #pragma unroll
        for (int i = 0; i < 4; i++) {
            const float q = osm[KVSZ + (tr * 4 + i) * QF_PITCH + m];
            const ull qd = pack_dup(q);
            ffma2(acc[i][0], qd, (ull)kvp.x);
            ffma2(acc[i][1], qd, (ull)kvp.y);
            den[i] += q * sv;
        }
    }

    #pragma unroll
    for (int i = 0; i < 4; i++) {
        const float inv = 1.0f / fmaxf(den[i], 1e-12f);
        const int n = n0 + tr * 4 + i;
        float2 p0 = unpack2(acc[i][0]), p1 = unpack2(acc[i][1]);
        const float r0 = p0.x*inv, r1 = p0.y*inv, r2 = p1.x*inv, r3 = p1.y*inv;
        unsigned short h0,h1,h2,h3, l0,l1,l2,l3;
        split1(r0, h0, l0); split1(r1, h1, l1);
        split1(r2, h2, l2); split1(r3, h3, l3);
        const size_t o = (size_t)(b * NSEQ + n) * CDIM + h * DDIM + tc * 4;
        uint32_t* oh = reinterpret_cast<uint32_t*>(&g_oh[o]);
        uint32_t* ol = reinterpret_cast<uint32_t*>(&g_ol[o]);
        oh[0] = (uint32_t)h0 | ((uint32_t)h1 << 16);
        oh[1] = (uint32_t)h2 | ((uint32_t)h3 << 16);
        ol[0] = (uint32_t)l0 | ((uint32_t)l1 << 16);
        ol[1] = (uint32_t)l2 | ((uint32_t)l3 << 16);
    }
}

// ---------------------------------------------------------------------------
extern "C" void kernel_launch(void* const* d_in, const int* in_sizes, int n_in,
                              void* d_out, int out_size)
{
    const float* x      = (const float*)d_in[0];
    const float* qkv_w  = (const float*)d_in[1];
    const float* proj_w = (const float*)d_in[2];
    const float* proj_b = (const float*)d_in[3];
    const float* randm  = (const float*)d_in[4];
    float* out = (float*)d_out;

    float *p_qkv;
    cudaGetSymbolAddress((void**)&p_qkv, g_qkv);
    __nv_bfloat16 *p_xh, *p_xl, *p_qwh, *p_qwl, *p_pwh, *p_pwl, *p_oh, *p_ol;
    cudaGetSymbolAddress((void**)&p_xh,  g_xh);
    cudaGetSymbolAddress((void**)&p_xl,  g_xl);
    cudaGetSymbolAddress((void**)&p_qwh, g_qwh);
    cudaGetSymbolAddress((void**)&p_qwl, g_qwl);
    cudaGetSymbolAddress((void**)&p_pwh, g_pwh);
    cudaGetSymbolAddress((void**)&p_pwl, g_pwl);
    cudaGetSymbolAddress((void**)&p_oh,  g_oh);
    cudaGetSymbolAddress((void**)&p_ol,  g_ol);

    cudaFuncSetAttribute(out_kernel, cudaFuncAttributeMaxDynamicSharedMemorySize,
                         OUT_SMEM_FLOATS * 4);
    cudaFuncSetAttribute(mma_gemm<false>, cudaFuncAttributeMaxDynamicSharedMemorySize,
                         GEMM_DYN_SMEM);
    cudaFuncSetAttribute(mma_gemm<true>, cudaFuncAttributeMaxDynamicSharedMemorySize,
                         GEMM_DYN_SMEM);

    // 0) hi/lo splits
    {
        const int n4x = BNTOK * CDIM / 4;
        split_kernel<<<(n4x + 255) / 256, 256>>>(
            (const float4*)x, (uint32_t*)p_xh, (uint32_t*)p_xl, n4x);
        const int n4q = 3 * CDIM * CDIM / 4;
        split_kernel<<<(n4q + 255) / 256, 256>>>(
            (const float4*)qkv_w, (uint32_t*)p_qwh, (uint32_t*)p_qwl, n4q);
        const int n4p = CDIM * CDIM / 4;
        split_kernel<<<(n4p + 255) / 256, 256>>>(
            (const float4*)proj_w, (uint32_t*)p_pwh, (uint32_t*)p_pwl, n4p);
    }
    // 1) qkv = x @ qkv_w^T : [8192, 2304] via bf16x3 mma.sync
    {
        dim3 grid(3 * CDIM / 128, BNTOK / 128);
        mma_gemm<false><<<grid, 256, GEMM_DYN_SMEM>>>(
            p_xh, p_xl, p_qwh, p_qwl, nullptr, p_qkv, 3 * CDIM, CDIM);
    }
    // 2) feature maps qf, kf
    {
        dim3 grid(BATCH * HDIM, NSEQ / 16);
        feat_kernel<<<grid, 256>>>(randm);
    }
    // 3) KV + S partial reduction, then merge
    {
        dim3 grid(BATCH * HDIM, NSPLIT);
        kv_kernel<<<grid, 256>>>();
        kv_reduce<<<(BATCH * HDIM * KVSZ + 255) / 256, 256>>>();
    }
    // 4) normalized output -> bf16 hi/lo [b, n, c]
    {
        dim3 grid(BATCH * HDIM, NSEQ / 64);
        out_kernel<<<grid, 256, OUT_SMEM_FLOATS * 4>>>();
    }
    // 5) final projection + bias -> d_out via bf16x3 mma.sync
    {
        dim3 grid(CDIM / 128, BNTOK / 128);
        mma_gemm<true><<<grid, 256, GEMM_DYN_SMEM>>>(
            p_oh, p_ol, p_pwh, p_pwl, proj_b, out, CDIM, CDIM);
    }
}

// round 13
// speedup vs baseline: 2.6646x; 1.0008x over previous
#include <cuda_runtime.h>
#include <cuda_bf16.h>
#include <math.h>
#include <stdint.h>

#define BATCH 8
#define NSEQ  1024
#define CDIM  768
#define HDIM  12
#define DDIM  64
#define MDIM  128
#define BNTOK (BATCH*NSEQ)          // 8192
#define KVSZ  (MDIM*DDIM + MDIM)    // 8320 floats per (b,h): KV + S
#define NSPLIT 8

typedef unsigned long long ull;

// ---- packed fp32x2 helpers (feat/kv/out kernels) --------------------------
__device__ __forceinline__ ull pack_dup(float x) {
    ull r; asm("mov.b64 %0, {%1, %1};" : "=l"(r) : "f"(x)); return r;
}
__device__ __forceinline__ void ffma2(ull& acc, ull a, ull b) {
    asm("fma.rn.f32x2 %0, %1, %2, %0;" : "+l"(acc) : "l"(a), "l"(b));
}
__device__ __forceinline__ float2 unpack2(ull v) {
    float2 r; asm("mov.b64 {%0, %1}, %2;" : "=f"(r.x), "=f"(r.y) : "l"(v)); return r;
}

// ---- baseline-PTX tensor-core helpers (sm_80+, valid on compute_103) ------
__device__ __forceinline__ uint32_t smem_to_u32(const void* p) {
    uint32_t a;
    asm("{ .reg .u64 t; cvta.to.shared.u64 t, %1; cvt.u32.u64 %0, t; }" : "=r"(a) : "l"(p));
    return a;
}
__device__ __forceinline__ void cp16(uint32_t dst, const void* src) {
    asm volatile("cp.async.cg.shared.global [%0], [%1], 16;" :: "r"(dst), "l"(src));
}
#define CP_COMMIT() asm volatile("cp.async.commit_group;" ::: "memory")
#define CP_WAIT(n)  asm volatile("cp.async.wait_group %0;" :: "n"(n) : "memory")

__device__ __forceinline__ void ldsm4(uint32_t& r0, uint32_t& r1, uint32_t& r2,
                                      uint32_t& r3, uint32_t a) {
    asm volatile("ldmatrix.sync.aligned.m8n8.x4.shared.b16 {%0,%1,%2,%3}, [%4];"
                 : "=r"(r0), "=r"(r1), "=r"(r2), "=r"(r3) : "r"(a));
}
__device__ __forceinline__ void mma16816(float* c, const uint32_t* a, const uint32_t* b) {
    asm volatile("mma.sync.aligned.m16n8k16.row.col.f32.bf16.bf16.f32 "
        "{%0,%1,%2,%3}, {%4,%5,%6,%7}, {%8,%9}, {%0,%1,%2,%3};"
        : "+f"(c[0]), "+f"(c[1]), "+f"(c[2]), "+f"(c[3])
        : "r"(a[0]), "r"(a[1]), "r"(a[2]), "r"(a[3]), "r"(b[0]), "r"(b[1]));
}

// ---- bf16 hi/lo split helpers ---------------------------------------------
__device__ __forceinline__ void split1(float v, unsigned short& h, unsigned short& l) {
    __nv_bfloat16 hb = __float2bfloat16(v);
    float r = v - __bfloat162float(hb);
    __nv_bfloat16 lb = __float2bfloat16(r);
    h = *reinterpret_cast<unsigned short*>(&hb);
    l = *reinterpret_cast<unsigned short*>(&lb);
}

// ---------------- scratch (device globals; no allocation allowed) ----------
__device__ float g_qkv[BNTOK * 3 * CDIM];                     // 75.5 MB
__device__ float g_qf [BATCH * HDIM * NSEQ * MDIM];           // 50.3 MB
__device__ float g_kf [BATCH * HDIM * NSEQ * MDIM];           // 50.3 MB
__device__ float g_kvp[NSPLIT * BATCH * HDIM * KVSZ];         // 25.5 MB
__device__ float g_kv [BATCH * HDIM * KVSZ];                  // 3.2 MB
__device__ __nv_bfloat16 g_xh [BNTOK * CDIM];                 // 12.6 MB
__device__ __nv_bfloat16 g_xl [BNTOK * CDIM];
__device__ __nv_bfloat16 g_qwh[3 * CDIM * CDIM];              // 3.5 MB
__device__ __nv_bfloat16 g_qwl[3 * CDIM * CDIM];
__device__ __nv_bfloat16 g_pwh[CDIM * CDIM];                  // 1.2 MB
__device__ __nv_bfloat16 g_pwl[CDIM * CDIM];
__device__ __nv_bfloat16 g_oh [BNTOK * CDIM];                 // 12.6 MB
__device__ __nv_bfloat16 g_ol [BNTOK * CDIM];

extern __shared__ float dyn_smem[];

// ---------------------------------------------------------------------------
// split fp32 -> bf16 hi/lo, vectorized by 4
// ---------------------------------------------------------------------------
__global__ __launch_bounds__(256) void split_kernel(
    const float4* __restrict__ src, uint32_t* __restrict__ hi,
    uint32_t* __restrict__ lo, int n4)
{
    const int i = blockIdx.x * 256 + threadIdx.x;
    if (i >= n4) return;
    const float4 v = src[i];
    unsigned short h0,h1,h2,h3, l0,l1,l2,l3;
    split1(v.x, h0, l0); split1(v.y, h1, l1);
    split1(v.z, h2, l2); split1(v.w, h3, l3);
    hi[2*i]   = (uint32_t)h0 | ((uint32_t)h1 << 16);
    hi[2*i+1] = (uint32_t)h2 | ((uint32_t)h3 << 16);
    lo[2*i]   = (uint32_t)l0 | ((uint32_t)l1 << 16);
    lo[2*i+1] = (uint32_t)l2 | ((uint32_t)l3 << 16);
}

// ---------------------------------------------------------------------------
// bf16x3 tensor-core GEMM via mma.sync: C[M,N] = A[M,K] @ Bw[N,K]^T (+bias).
// C ~= Ah*Bh + Ah*Bl + Al*Bh, fp32 accumulators.
// 128x128 CTA tile, BK=32, 8 warps (2 x 4), warp tile 64x32, cp.async
// double buffering, ONE __syncthreads per k-chunk, product-major MMA order
// (no back-to-back RAW on the same accumulator).
// ---------------------------------------------------------------------------
#define PITCHB   80                          // bytes per 32-bf16 row in smem
#define TILE_B   (128 * PITCHB)              // 10240 B per operand tile
#define STAGE_B  (4 * TILE_B)                // AH AL BH BL
#define OFF_AH   0
#define OFF_AL   TILE_B
#define OFF_BH   (2 * TILE_B)
#define OFF_BL   (3 * TILE_B)
#define GEMM_DYN_SMEM (2 * STAGE_B)          // 81920 B

__device__ __forceinline__ void stage_tile(uint32_t sdst,
    const __nv_bfloat16* __restrict__ g, int ld, int k0, int tid)
{
    // 128 rows x 32 bf16 = 512 x 16B chunks; 256 threads x 2
    #pragma unroll
    for (int i = 0; i < 2; i++) {
        const int c   = tid + i * 256;
        const int row = c >> 2, c16 = c & 3;
        cp16(sdst + row * PITCHB + c16 * 16,
             g + (size_t)row * ld + k0 + c16 * 8);
    }
}

template<bool ADD_BIAS>
__global__ __launch_bounds__(256) void mma_gemm(
    const __nv_bfloat16* __restrict__ Ah, const __nv_bfloat16* __restrict__ Al,
    const __nv_bfloat16* __restrict__ Bh, const __nv_bfloat16* __restrict__ Bl,
    const float* __restrict__ bias, float* __restrict__ C, int Nd, int Kd)
{
    const uint32_t sb = smem_to_u32(dyn_smem);
    const int tid  = threadIdx.x;
    const int wid  = tid >> 5, lane = tid & 31;
    const int wm   = wid & 1;          // 0..1 -> 64-row slab
    const int wn   = wid >> 1;         // 0..3 -> 32-col slab
    const int row0 = blockIdx.y * 128, col0 = blockIdx.x * 128;

    // ldmatrix per-lane offsets
    const int t8   = lane & 7;
    const int g01  = (lane >> 3) & 1;
    const int g2   = lane >> 4;
    const int mrow = g01 * 8 + t8;               // row within 16
    const int kofw = g2 * 8;                     // k within 16

    const __nv_bfloat16* gAh = Ah + (size_t)row0 * Kd;
    const __nv_bfloat16* gAl = Al + (size_t)row0 * Kd;
    const __nv_bfloat16* gBh = Bh + (size_t)col0 * Kd;
    const __nv_bfloat16* gBl = Bl + (size_t)col0 * Kd;

    float acc[4][4][4];
    #pragma unroll
    for (int i = 0; i < 4; i++)
        #pragma unroll
        for (int j = 0; j < 4; j++)
            #pragma unroll
            for (int r = 0; r < 4; r++) acc[i][j][r] = 0.f;

    const int nchunk = Kd >> 5;   // BK=32

    // preload stage 0
    stage_tile(sb + OFF_AH, gAh, Kd, 0, tid);
    stage_tile(sb + OFF_AL, gAl, Kd, 0, tid);
    stage_tile(sb + OFF_BH, gBh, Kd, 0, tid);
    stage_tile(sb + OFF_BL, gBl, Kd, 0, tid);
    CP_COMMIT();

    for (int c = 0; c < nchunk; c++) {
        CP_WAIT(0);          // stage c resident
        __syncthreads();     // all warps see it; all finished chunk c-1
        if (c + 1 < nchunk) {
            // prefetch c+1 into the other buffer, overlapped with compute c
            const uint32_t nb = sb + ((c + 1) & 1) * STAGE_B;
            const int k0 = (c + 1) << 5;
            stage_tile(nb + OFF_AH, gAh, Kd, k0, tid);
            stage_tile(nb + OFF_AL, gAl, Kd, k0, tid);
            stage_tile(nb + OFF_BH, gBh, Kd, k0, tid);
            stage_tile(nb + OFF_BL, gBl, Kd, k0, tid);
            CP_COMMIT();
        }

        const uint32_t st = sb + (c & 1) * STAGE_B;
        #pragma unroll
        for (int ks = 0; ks < 2; ks++) {
            const uint32_t kb = ks * 32 + kofw * 2;   // byte offset along K
            uint32_t ah[4][4], al[4][4];
            #pragma unroll
            for (int mf = 0; mf < 4; mf++) {
                const uint32_t ra = (wm * 64 + mf * 16 + mrow) * PITCHB + kb;
                ldsm4(ah[mf][0], ah[mf][1], ah[mf][2], ah[mf][3], st + OFF_AH + ra);
                ldsm4(al[mf][0], al[mf][1], al[mf][2], al[mf][3], st + OFF_AL + ra);
            }
            uint32_t bh[4][2], bl[4][2];
            #pragma unroll
            for (int nf2 = 0; nf2 < 2; nf2++) {
                const uint32_t rb = (wn * 32 + nf2 * 16 + mrow) * PITCHB + kb;
                uint32_t r0, r1, r2, r3;
                ldsm4(r0, r1, r2, r3, st + OFF_BH + rb);
                bh[nf2*2][0] = r0; bh[nf2*2+1][0] = r1;
                bh[nf2*2][1] = r2; bh[nf2*2+1][1] = r3;
                ldsm4(r0, r1, r2, r3, st + OFF_BL + rb);
                bl[nf2*2][0] = r0; bl[nf2*2+1][0] = r1;
                bl[nf2*2][1] = r2; bl[nf2*2+1][1] = r3;
            }
            // product-major order: 16 distinct accumulators between revisits
            #pragma unroll
            for (int mf = 0; mf < 4; mf++)
                #pragma unroll
                for (int nf = 0; nf < 4; nf++)
                    mma16816(acc[mf][nf], ah[mf], bh[nf]);   // Ah*Bh
            #pragma unroll
            for (int mf = 0; mf < 4; mf++)
                #pragma unroll
                for (int nf = 0; nf < 4; nf++)
                    mma16816(acc[mf][nf], ah[mf], bl[nf]);   // Ah*Bl
            #pragma unroll
            for (int mf = 0; mf < 4; mf++)
                #pragma unroll
                for (int nf = 0; nf < 4; nf++)
                    mma16816(acc[mf][nf], al[mf], bh[nf]);   // Al*Bh
        }
    }

    // epilogue: fragment layout -> float2 stores
    const int rg = lane >> 2;          // 0..7
    const int cp = (lane & 3) * 2;     // 0,2,4,6
    #pragma unroll
    for (int mf = 0; mf < 4; mf++) {
        #pragma unroll
        for (int nf = 0; nf < 4; nf++) {
            const int col = col0 + wn * 32 + nf * 8 + cp;
            float b0 = 0.f, b1 = 0.f;
            if (ADD_BIAS) { b0 = bias[col]; b1 = bias[col + 1]; }
            const int r0 = row0 + wm * 64 + mf * 16 + rg;
            *reinterpret_cast<float2*>(&C[(size_t)r0 * Nd + col]) =
                make_float2(acc[mf][nf][0] + b0, acc[mf][nf][1] + b1);
            *reinterpret_cast<float2*>(&C[(size_t)(r0 + 8) * Nd + col]) =
                make_float2(acc[mf][nf][2] + b0, acc[mf][nf][3] + b1);
        }
    }
}

// ---------------------------------------------------------------------------
// Feature map q AND k (unchanged)
// ---------------------------------------------------------------------------
__global__ __launch_bounds__(256) void feat_kernel(const float* __restrict__ R)
{
    const int bh = blockIdx.x;
    const int b  = bh / HDIM, h = bh % HDIM;
    const int n0 = blockIdx.y * 16;
    const int tid  = threadIdx.x;
    const int lane = tid & 31;
    const int wrp  = tid >> 5;

    __shared__ float Rs[DDIM][MDIM];
    __shared__ float zq[16][DDIM];
    __shared__ float zk[16][DDIM];

    const float sq   = 0.3535533905932738f;
    const float minv = 0.08838834764831845f;

    #pragma unroll
    for (int i = tid; i < DDIM * MDIM / 4; i += 256) {
        float4 r4 = *reinterpret_cast<const float4*>(&R[h * DDIM * MDIM + i * 4]);
        *reinterpret_cast<float4*>(&Rs[0][0] + i * 4) = r4;
    }
    {
        const int r = tid >> 4, d4 = (tid & 15) * 4;
        const size_t base = (size_t)(b * NSEQ + n0 + r) * (3 * CDIM) + h * DDIM + d4;
        float4 q4 = *reinterpret_cast<const float4*>(&g_qkv[base]);
        float4 k4 = *reinterpret_cast<const float4*>(&g_qkv[base + CDIM]);
        q4.x *= sq; q4.y *= sq; q4.z *= sq; q4.w *= sq;
        k4.x *= sq; k4.y *= sq; k4.z *= sq; k4.w *= sq;
        *reinterpret_cast<float4*>(&zq[r][d4]) = q4;
        *reinterpret_cast<float4*>(&zk[r][d4]) = k4;
    }
    __syncthreads();

    ull aq[2][2], ak[2][2];
    float nq[2], nk[2];
    #pragma unroll
    for (int i = 0; i < 2; i++) {
        nq[i] = 0.f; nk[i] = 0.f;
        aq[i][0] = aq[i][1] = 0ULL;
        ak[i][0] = ak[i][1] = 0ULL;
    }

    #pragma unroll 8
    for (int d = 0; d < DDIM; d++) {
        longlong2 rp = *reinterpret_cast<const longlong2*>(&Rs[d][lane * 4]);
        #pragma unroll
        for (int i = 0; i < 2; i++) {
            const float qv = zq[wrp * 2 + i][d];
            const float kv = zk[wrp * 2 + i][d];
            const ull qd = pack_dup(qv), kd = pack_dup(kv);
            ffma2(aq[i][0], qd, (ull)rp.x); ffma2(aq[i][1], qd, (ull)rp.y);
            ffma2(ak[i][0], kd, (ull)rp.x); ffma2(ak[i][1], kd, (ull)rp.y);
            nq[i] += qv * qv;           nk[i] += kv * kv;
        }
    }

    #pragma unroll
    for (int i = 0; i < 2; i++) {
        const int n = n0 + wrp * 2 + i;
        const size_t o = ((size_t)bh * NSEQ + n) * MDIM + lane * 4;
        const float hq = 0.5f * nq[i], hk = 0.5f * nk[i];
        float2 q0 = unpack2(aq[i][0]), q1 = unpack2(aq[i][1]);
        float2 k0 = unpack2(ak[i][0]), k1 = unpack2(ak[i][1]);
        float4 fq = make_float4(expf(q0.x-hq)*minv, expf(q0.y-hq)*minv,
                                expf(q1.x-hq)*minv, expf(q1.y-hq)*minv);
        float4 fk = make_float4(expf(k0.x-hk)*minv, expf(k0.y-hk)*minv,
                                expf(k1.x-hk)*minv, expf(k1.y-hk)*minv);
        *reinterpret_cast<float4*>(&g_qf[o]) = fq;
        *reinterpret_cast<float4*>(&g_kf[o]) = fk;
    }
}

// ---------------------------------------------------------------------------
// Partial KV + S (unchanged)
// ---------------------------------------------------------------------------
__global__ __launch_bounds__(256) void kv_kernel()
{
    const int bh = blockIdx.x;
    const int b  = bh / HDIM, h = bh % HDIM;
    const int p  = blockIdx.y;
    const int tm = threadIdx.x >> 4;
    const int td = threadIdx.x & 15;

    __shared__ float kfs[32][MDIM];
    __shared__ float vs [32][DDIM];

    ull acc[8][2];
    float s[8];
    #pragma unroll
    for (int i = 0; i < 8; i++) { s[i] = 0.f; acc[i][0] = acc[i][1] = 0ULL; }

    const int nbase = p * (NSEQ / NSPLIT);
    for (int n0 = nbase; n0 < nbase + NSEQ / NSPLIT; n0 += 32) {
        __syncthreads();
        #pragma unroll
        for (int i = threadIdx.x; i < 32 * MDIM / 4; i += 256) {
            const int nn = i >> 5, m4 = (i & 31) * 4;
            *reinterpret_cast<float4*>(&kfs[nn][m4]) =
                *reinterpret_cast<const float4*>(&g_kf[((size_t)bh * NSEQ + n0 + nn) * MDIM + m4]);
        }
        #pragma unroll
        for (int i = threadIdx.x; i < 32 * DDIM / 4; i += 256) {
            const int nn = i >> 4, d4 = (i & 15) * 4;
            *reinterpret_cast<float4*>(&vs[nn][d4]) =
                *reinterpret_cast<const float4*>(
                    &g_qkv[(size_t)(b * NSEQ + n0 + nn) * (3 * CDIM) + 2 * CDIM + h * DDIM + d4]);
        }
        __syncthreads();
        #pragma unroll 4
        for (int nn = 0; nn < 32; nn++) {
            float a[8];
            #pragma unroll
            for (int i = 0; i < 8; i++) a[i] = kfs[nn][tm * 8 + i];
            longlong2 bp = *reinterpret_cast<const longlong2*>(&vs[nn][td * 4]);
            #pragma unroll
            for (int i = 0; i < 8; i++) {
                const ull ad = pack_dup(a[i]);
                ffma2(acc[i][0], ad, (ull)bp.x);
                ffma2(acc[i][1], ad, (ull)bp.y);
                s[i] += a[i];
            }
        }
    }

    float* kvb = g_kvp + ((size_t)p * (BATCH * HDIM) + bh) * KVSZ;
    #pragma unroll
    for (int i = 0; i < 8; i++) {
        const int m = tm * 8 + i;
        float2 p0 = unpack2(acc[i][0]), p1 = unpack2(acc[i][1]);
        *reinterpret_cast<float4*>(&kvb[m * DDIM + td * 4]) =
            make_float4(p0.x, p0.y, p1.x, p1.y);
        if (td == 0) kvb[MDIM * DDIM + m] = s[i];
    }
}

__global__ __launch_bounds__(256) void kv_reduce()
{
    const int i = blockIdx.x * 256 + threadIdx.x;
    if (i < BATCH * HDIM * KVSZ) {
        float s = 0.f;
        #pragma unroll
        for (int pp = 0; pp < NSPLIT; pp++)
            s += g_kvp[(size_t)pp * (BATCH * HDIM * KVSZ) + i];
        g_kv[i] = s;
    }
}

// ---------------------------------------------------------------------------
// out kernel: writes bf16 hi/lo directly (feeds proj GEMM)
// ---------------------------------------------------------------------------
#define QF_PITCH 132
#define OUT_SMEM_FLOATS (KVSZ + 64 * QF_PITCH)

__global__ __launch_bounds__(256) void out_kernel()
{
    float* osm = dyn_smem;   // [0,8192): KV  [8192,8320): S  [8320,..): qf
    const int bh = blockIdx.x;
    const int b  = bh / HDIM, h = bh % HDIM;
    const int n0 = blockIdx.y * 64;
    const int tr = threadIdx.x >> 4;
    const int tc = threadIdx.x & 15;

    const float* kvb = g_kv + (size_t)bh * KVSZ;
    #pragma unroll
    for (int i = threadIdx.x; i < KVSZ / 4; i += 256)
        *reinterpret_cast<float4*>(&osm[i * 4]) =
            *reinterpret_cast<const float4*>(&kvb[i * 4]);
    #pragma unroll
    for (int i = threadIdx.x; i < 64 * 32; i += 256) {
        const int r = i >> 5, d4 = (i & 31) * 4;
        *reinterpret_cast<float4*>(&osm[KVSZ + r * QF_PITCH + d4]) =
            *reinterpret_cast<const float4*>(&g_qf[((size_t)bh * NSEQ + n0 + r) * MDIM + d4]);
    }
    __syncthreads();

    ull acc[4][2];
    float den[4];
    #pragma unroll
    for (int i = 0; i < 4; i++) { den[i] = 0.f; acc[i][0] = acc[i][1] = 0ULL; }

    #pragma unroll 4
    for (int m = 0; m < MDIM; m++) {
        longlong2 kvp = *reinterpret_cast<const longlong2*>(&osm[m * DDIM + tc * 4]);
        const float sv = osm[MDIM * DDIM + m];
        #pragma unroll
        for (int i = 0; i < 4; i++) {
            const float q = osm[KVSZ + (tr * 4 + i) * QF_PITCH + m];
            const ull qd = pack_dup(q);
            ffma2(acc[i][0], qd, (ull)kvp.x);
            ffma2(acc[i][1], qd, (ull)kvp.y);
            den[i] += q * sv;
        }
    }

    #pragma unroll
    for (int i = 0; i < 4; i++) {
        const float inv = 1.0f / fmaxf(den[i], 1e-12f);
        const int n = n0 + tr * 4 + i;
        float2 p0 = unpack2(acc[i][0]), p1 = unpack2(acc[i][1]);
        const float r0 = p0.x*inv, r1 = p0.y*inv, r2 = p1.x*inv, r3 = p1.y*inv;
        unsigned short h0,h1,h2,h3, l0,l1,l2,l3;
        split1(r0, h0, l0); split1(r1, h1, l1);
        split1(r2, h2, l2); split1(r3, h3, l3);
        const size_t o = (size_t)(b * NSEQ + n) * CDIM + h * DDIM + tc * 4;
        uint32_t* oh = reinterpret_cast<uint32_t*>(&g_oh[o]);
        uint32_t* ol = reinterpret_cast<uint32_t*>(&g_ol[o]);
        oh[0] = (uint32_t)h0 | ((uint32_t)h1 << 16);
        oh[1] = (uint32_t)h2 | ((uint32_t)h3 << 16);
        ol[0] = (uint32_t)l0 | ((uint32_t)l1 << 16);
        ol[1] = (uint32_t)l2 | ((uint32_t)l3 << 16);
    }
}

// ---------------------------------------------------------------------------
extern "C" void kernel_launch(void* const* d_in, const int* in_sizes, int n_in,
                              void* d_out, int out_size)
{
    const float* x      = (const float*)d_in[0];
    const float* qkv_w  = (const float*)d_in[1];
    const float* proj_w = (const float*)d_in[2];
    const float* proj_b = (const float*)d_in[3];
    const float* randm  = (const float*)d_in[4];
    float* out = (float*)d_out;

    float *p_qkv;
    cudaGetSymbolAddress((void**)&p_qkv, g_qkv);
    __nv_bfloat16 *p_xh, *p_xl, *p_qwh, *p_qwl, *p_pwh, *p_pwl, *p_oh, *p_ol;
    cudaGetSymbolAddress((void**)&p_xh,  g_xh);
    cudaGetSymbolAddress((void**)&p_xl,  g_xl);
    cudaGetSymbolAddress((void**)&p_qwh, g_qwh);
    cudaGetSymbolAddress((void**)&p_qwl, g_qwl);
    cudaGetSymbolAddress((void**)&p_pwh, g_pwh);
    cudaGetSymbolAddress((void**)&p_pwl, g_pwl);
    cudaGetSymbolAddress((void**)&p_oh,  g_oh);
    cudaGetSymbolAddress((void**)&p_ol,  g_ol);

    cudaFuncSetAttribute(out_kernel, cudaFuncAttributeMaxDynamicSharedMemorySize,
                         OUT_SMEM_FLOATS * 4);
    cudaFuncSetAttribute(mma_gemm<false>, cudaFuncAttributeMaxDynamicSharedMemorySize,
                         GEMM_DYN_SMEM);
    cudaFuncSetAttribute(mma_gemm<true>, cudaFuncAttributeMaxDynamicSharedMemorySize,
                         GEMM_DYN_SMEM);

    // 0) hi/lo splits
    {
        const int n4x = BNTOK * CDIM / 4;
        split_kernel<<<(n4x + 255) / 256, 256>>>(
            (const float4*)x, (uint32_t*)p_xh, (uint32_t*)p_xl, n4x);
        const int n4q = 3 * CDIM * CDIM / 4;
        split_kernel<<<(n4q + 255) / 256, 256>>>(
            (const float4*)qkv_w, (uint32_t*)p_qwh, (uint32_t*)p_qwl, n4q);
        const int n4p = CDIM * CDIM / 4;
        split_kernel<<<(n4p + 255) / 256, 256>>>(
            (const float4*)proj_w, (uint32_t*)p_pwh, (uint32_t*)p_pwl, n4p);
    }
    // 1) qkv = x @ qkv_w^T : [8192, 2304] via bf16x3 mma.sync
    {
        dim3 grid(3 * CDIM / 128, BNTOK / 128);
        mma_gemm<false><<<grid, 256, GEMM_DYN_SMEM>>>(
            p_xh, p_xl, p_qwh, p_qwl, nullptr, p_qkv, 3 * CDIM, CDIM);
    }
    // 2) feature maps qf, kf
    {
        dim3 grid(BATCH * HDIM, NSEQ / 16);
        feat_kernel<<<grid, 256>>>(randm);
    }
    // 3) KV + S partial reduction, then merge
    {
        dim3 grid(BATCH * HDIM, NSPLIT);
        kv_kernel<<<grid, 256>>>();
        kv_reduce<<<(BATCH * HDIM * KVSZ + 255) / 256, 256>>>();
    }
    // 4) normalized output -> bf16 hi/lo [b, n, c]
    {
        dim3 grid(BATCH * HDIM, NSEQ / 64);
        out_kernel<<<grid, 256, OUT_SMEM_FLOATS * 4>>>();
    }
    // 5) final projection + bias -> d_out via bf16x3 mma.sync
    {
        dim3 grid(CDIM / 128, BNTOK / 128);
        mma_gemm<true><<<grid, 256, GEMM_DYN_SMEM>>>(
            p_oh, p_ol, p_pwh, p_pwl, proj_b, out, CDIM, CDIM);
    }
}

// round 14
// speedup vs baseline: 3.3925x; 1.2732x over previous
#include <cuda_runtime.h>
#include <cuda_bf16.h>
#include <cuda_fp16.h>
#include <math.h>
#include <stdint.h>

#define BATCH 8
#define NSEQ  1024
#define CDIM  768
#define HDIM  12
#define DDIM  64
#define MDIM  128
#define BNTOK (BATCH*NSEQ)          // 8192
#define KVSZ  (MDIM*DDIM + MDIM)    // 8320 floats per (b,h): KV + S
#define NSPLIT 8

typedef unsigned long long ull;

// ---- packed fp32x2 helpers (feat/kv/out kernels) --------------------------
__device__ __forceinline__ ull pack_dup(float x) {
    ull r; asm("mov.b64 %0, {%1, %1};" : "=l"(r) : "f"(x)); return r;
}
__device__ __forceinline__ void ffma2(ull& acc, ull a, ull b) {
    asm("fma.rn.f32x2 %0, %1, %2, %0;" : "+l"(acc) : "l"(a), "l"(b));
}
__device__ __forceinline__ float2 unpack2(ull v) {
    float2 r; asm("mov.b64 {%0, %1}, %2;" : "=f"(r.x), "=f"(r.y) : "l"(v)); return r;
}

// ---- baseline-PTX tensor-core helpers (sm_80+, valid on compute_103) ------
__device__ __forceinline__ uint32_t smem_to_u32(const void* p) {
    uint32_t a;
    asm("{ .reg .u64 t; cvta.to.shared.u64 t, %1; cvt.u32.u64 %0, t; }" : "=r"(a) : "l"(p));
    return a;
}
__device__ __forceinline__ void cp16(uint32_t dst, const void* src) {
    asm volatile("cp.async.cg.shared.global [%0], [%1], 16;" :: "r"(dst), "l"(src));
}
#define CP_COMMIT() asm volatile("cp.async.commit_group;" ::: "memory")
#define CP_WAIT(n)  asm volatile("cp.async.wait_group %0;" :: "n"(n) : "memory")

__device__ __forceinline__ void ldsm4(uint32_t& r0, uint32_t& r1, uint32_t& r2,
                                      uint32_t& r3, uint32_t a) {
    asm volatile("ldmatrix.sync.aligned.m8n8.x4.shared.b16 {%0,%1,%2,%3}, [%4];"
                 : "=r"(r0), "=r"(r1), "=r"(r2), "=r"(r3) : "r"(a));
}
// fp16 MMA, fp32 accumulate
__device__ __forceinline__ void mma16816(float* c, const uint32_t* a, const uint32_t* b) {
    asm volatile("mma.sync.aligned.m16n8k16.row.col.f32.f16.f16.f32 "
        "{%0,%1,%2,%3}, {%4,%5,%6,%7}, {%8,%9}, {%0,%1,%2,%3};"
        : "+f"(c[0]), "+f"(c[1]), "+f"(c[2]), "+f"(c[3])
        : "r"(a[0]), "r"(a[1]), "r"(a[2]), "r"(a[3]), "r"(b[0]), "r"(b[1]));
}

// ---- fp16 split helpers ----------------------------------------------------
__device__ __forceinline__ void split1h(float v, __half& h, __half& l) {
    h = __float2half_rn(v);
    l = __float2half_rn(v - __half2float(h));
}

// ---------------- scratch (device globals; no allocation allowed) ----------
__device__ float g_qkv[BNTOK * 3 * CDIM];                     // 75.5 MB
__device__ float g_qf [BATCH * HDIM * NSEQ * MDIM];           // 50.3 MB
__device__ float g_kf [BATCH * HDIM * NSEQ * MDIM];           // 50.3 MB
__device__ float g_kvp[NSPLIT * BATCH * HDIM * KVSZ];         // 25.5 MB
__device__ float g_kv [BATCH * HDIM * KVSZ];                  // 3.2 MB
__device__ __half g_xh [BNTOK * CDIM];                        // 12.6 MB (A fp16)
__device__ __half g_qwh[3 * CDIM * CDIM];                     // weights hi
__device__ __half g_qwl[3 * CDIM * CDIM];                     // weights lo
__device__ __half g_pwh[CDIM * CDIM];
__device__ __half g_pwl[CDIM * CDIM];
__device__ __half g_oh [BNTOK * CDIM];                        // o fp16

extern __shared__ float dyn_smem[];

// ---------------------------------------------------------------------------
// fp32 -> fp16 (single), vectorized by 4
// ---------------------------------------------------------------------------
__global__ __launch_bounds__(256) void tohalf_kernel(
    const float4* __restrict__ src, uint32_t* __restrict__ dst, int n4)
{
    const int i = blockIdx.x * 256 + threadIdx.x;
    if (i >= n4) return;
    const float4 v = src[i];
    __half2 p0 = __floats2half2_rn(v.x, v.y);
    __half2 p1 = __floats2half2_rn(v.z, v.w);
    dst[2*i]   = *reinterpret_cast<uint32_t*>(&p0);
    dst[2*i+1] = *reinterpret_cast<uint32_t*>(&p1);
}

// ---------------------------------------------------------------------------
// fp32 -> fp16 hi + fp16 residual, vectorized by 4 (weights)
// ---------------------------------------------------------------------------
__global__ __launch_bounds__(256) void splith_kernel(
    const float4* __restrict__ src, uint32_t* __restrict__ hi,
    uint32_t* __restrict__ lo, int n4)
{
    const int i = blockIdx.x * 256 + threadIdx.x;
    if (i >= n4) return;
    const float4 v = src[i];
    __half h0,h1,h2,h3, l0,l1,l2,l3;
    split1h(v.x, h0, l0); split1h(v.y, h1, l1);
    split1h(v.z, h2, l2); split1h(v.w, h3, l3);
    __half2 ph0 = __halves2half2(h0, h1), ph1 = __halves2half2(h2, h3);
    __half2 pl0 = __halves2half2(l0, l1), pl1 = __halves2half2(l2, l3);
    hi[2*i]   = *reinterpret_cast<uint32_t*>(&ph0);
    hi[2*i+1] = *reinterpret_cast<uint32_t*>(&ph1);
    lo[2*i]   = *reinterpret_cast<uint32_t*>(&pl0);
    lo[2*i+1] = *reinterpret_cast<uint32_t*>(&pl1);
}

// ---------------------------------------------------------------------------
// fp16x2 tensor-core GEMM via mma.sync: C[M,N] = A[M,K] @ Bw[N,K]^T (+bias).
// C ~= A16*Bh + A16*Bl, fp32 accumulators (B = weight side, split fp16 hi/lo).
// 128x128 CTA tile, BK=32, 8 warps (2 x 4), warp tile 64x32, cp.async
// double buffering, one __syncthreads per k-chunk.
// ---------------------------------------------------------------------------
#define PITCHB   80                          // bytes per 32-fp16 row in smem
#define TILE_B   (128 * PITCHB)              // 10240 B per operand tile
#define STAGE_B  (3 * TILE_B)                // A BH BL
#define OFF_A    0
#define OFF_BH   TILE_B
#define OFF_BL   (2 * TILE_B)
#define GEMM_DYN_SMEM (2 * STAGE_B)          // 61440 B

__device__ __forceinline__ void stage_tile(uint32_t sdst,
    const __half* __restrict__ g, int ld, int k0, int tid)
{
    // 128 rows x 32 fp16 = 512 x 16B chunks; 256 threads x 2
    #pragma unroll
    for (int i = 0; i < 2; i++) {
        const int c   = tid + i * 256;
        const int row = c >> 2, c16 = c & 3;
        cp16(sdst + row * PITCHB + c16 * 16,
             g + (size_t)row * ld + k0 + c16 * 8);
    }
}

template<bool ADD_BIAS>
__global__ __launch_bounds__(256) void mma_gemm(
    const __half* __restrict__ A16,
    const __half* __restrict__ Bh, const __half* __restrict__ Bl,
    const float* __restrict__ bias, float* __restrict__ C, int Nd, int Kd)
{
    const uint32_t sb = smem_to_u32(dyn_smem);
    const int tid  = threadIdx.x;
    const int wid  = tid >> 5, lane = tid & 31;
    const int wm   = wid & 1;          // 0..1 -> 64-row slab
    const int wn   = wid >> 1;         // 0..3 -> 32-col slab
    const int row0 = blockIdx.y * 128, col0 = blockIdx.x * 128;

    // ldmatrix per-lane offsets
    const int t8   = lane & 7;
    const int g01  = (lane >> 3) & 1;
    const int g2   = lane >> 4;
    const int mrow = g01 * 8 + t8;               // row within 16
    const int kofw = g2 * 8;                     // k within 16

    const __half* gA  = A16 + (size_t)row0 * Kd;
    const __half* gBh = Bh  + (size_t)col0 * Kd;
    const __half* gBl = Bl  + (size_t)col0 * Kd;

    float acc[4][4][4];
    #pragma unroll
    for (int i = 0; i < 4; i++)
        #pragma unroll
        for (int j = 0; j < 4; j++)
            #pragma unroll
            for (int r = 0; r < 4; r++) acc[i][j][r] = 0.f;

    const int nchunk = Kd >> 5;   // BK=32

    // preload stage 0
    stage_tile(sb + OFF_A,  gA,  Kd, 0, tid);
    stage_tile(sb + OFF_BH, gBh, Kd, 0, tid);
    stage_tile(sb + OFF_BL, gBl, Kd, 0, tid);
    CP_COMMIT();

    for (int c = 0; c < nchunk; c++) {
        CP_WAIT(0);          // stage c resident
        __syncthreads();     // all warps see it; all finished chunk c-1
        if (c + 1 < nchunk) {
            const uint32_t nb = sb + ((c + 1) & 1) * STAGE_B;
            const int k0 = (c + 1) << 5;
            stage_tile(nb + OFF_A,  gA,  Kd, k0, tid);
            stage_tile(nb + OFF_BH, gBh, Kd, k0, tid);
            stage_tile(nb + OFF_BL, gBl, Kd, k0, tid);
            CP_COMMIT();
        }

        const uint32_t st = sb + (c & 1) * STAGE_B;
        #pragma unroll
        for (int ks = 0; ks < 2; ks++) {
            const uint32_t kb = ks * 32 + kofw * 2;   // byte offset along K
            uint32_t ah[4][4];
            #pragma unroll
            for (int mf = 0; mf < 4; mf++) {
                const uint32_t ra = (wm * 64 + mf * 16 + mrow) * PITCHB + kb;
                ldsm4(ah[mf][0], ah[mf][1], ah[mf][2], ah[mf][3], st + OFF_A + ra);
            }
            uint32_t bh[4][2], bl[4][2];
            #pragma unroll
            for (int nf2 = 0; nf2 < 2; nf2++) {
                const uint32_t rb = (wn * 32 + nf2 * 16 + mrow) * PITCHB + kb;
                uint32_t r0, r1, r2, r3;
                ldsm4(r0, r1, r2, r3, st + OFF_BH + rb);
                bh[nf2*2][0] = r0; bh[nf2*2+1][0] = r1;
                bh[nf2*2][1] = r2; bh[nf2*2+1][1] = r3;
                ldsm4(r0, r1, r2, r3, st + OFF_BL + rb);
                bl[nf2*2][0] = r0; bl[nf2*2+1][0] = r1;
                bl[nf2*2][1] = r2; bl[nf2*2+1][1] = r3;
            }
            // product-major: 16 distinct accumulators between revisits
            #pragma unroll
            for (int mf = 0; mf < 4; mf++)
                #pragma unroll
                for (int nf = 0; nf < 4; nf++)
                    mma16816(acc[mf][nf], ah[mf], bh[nf]);   // A*Bh
            #pragma unroll
            for (int mf = 0; mf < 4; mf++)
                #pragma unroll
                for (int nf = 0; nf < 4; nf++)
                    mma16816(acc[mf][nf], ah[mf], bl[nf]);   // A*Bl
        }
    }

    // epilogue: fragment layout -> float2 stores
    const int rg = lane >> 2;          // 0..7
    const int cp = (lane & 3) * 2;     // 0,2,4,6
    #pragma unroll
    for (int mf = 0; mf < 4; mf++) {
        #pragma unroll
        for (int nf = 0; nf < 4; nf++) {
            const int col = col0 + wn * 32 + nf * 8 + cp;
            float b0 = 0.f, b1 = 0.f;
            if (ADD_BIAS) { b0 = bias[col]; b1 = bias[col + 1]; }
            const int r0 = row0 + wm * 64 + mf * 16 + rg;
            *reinterpret_cast<float2*>(&C[(size_t)r0 * Nd + col]) =
                make_float2(acc[mf][nf][0] + b0, acc[mf][nf][1] + b1);
            *reinterpret_cast<float2*>(&C[(size_t)(r0 + 8) * Nd + col]) =
                make_float2(acc[mf][nf][2] + b0, acc[mf][nf][3] + b1);
        }
    }
}

// ---------------------------------------------------------------------------
// Feature map q AND k (unchanged)
// ---------------------------------------------------------------------------
__global__ __launch_bounds__(256) void feat_kernel(const float* __restrict__ R)
{
    const int bh = blockIdx.x;
    const int b  = bh / HDIM, h = bh % HDIM;
    const int n0 = blockIdx.y * 16;
    const int tid  = threadIdx.x;
    const int lane = tid & 31;
    const int wrp  = tid >> 5;

    __shared__ float Rs[DDIM][MDIM];
    __shared__ float zq[16][DDIM];
    __shared__ float zk[16][DDIM];

    const float sq   = 0.3535533905932738f;
    const float minv = 0.08838834764831845f;

    #pragma unroll
    for (int i = tid; i < DDIM * MDIM / 4; i += 256) {
        float4 r4 = *reinterpret_cast<const float4*>(&R[h * DDIM * MDIM + i * 4]);
        *reinterpret_cast<float4*>(&Rs[0][0] + i * 4) = r4;
    }
    {
        const int r = tid >> 4, d4 = (tid & 15) * 4;
        const size_t base = (size_t)(b * NSEQ + n0 + r) * (3 * CDIM) + h * DDIM + d4;
        float4 q4 = *reinterpret_cast<const float4*>(&g_qkv[base]);
        float4 k4 = *reinterpret_cast<const float4*>(&g_qkv[base + CDIM]);
        q4.x *= sq; q4.y *= sq; q4.z *= sq; q4.w *= sq;
        k4.x *= sq; k4.y *= sq; k4.z *= sq; k4.w *= sq;
        *reinterpret_cast<float4*>(&zq[r][d4]) = q4;
        *reinterpret_cast<float4*>(&zk[r][d4]) = k4;
    }
    __syncthreads();

    ull aq[2][2], ak[2][2];
    float nq[2], nk[2];
    #pragma unroll
    for (int i = 0; i < 2; i++) {
        nq[i] = 0.f; nk[i] = 0.f;
        aq[i][0] = aq[i][1] = 0ULL;
        ak[i][0] = ak[i][1] = 0ULL;
    }

    #pragma unroll 8
    for (int d = 0; d < DDIM; d++) {
        longlong2 rp = *reinterpret_cast<const longlong2*>(&Rs[d][lane * 4]);
        #pragma unroll
        for (int i = 0; i < 2; i++) {
            const float qv = zq[wrp * 2 + i][d];
            const float kv = zk[wrp * 2 + i][d];
            const ull qd = pack_dup(qv), kd = pack_dup(kv);
            ffma2(aq[i][0], qd, (ull)rp.x); ffma2(aq[i][1], qd, (ull)rp.y);
            ffma2(ak[i][0], kd, (ull)rp.x); ffma2(ak[i][1], kd, (ull)rp.y);
            nq[i] += qv * qv;           nk[i] += kv * kv;
        }
    }

    #pragma unroll
    for (int i = 0; i < 2; i++) {
        const int n = n0 + wrp * 2 + i;
        const size_t o = ((size_t)bh * NSEQ + n) * MDIM + lane * 4;
        const float hq = 0.5f * nq[i], hk = 0.5f * nk[i];
        float2 q0 = unpack2(aq[i][0]), q1 = unpack2(aq[i][1]);
        float2 k0 = unpack2(ak[i][0]), k1 = unpack2(ak[i][1]);
        float4 fq = make_float4(expf(q0.x-hq)*minv, expf(q0.y-hq)*minv,
                                expf(q1.x-hq)*minv, expf(q1.y-hq)*minv);
        float4 fk = make_float4(expf(k0.x-hk)*minv, expf(k0.y-hk)*minv,
                                expf(k1.x-hk)*minv, expf(k1.y-hk)*minv);
        *reinterpret_cast<float4*>(&g_qf[o]) = fq;
        *reinterpret_cast<float4*>(&g_kf[o]) = fk;
    }
}

// ---------------------------------------------------------------------------
// Partial KV + S (unchanged)
// ---------------------------------------------------------------------------
__global__ __launch_bounds__(256) void kv_kernel()
{
    const int bh = blockIdx.x;
    const int b  = bh / HDIM, h = bh % HDIM;
    const int p  = blockIdx.y;
    const int tm = threadIdx.x >> 4;
    const int td = threadIdx.x & 15;

    __shared__ float kfs[32][MDIM];
    __shared__ float vs [32][DDIM];

    ull acc[8][2];
    float s[8];
    #pragma unroll
    for (int i = 0; i < 8; i++) { s[i] = 0.f; acc[i][0] = acc[i][1] = 0ULL; }

    const int nbase = p * (NSEQ / NSPLIT);
    for (int n0 = nbase; n0 < nbase + NSEQ / NSPLIT; n0 += 32) {
        __syncthreads();
        #pragma unroll
        for (int i = threadIdx.x; i < 32 * MDIM / 4; i += 256) {
            const int nn = i >> 5, m4 = (i & 31) * 4;
            *reinterpret_cast<float4*>(&kfs[nn][m4]) =
                *reinterpret_cast<const float4*>(&g_kf[((size_t)bh * NSEQ + n0 + nn) * MDIM + m4]);
        }
        #pragma unroll
        for (int i = threadIdx.x; i < 32 * DDIM / 4; i += 256) {
            const int nn = i >> 4, d4 = (i & 15) * 4;
            *reinterpret_cast<float4*>(&vs[nn][d4]) =
                *reinterpret_cast<const float4*>(
                    &g_qkv[(size_t)(b * NSEQ + n0 + nn) * (3 * CDIM) + 2 * CDIM + h * DDIM + d4]);
        }
        __syncthreads();
        #pragma unroll 4
        for (int nn = 0; nn < 32; nn++) {
            float a[8];
            #pragma unroll
            for (int i = 0; i < 8; i++) a[i] = kfs[nn][tm * 8 + i];
            longlong2 bp = *reinterpret_cast<const longlong2*>(&vs[nn][td * 4]);
            #pragma unroll
            for (int i = 0; i < 8; i++) {
                const ull ad = pack_dup(a[i]);
                ffma2(acc[i][0], ad, (ull)bp.x);
                ffma2(acc[i][1], ad, (ull)bp.y);
                s[i] += a[i];
            }
        }
    }

    float* kvb = g_kvp + ((size_t)p * (BATCH * HDIM) + bh) * KVSZ;
    #pragma unroll
    for (int i = 0; i < 8; i++) {
        const int m = tm * 8 + i;
        float2 p0 = unpack2(acc[i][0]), p1 = unpack2(acc[i][1]);
        *reinterpret_cast<float4*>(&kvb[m * DDIM + td * 4]) =
            make_float4(p0.x, p0.y, p1.x, p1.y);
        if (td == 0) kvb[MDIM * DDIM + m] = s[i];
    }
}

__global__ __launch_bounds__(256) void kv_reduce()
{
    const int i = blockIdx.x * 256 + threadIdx.x;
    if (i < BATCH * HDIM * KVSZ) {
        float s = 0.f;
        #pragma unroll
        for (int pp = 0; pp < NSPLIT; pp++)
            s += g_kvp[(size_t)pp * (BATCH * HDIM * KVSZ) + i];
        g_kv[i] = s;
    }
}

// ---------------------------------------------------------------------------
// out kernel: writes fp16 o directly (feeds proj GEMM)
// ---------------------------------------------------------------------------
#define QF_PITCH 132
#define OUT_SMEM_FLOATS (KVSZ + 64 * QF_PITCH)

__global__ __launch_bounds__(256) void out_kernel()
{
    float* osm = dyn_smem;   // [0,8192): KV  [8192,8320): S  [8320,..): qf
    const int bh = blockIdx.x;
    const int b  = bh / HDIM, h = bh % HDIM;
    const int n0 = blockIdx.y * 64;
    const int tr = threadIdx.x >> 4;
    const int tc = threadIdx.x & 15;

    const float* kvb = g_kv + (size_t)bh * KVSZ;
    #pragma unroll
    for (int i = threadIdx.x; i < KVSZ / 4; i += 256)
        *reinterpret_cast<float4*>(&osm[i * 4]) =
            *reinterpret_cast<const float4*>(&kvb[i * 4]);
    #pragma unroll
    for (int i = threadIdx.x; i < 64 * 32; i += 256) {
        const int r = i >> 5, d4 = (i & 31) * 4;
        *reinterpret_cast<float4*>(&osm[KVSZ + r * QF_PITCH + d4]) =
            *reinterpret_cast<const float4*>(&g_qf[((size_t)bh * NSEQ + n0 + r) * MDIM + d4]);
    }
    __syncthreads();

    ull acc[4][2];
    float den[4];
    #pragma unroll
    for (int i = 0; i < 4; i++) { den[i] = 0.f; acc[i][0] = acc[i][1] = 0ULL; }

    #pragma unroll 4
    for (int m = 0; m < MDIM; m++) {
        longlong2 kvp = *reinterpret_cast<const longlong2*>(&osm[m * DDIM + tc * 4]);
        const float sv = osm[MDIM * DDIM + m];
        #pragma unroll
        for (int i = 0; i < 4; i++) {
            const float q = osm[KVSZ + (tr * 4 + i) * QF_PITCH + m];
            const ull qd = pack_dup(q);
            ffma2(acc[i][0], qd, (ull)kvp.x);
            ffma2(acc[i][1], qd, (ull)kvp.y);
            den[i] += q * sv;
        }
    }

    #pragma unroll
    for (int i = 0; i < 4; i++) {
        const float inv = 1.0f / fmaxf(den[i], 1e-12f);
        const int n = n0 + tr * 4 + i;
        float2 p0 = unpack2(acc[i][0]), p1 = unpack2(acc[i][1]);
        __half2 o0 = __floats2half2_rn(p0.x * inv, p0.y * inv);
        __half2 o1 = __floats2half2_rn(p1.x * inv, p1.y * inv);
        const size_t o = (size_t)(b * NSEQ + n) * CDIM + h * DDIM + tc * 4;
        uint32_t* op = reinterpret_cast<uint32_t*>(&g_oh[o]);
        op[0] = *reinterpret_cast<uint32_t*>(&o0);
        op[1] = *reinterpret_cast<uint32_t*>(&o1);
    }
}

// ---------------------------------------------------------------------------
extern "C" void kernel_launch(void* const* d_in, const int* in_sizes, int n_in,
                              void* d_out, int out_size)
{
    const float* x      = (const float*)d_in[0];
    const float* qkv_w  = (const float*)d_in[1];
    const float* proj_w = (const float*)d_in[2];
    const float* proj_b = (const float*)d_in[3];
    const float* randm  = (const float*)d_in[4];
    float* out = (float*)d_out;

    float *p_qkv;
    cudaGetSymbolAddress((void**)&p_qkv, g_qkv);
    __half *p_xh, *p_qwh, *p_qwl, *p_pwh, *p_pwl, *p_oh;
    cudaGetSymbolAddress((void**)&p_xh,  g_xh);
    cudaGetSymbolAddress((void**)&p_qwh, g_qwh);
    cudaGetSymbolAddress((void**)&p_qwl, g_qwl);
    cudaGetSymbolAddress((void**)&p_pwh, g_pwh);
    cudaGetSymbolAddress((void**)&p_pwl, g_pwl);
    cudaGetSymbolAddress((void**)&p_oh,  g_oh);

    cudaFuncSetAttribute(out_kernel, cudaFuncAttributeMaxDynamicSharedMemorySize,
                         OUT_SMEM_FLOATS * 4);
    cudaFuncSetAttribute(mma_gemm<false>, cudaFuncAttributeMaxDynamicSharedMemorySize,
                         GEMM_DYN_SMEM);
    cudaFuncSetAttribute(mma_gemm<true>, cudaFuncAttributeMaxDynamicSharedMemorySize,
                         GEMM_DYN_SMEM);

    // 0) conversions: x -> fp16; weights -> fp16 hi/lo
    {
        const int n4x = BNTOK * CDIM / 4;
        tohalf_kernel<<<(n4x + 255) / 256, 256>>>(
            (const float4*)x, (uint32_t*)p_xh, n4x);
        const int n4q = 3 * CDIM * CDIM / 4;
        splith_kernel<<<(n4q + 255) / 256, 256>>>(
            (const float4*)qkv_w, (uint32_t*)p_qwh, (uint32_t*)p_qwl, n4q);
        const int n4p = CDIM * CDIM / 4;
        splith_kernel<<<(n4p + 255) / 256, 256>>>(
            (const float4*)proj_w, (uint32_t*)p_pwh, (uint32_t*)p_pwl, n4p);
    }
    // 1) qkv = x @ qkv_w^T : [8192, 2304] via fp16x2 mma.sync
    {
        dim3 grid(3 * CDIM / 128, BNTOK / 128);
        mma_gemm<false><<<grid, 256, GEMM_DYN_SMEM>>>(
            p_xh, p_qwh, p_qwl, nullptr, p_qkv, 3 * CDIM, CDIM);
    }
    // 2) feature maps qf, kf
    {
        dim3 grid(BATCH * HDIM, NSEQ / 16);
        feat_kernel<<<grid, 256>>>(randm);
    }
    // 3) KV + S partial reduction, then merge
    {
        dim3 grid(BATCH * HDIM, NSPLIT);
        kv_kernel<<<grid, 256>>>();
        kv_reduce<<<(BATCH * HDIM * KVSZ + 255) / 256, 256>>>();
    }
    // 4) normalized output -> fp16 [b, n, c]
    {
        dim3 grid(BATCH * HDIM, NSEQ / 64);
        out_kernel<<<grid, 256, OUT_SMEM_FLOATS * 4>>>();
    }
    // 5) final projection + bias -> d_out via fp16x2 mma.sync
    {
        dim3 grid(CDIM / 128, BNTOK / 128);
        mma_gemm<true><<<grid, 256, GEMM_DYN_SMEM>>>(
            p_oh, p_pwh, p_pwl, proj_b, out, CDIM, CDIM);
    }
}

// round 15
// speedup vs baseline: 3.5065x; 1.0336x over previous
#include <cuda_runtime.h>
#include <cuda_bf16.h>
#include <cuda_fp16.h>
#include <math.h>
#include <stdint.h>

#define BATCH 8
#define NSEQ  1024
#define CDIM  768
#define HDIM  12
#define DDIM  64
#define MDIM  128
#define BNTOK (BATCH*NSEQ)          // 8192
#define KVSZ  (MDIM*DDIM + MDIM)    // 8320 floats per (b,h): KV + S
#define NSPLIT 8
#define BH    (BATCH*HDIM)          // 96

typedef unsigned long long ull;

// ---- packed fp32x2 helpers (kv/out kernels) -------------------------------
__device__ __forceinline__ ull pack_dup(float x) {
    ull r; asm("mov.b64 %0, {%1, %1};" : "=l"(r) : "f"(x)); return r;
}
__device__ __forceinline__ void ffma2(ull& acc, ull a, ull b) {
    asm("fma.rn.f32x2 %0, %1, %2, %0;" : "+l"(acc) : "l"(a), "l"(b));
}
__device__ __forceinline__ float2 unpack2(ull v) {
    float2 r; asm("mov.b64 {%0, %1}, %2;" : "=f"(r.x), "=f"(r.y) : "l"(v)); return r;
}

// ---- baseline-PTX tensor-core helpers (sm_80+, valid on compute_103) ------
__device__ __forceinline__ uint32_t smem_to_u32(const void* p) {
    uint32_t a;
    asm("{ .reg .u64 t; cvta.to.shared.u64 t, %1; cvt.u32.u64 %0, t; }" : "=r"(a) : "l"(p));
    return a;
}
__device__ __forceinline__ void cp16(uint32_t dst, const void* src) {
    asm volatile("cp.async.cg.shared.global [%0], [%1], 16;" :: "r"(dst), "l"(src));
}
#define CP_COMMIT() asm volatile("cp.async.commit_group;" ::: "memory")
#define CP_WAIT(n)  asm volatile("cp.async.wait_group %0;" :: "n"(n) : "memory")

__device__ __forceinline__ void ldsm4(uint32_t& r0, uint32_t& r1, uint32_t& r2,
                                      uint32_t& r3, uint32_t a) {
    asm volatile("ldmatrix.sync.aligned.m8n8.x4.shared.b16 {%0,%1,%2,%3}, [%4];"
                 : "=r"(r0), "=r"(r1), "=r"(r2), "=r"(r3) : "r"(a));
}
// fp16 MMA, fp32 accumulate
__device__ __forceinline__ void mma16816(float* c, const uint32_t* a, const uint32_t* b) {
    asm volatile("mma.sync.aligned.m16n8k16.row.col.f32.f16.f16.f32 "
        "{%0,%1,%2,%3}, {%4,%5,%6,%7}, {%8,%9}, {%0,%1,%2,%3};"
        : "+f"(c[0]), "+f"(c[1]), "+f"(c[2]), "+f"(c[3])
        : "r"(a[0]), "r"(a[1]), "r"(a[2]), "r"(a[3]), "r"(b[0]), "r"(b[1]));
}

// ---- fp16 split helpers ----------------------------------------------------
__device__ __forceinline__ void split1h(float v, __half& h, __half& l) {
    h = __float2half_rn(v);
    l = __float2half_rn(v - __half2float(h));
}

// ---------------- scratch (device globals; no allocation allowed) ----------
__device__ float g_qkv[BNTOK * 3 * CDIM];                     // 75.5 MB
__device__ float g_qf [BH * NSEQ * MDIM];                     // 50.3 MB
__device__ float g_kf [BH * NSEQ * MDIM];                     // 50.3 MB
__device__ float g_kvp[NSPLIT * BH * KVSZ];                   // 25.5 MB
__device__ float g_kv [BH * KVSZ];                            // 3.2 MB
__device__ __half g_xh [BNTOK * CDIM];                        // A fp16
__device__ __half g_qwh[3 * CDIM * CDIM];                     // weights hi
__device__ __half g_qwl[3 * CDIM * CDIM];                     // weights lo
__device__ __half g_pwh[CDIM * CDIM];
__device__ __half g_pwl[CDIM * CDIM];
__device__ __half g_oh [BNTOK * CDIM];                        // o fp16
// feat-mma scratch
__device__ __half g_zqh[BH * NSEQ * DDIM];                    // 12.6 MB each
__device__ __half g_zql[BH * NSEQ * DDIM];
__device__ __half g_zkh[BH * NSEQ * DDIM];
__device__ __half g_zkl[BH * NSEQ * DDIM];
__device__ float  g_sqq[BH * NSEQ];
__device__ float  g_sqk[BH * NSEQ];
__device__ __half g_rth[HDIM * MDIM * DDIM];                  // R^T hi [h][m][d]
__device__ __half g_rtl[HDIM * MDIM * DDIM];                  // R^T lo

extern __shared__ float dyn_smem[];

// ---------------------------------------------------------------------------
// fp32 -> fp16 (single), vectorized by 4
// ---------------------------------------------------------------------------
__global__ __launch_bounds__(256) void tohalf_kernel(
    const float4* __restrict__ src, uint32_t* __restrict__ dst, int n4)
{
    const int i = blockIdx.x * 256 + threadIdx.x;
    if (i >= n4) return;
    const float4 v = src[i];
    __half2 p0 = __floats2half2_rn(v.x, v.y);
    __half2 p1 = __floats2half2_rn(v.z, v.w);
    dst[2*i]   = *reinterpret_cast<uint32_t*>(&p0);
    dst[2*i+1] = *reinterpret_cast<uint32_t*>(&p1);
}

// ---------------------------------------------------------------------------
// fp32 -> fp16 hi + fp16 residual, vectorized by 4 (weights)
// ---------------------------------------------------------------------------
__global__ __launch_bounds__(256) void splith_kernel(
    const float4* __restrict__ src, uint32_t* __restrict__ hi,
    uint32_t* __restrict__ lo, int n4)
{
    const int i = blockIdx.x * 256 + threadIdx.x;
    if (i >= n4) return;
    const float4 v = src[i];
    __half h0,h1,h2,h3, l0,l1,l2,l3;
    split1h(v.x, h0, l0); split1h(v.y, h1, l1);
    split1h(v.z, h2, l2); split1h(v.w, h3, l3);
    __half2 ph0 = __halves2half2(h0, h1), ph1 = __halves2half2(h2, h3);
    __half2 pl0 = __halves2half2(l0, l1), pl1 = __halves2half2(l2, l3);
    hi[2*i]   = *reinterpret_cast<uint32_t*>(&ph0);
    hi[2*i+1] = *reinterpret_cast<uint32_t*>(&ph1);
    lo[2*i]   = *reinterpret_cast<uint32_t*>(&pl0);
    lo[2*i+1] = *reinterpret_cast<uint32_t*>(&pl1);
}

// ---------------------------------------------------------------------------
// R[h][d][m] fp32 -> Rt[h][m][d] fp16 hi/lo
// ---------------------------------------------------------------------------
__global__ __launch_bounds__(256) void rt_split_kernel(const float* __restrict__ R)
{
    const int h = blockIdx.x;
    for (int i = threadIdx.x; i < DDIM * MDIM; i += 256) {
        const int d = i >> 7, m = i & 127;
        const float v = R[h * DDIM * MDIM + d * MDIM + m];
        __half hh, hl;
        split1h(v, hh, hl);
        g_rth[h * MDIM * DDIM + m * DDIM + d] = hh;
        g_rtl[h * MDIM * DDIM + m * DDIM + d] = hl;
    }
}

// ---------------------------------------------------------------------------
// q,k -> z = v*sq: fp16 hi/lo in [bh][n][d] layout + 0.5*||z||^2 per row.
// One warp per (bh, n); lane covers 2 d.
// ---------------------------------------------------------------------------
__global__ __launch_bounds__(256) void qk_split_kernel()
{
    const int row  = blockIdx.x * 8 + (threadIdx.x >> 5);   // bh*1024+n
    const int lane = threadIdx.x & 31;
    const int bh = row >> 10, n = row & 1023;
    const int b = bh / HDIM, h = bh % HDIM;
    const float sq = 0.3535533905932738f;   // 64^-0.25

    const size_t base = (size_t)(b * NSEQ + n) * (3 * CDIM) + h * DDIM + lane * 2;
    float2 q2 = *reinterpret_cast<const float2*>(&g_qkv[base]);
    float2 k2 = *reinterpret_cast<const float2*>(&g_qkv[base + CDIM]);
    q2.x *= sq; q2.y *= sq; k2.x *= sq; k2.y *= sq;

    float sumq = q2.x * q2.x + q2.y * q2.y;
    float sumk = k2.x * k2.x + k2.y * k2.y;
    #pragma unroll
    for (int s = 16; s > 0; s >>= 1) {
        sumq += __shfl_xor_sync(0xFFFFFFFFu, sumq, s);
        sumk += __shfl_xor_sync(0xFFFFFFFFu, sumk, s);
    }
    if (lane == 0) {
        g_sqq[row] = 0.5f * sumq;
        g_sqk[row] = 0.5f * sumk;
    }

    __half qh0,ql0,qh1,ql1, kh0,kl0,kh1,kl1;
    split1h(q2.x, qh0, ql0); split1h(q2.y, qh1, ql1);
    split1h(k2.x, kh0, kl0); split1h(k2.y, kh1, kl1);
    const size_t o = (size_t)row * DDIM + lane * 2;
    *reinterpret_cast<__half2*>(&g_zqh[o]) = __halves2half2(qh0, qh1);
    *reinterpret_cast<__half2*>(&g_zql[o]) = __halves2half2(ql0, ql1);
    *reinterpret_cast<__half2*>(&g_zkh[o]) = __halves2half2(kh0, kh1);
    *reinterpret_cast<__half2*>(&g_zkl[o]) = __halves2half2(kl0, kl1);
}

// ---------------------------------------------------------------------------
// GEMM smem tiling constants (shared by mma_gemm and feat_mma)
// ---------------------------------------------------------------------------
#define PITCHB   80                          // bytes per 32-fp16 row in smem
#define TILE_B   (128 * PITCHB)              // 10240 B per operand tile
#define STAGE_B  (3 * TILE_B)                // A BH BL
#define OFF_A    0
#define OFF_BH   TILE_B
#define OFF_BL   (2 * TILE_B)
#define GEMM_DYN_SMEM (2 * STAGE_B)          // 61440 B

__device__ __forceinline__ void stage_tile(uint32_t sdst,
    const __half* __restrict__ g, int ld, int k0, int tid)
{
    // 128 rows x 32 fp16 = 512 x 16B chunks; 256 threads x 2
    #pragma unroll
    for (int i = 0; i < 2; i++) {
        const int c   = tid + i * 256;
        const int row = c >> 2, c16 = c & 3;
        cp16(sdst + row * PITCHB + c16 * 16,
             g + (size_t)row * ld + k0 + c16 * 8);
    }
}

// ---------------------------------------------------------------------------
// fp16x2 tensor-core GEMM via mma.sync: C[M,N] = A[M,K] @ Bw[N,K]^T (+bias).
// ---------------------------------------------------------------------------
template<bool ADD_BIAS>
__global__ __launch_bounds__(256) void mma_gemm(
    const __half* __restrict__ A16,
    const __half* __restrict__ Bh, const __half* __restrict__ Bl,
    const float* __restrict__ bias, float* __restrict__ C, int Nd, int Kd)
{
    const uint32_t sb = smem_to_u32(dyn_smem);
    const int tid  = threadIdx.x;
    const int wid  = tid >> 5, lane = tid & 31;
    const int wm   = wid & 1;
    const int wn   = wid >> 1;
    const int row0 = blockIdx.y * 128, col0 = blockIdx.x * 128;

    const int t8   = lane & 7;
    const int g01  = (lane >> 3) & 1;
    const int g2   = lane >> 4;
    const int mrow = g01 * 8 + t8;
    const int kofw = g2 * 8;

    const __half* gA  = A16 + (size_t)row0 * Kd;
    const __half* gBh = Bh  + (size_t)col0 * Kd;
    const __half* gBl = Bl  + (size_t)col0 * Kd;

    float acc[4][4][4];
    #pragma unroll
    for (int i = 0; i < 4; i++)
        #pragma unroll
        for (int j = 0; j < 4; j++)
            #pragma unroll
            for (int r = 0; r < 4; r++) acc[i][j][r] = 0.f;

    const int nchunk = Kd >> 5;

    stage_tile(sb + OFF_A,  gA,  Kd, 0, tid);
    stage_tile(sb + OFF_BH, gBh, Kd, 0, tid);
    stage_tile(sb + OFF_BL, gBl, Kd, 0, tid);
    CP_COMMIT();

    for (int c = 0; c < nchunk; c++) {
        CP_WAIT(0);
        __syncthreads();
        if (c + 1 < nchunk) {
            const uint32_t nb = sb + ((c + 1) & 1) * STAGE_B;
            const int k0 = (c + 1) << 5;
            stage_tile(nb + OFF_A,  gA,  Kd, k0, tid);
            stage_tile(nb + OFF_BH, gBh, Kd, k0, tid);
            stage_tile(nb + OFF_BL, gBl, Kd, k0, tid);
            CP_COMMIT();
        }

        const uint32_t st = sb + (c & 1) * STAGE_B;
        #pragma unroll
        for (int ks = 0; ks < 2; ks++) {
            const uint32_t kb = ks * 32 + kofw * 2;
            uint32_t ah[4][4];
            #pragma unroll
            for (int mf = 0; mf < 4; mf++) {
                const uint32_t ra = (wm * 64 + mf * 16 + mrow) * PITCHB + kb;
                ldsm4(ah[mf][0], ah[mf][1], ah[mf][2], ah[mf][3], st + OFF_A + ra);
            }
            uint32_t bh[4][2], bl[4][2];
            #pragma unroll
            for (int nf2 = 0; nf2 < 2; nf2++) {
                const uint32_t rb = (wn * 32 + nf2 * 16 + mrow) * PITCHB + kb;
                uint32_t r0, r1, r2, r3;
                ldsm4(r0, r1, r2, r3, st + OFF_BH + rb);
                bh[nf2*2][0] = r0; bh[nf2*2+1][0] = r1;
                bh[nf2*2][1] = r2; bh[nf2*2+1][1] = r3;
                ldsm4(r0, r1, r2, r3, st + OFF_BL + rb);
                bl[nf2*2][0] = r0; bl[nf2*2+1][0] = r1;
                bl[nf2*2][1] = r2; bl[nf2*2+1][1] = r3;
            }
            #pragma unroll
            for (int mf = 0; mf < 4; mf++)
                #pragma unroll
                for (int nf = 0; nf < 4; nf++)
                    mma16816(acc[mf][nf], ah[mf], bh[nf]);   // A*Bh
            #pragma unroll
            for (int mf = 0; mf < 4; mf++)
                #pragma unroll
                for (int nf = 0; nf < 4; nf++)
                    mma16816(acc[mf][nf], ah[mf], bl[nf]);   // A*Bl
        }
    }

    const int rg = lane >> 2;
    const int cp = (lane & 3) * 2;
    #pragma unroll
    for (int mf = 0; mf < 4; mf++) {
        #pragma unroll
        for (int nf = 0; nf < 4; nf++) {
            const int col = col0 + wn * 32 + nf * 8 + cp;
            float b0 = 0.f, b1 = 0.f;
            if (ADD_BIAS) { b0 = bias[col]; b1 = bias[col + 1]; }
            const int r0 = row0 + wm * 64 + mf * 16 + rg;
            *reinterpret_cast<float2*>(&C[(size_t)r0 * Nd + col]) =
                make_float2(acc[mf][nf][0] + b0, acc[mf][nf][1] + b1);
            *reinterpret_cast<float2*>(&C[(size_t)(r0 + 8) * Nd + col]) =
                make_float2(acc[mf][nf][2] + b0, acc[mf][nf][3] + b1);
        }
    }
}

// ---------------------------------------------------------------------------
// feat via mma.sync: logits[128n x 128m] = z[128 x 64] @ Rt[128m x 64]^T,
// z & Rt fp16 hi/lo (3 product passes), then phi = exp(logit - sqn)*minv.
// Grid: (BH, NSEQ/128, 2) — z=0: q, z=1: k.
// ---------------------------------------------------------------------------
#define FEAT_DYN_SMEM (8 * TILE_B + 512)     // 2 chunks x {zh,zl,rh,rl} + sqs

__global__ __launch_bounds__(256) void feat_mma()
{
    const uint32_t sb = smem_to_u32(dyn_smem);
    float* sqs = dyn_smem + (8 * TILE_B) / 4;
    const int tid  = threadIdx.x;
    const int wid  = tid >> 5, lane = tid & 31;
    const int wm   = wid & 1;
    const int wn   = wid >> 1;
    const int bh = blockIdx.x, h = bh % HDIM;
    const int n0 = blockIdx.y * 128;
    const int isk = blockIdx.z;

    const __half* zh = (isk ? g_zkh : g_zqh) + ((size_t)bh * NSEQ + n0) * DDIM;
    const __half* zl = (isk ? g_zkl : g_zql) + ((size_t)bh * NSEQ + n0) * DDIM;
    const __half* rh = g_rth + (size_t)h * MDIM * DDIM;
    const __half* rl = g_rtl + (size_t)h * MDIM * DDIM;
    const float* sqp = (isk ? g_sqk : g_sqq) + bh * NSEQ + n0;
    float* outp = (isk ? g_kf : g_qf) + ((size_t)bh * NSEQ + n0) * MDIM;

    const int t8   = lane & 7;
    const int g01  = (lane >> 3) & 1;
    const int g2   = lane >> 4;
    const int mrow = g01 * 8 + t8;
    const int kofw = g2 * 8;

    // load both k-chunks (K=64) up front: chunk c at sb + c*4*TILE_B
    #pragma unroll
    for (int c = 0; c < 2; c++) {
        const uint32_t st = sb + c * 4 * TILE_B;
        const int k0 = c * 32;
        stage_tile(st + 0 * TILE_B, zh, DDIM, k0, tid);
        stage_tile(st + 1 * TILE_B, zl, DDIM, k0, tid);
        stage_tile(st + 2 * TILE_B, rh, DDIM, k0, tid);
        stage_tile(st + 3 * TILE_B, rl, DDIM, k0, tid);
    }
    CP_COMMIT();
    for (int i = tid; i < 128; i += 256) sqs[i] = sqp[i];
    CP_WAIT(0);
    __syncthreads();

    float acc[4][4][4];
    #pragma unroll
    for (int i = 0; i < 4; i++)
        #pragma unroll
        for (int j = 0; j < 4; j++)
            #pragma unroll
            for (int r = 0; r < 4; r++) acc[i][j][r] = 0.f;

    #pragma unroll
    for (int c = 0; c < 2; c++) {
        const uint32_t st = sb + c * 4 * TILE_B;
        #pragma unroll
        for (int ks = 0; ks < 2; ks++) {
            const uint32_t kb = ks * 32 + kofw * 2;
            uint32_t ah[4][4], al[4][4];
            #pragma unroll
            for (int mf = 0; mf < 4; mf++) {
                const uint32_t ra = (wm * 64 + mf * 16 + mrow) * PITCHB + kb;
                ldsm4(ah[mf][0], ah[mf][1], ah[mf][2], ah[mf][3], st + 0 * TILE_B + ra);
                ldsm4(al[mf][0], al[mf][1], al[mf][2], al[mf][3], st + 1 * TILE_B + ra);
            }
            uint32_t bh2[4][2], bl2[4][2];
            #pragma unroll
            for (int nf2 = 0; nf2 < 2; nf2++) {
                const uint32_t rb = (wn * 32 + nf2 * 16 + mrow) * PITCHB + kb;
                uint32_t r0, r1, r2, r3;
                ldsm4(r0, r1, r2, r3, st + 2 * TILE_B + rb);
                bh2[nf2*2][0] = r0; bh2[nf2*2+1][0] = r1;
                bh2[nf2*2][1] = r2; bh2[nf2*2+1][1] = r3;
                ldsm4(r0, r1, r2, r3, st + 3 * TILE_B + rb);
                bl2[nf2*2][0] = r0; bl2[nf2*2+1][0] = r1;
                bl2[nf2*2][1] = r2; bl2[nf2*2+1][1] = r3;
            }
            #pragma unroll
            for (int mf = 0; mf < 4; mf++)
                #pragma unroll
                for (int nf = 0; nf < 4; nf++)
                    mma16816(acc[mf][nf], ah[mf], bh2[nf]);  // zh*Rh
            #pragma unroll
            for (int mf = 0; mf < 4; mf++)
                #pragma unroll
                for (int nf = 0; nf < 4; nf++)
                    mma16816(acc[mf][nf], ah[mf], bl2[nf]);  // zh*Rl
            #pragma unroll
            for (int mf = 0; mf < 4; mf++)
                #pragma unroll
                for (int nf = 0; nf < 4; nf++)
                    mma16816(acc[mf][nf], al[mf], bh2[nf]);  // zl*Rh
        }
    }

    const float minv = 0.08838834764831845f;   // 128^-0.5
    const int rg = lane >> 2;
    const int cp = (lane & 3) * 2;
    #pragma unroll
    for (int mf = 0; mf < 4; mf++) {
        const int r0 = wm * 64 + mf * 16 + rg;
        const float s0 = sqs[r0], s1 = sqs[r0 + 8];
        #pragma unroll
        for (int nf = 0; nf < 4; nf++) {
            const int col = wn * 32 + nf * 8 + cp;
            *reinterpret_cast<float2*>(&outp[(size_t)r0 * MDIM + col]) =
                make_float2(expf(acc[mf][nf][0] - s0) * minv,
                            expf(acc[mf][nf][1] - s0) * minv);
            *reinterpret_cast<float2*>(&outp[(size_t)(r0 + 8) * MDIM + col]) =
                make_float2(expf(acc[mf][nf][2] - s1) * minv,
                            expf(acc[mf][nf][3] - s1) * minv);
        }
    }
}

// ---------------------------------------------------------------------------
// Partial KV + S (unchanged)
// ---------------------------------------------------------------------------
__global__ __launch_bounds__(256) void kv_kernel()
{
    const int bh = blockIdx.x;
    const int b  = bh / HDIM, h = bh % HDIM;
    const int p  = blockIdx.y;
    const int tm = threadIdx.x >> 4;
    const int td = threadIdx.x & 15;

    __shared__ float kfs[32][MDIM];
    __shared__ float vs [32][DDIM];

    ull acc[8][2];
    float s[8];
    #pragma unroll
    for (int i = 0; i < 8; i++) { s[i] = 0.f; acc[i][0] = acc[i][1] = 0ULL; }

    const int nbase = p * (NSEQ / NSPLIT);
    for (int n0 = nbase; n0 < nbase + NSEQ / NSPLIT; n0 += 32) {
        __syncthreads();
        #pragma unroll
        for (int i = threadIdx.x; i < 32 * MDIM / 4; i += 256) {
            const int nn = i >> 5, m4 = (i & 31) * 4;
            *reinterpret_cast<float4*>(&kfs[nn][m4]) =
                *reinterpret_cast<const float4*>(&g_kf[((size_t)bh * NSEQ + n0 + nn) * MDIM + m4]);
        }
        #pragma unroll
        for (int i = threadIdx.x; i < 32 * DDIM / 4; i += 256) {
            const int nn = i >> 4, d4 = (i & 15) * 4;
            *reinterpret_cast<float4*>(&vs[nn][d4]) =
                *reinterpret_cast<const float4*>(
                    &g_qkv[(size_t)(b * NSEQ + n0 + nn) * (3 * CDIM) + 2 * CDIM + h * DDIM + d4]);
        }
        __syncthreads();
        #pragma unroll 4
        for (int nn = 0; nn < 32; nn++) {
            float a[8];
            #pragma unroll
            for (int i = 0; i < 8; i++) a[i] = kfs[nn][tm * 8 + i];
            longlong2 bp = *reinterpret_cast<const longlong2*>(&vs[nn][td * 4]);
            #pragma unroll
            for (int i = 0; i < 8; i++) {
                const ull ad = pack_dup(a[i]);
                ffma2(acc[i][0], ad, (ull)bp.x);
                ffma2(acc[i][1], ad, (ull)bp.y);
                s[i] += a[i];
            }
        }
    }

    float* kvb = g_kvp + ((size_t)p * BH + bh) * KVSZ;
    #pragma unroll
    for (int i = 0; i < 8; i++) {
        const int m = tm * 8 + i;
        float2 p0 = unpack2(acc[i][0]), p1 = unpack2(acc[i][1]);
        *reinterpret_cast<float4*>(&kvb[m * DDIM + td * 4]) =
            make_float4(p0.x, p0.y, p1.x, p1.y);
        if (td == 0) kvb[MDIM * DDIM + m] = s[i];
    }
}

__global__ __launch_bounds__(256) void kv_reduce()
{
    const int i = blockIdx.x * 256 + threadIdx.x;
    if (i < BH * KVSZ) {
        float s = 0.f;
        #pragma unroll
        for (int pp = 0; pp < NSPLIT; pp++)
            s += g_kvp[(size_t)pp * (BH * KVSZ) + i];
        g_kv[i] = s;
    }
}

// ---------------------------------------------------------------------------
// out kernel: writes fp16 o directly (feeds proj GEMM)
// ---------------------------------------------------------------------------
#define QF_PITCH 132
#define OUT_SMEM_FLOATS (KVSZ + 64 * QF_PITCH)

__global__ __launch_bounds__(256) void out_kernel()
{
    float* osm = dyn_smem;   // [0,8192): KV  [8192,8320): S  [8320,..): qf
    const int bh = blockIdx.x;
    const int b  = bh / HDIM, h = bh % HDIM;
    const int n0 = blockIdx.y * 64;
    const int tr = threadIdx.x >> 4;
    const int tc = threadIdx.x & 15;

    const float* kvb = g_kv + (size_t)bh * KVSZ;
    #pragma unroll
    for (int i = threadIdx.x; i < KVSZ / 4; i += 256)
        *reinterpret_cast<float4*>(&osm[i * 4]) =
            *reinterpret_cast<const float4*>(&kvb[i * 4]);
    #pragma unroll
    for (int i = threadIdx.x; i < 64 * 32; i += 256) {
        const int r = i >> 5, d4 = (i & 31) * 4;
        *reinterpret_cast<float4*>(&osm[KVSZ + r * QF_PITCH + d4]) =
            *reinterpret_cast<const float4*>(&g_qf[((size_t)bh * NSEQ + n0 + r) * MDIM + d4]);
    }
    __syncthreads();

    ull acc[4][2];
    float den[4];
    #pragma unroll
    for (int i = 0; i < 4; i++) { den[i] = 0.f; acc[i][0] = acc[i][1] = 0ULL; }

    #pragma unroll 4
    for (int m = 0; m < MDIM; m++) {
        longlong2 kvp = *reinterpret_cast<const longlong2*>(&osm[m * DDIM + tc * 4]);
        const float sv = osm[MDIM * DDIM + m];
        #pragma unroll
        for (int i = 0; i < 4; i++) {
            const float q = osm[KVSZ + (tr * 4 + i) * QF_PITCH + m];
            const ull qd = pack_dup(q);
            ffma2(acc[i][0], qd, (ull)kvp.x);
            ffma2(acc[i][1], qd, (ull)kvp.y);
            den[i] += q * sv;
        }
    }

    #pragma unroll
    for (int i = 0; i < 4; i++) {
        const float inv = 1.0f / fmaxf(den[i], 1e-12f);
        const int n = n0 + tr * 4 + i;
        float2 p0 = unpack2(acc[i][0]), p1 = unpack2(acc[i][1]);
        __half2 o0 = __floats2half2_rn(p0.x * inv, p0.y * inv);
        __half2 o1 = __floats2half2_rn(p1.x * inv, p1.y * inv);
        const size_t o = (size_t)(b * NSEQ + n) * CDIM + h * DDIM + tc * 4;
        uint32_t* op = reinterpret_cast<uint32_t*>(&g_oh[o]);
        op[0] = *reinterpret_cast<uint32_t*>(&o0);
        op[1] = *reinterpret_cast<uint32_t*>(&o1);
    }
}

// ---------------------------------------------------------------------------
extern "C" void kernel_launch(void* const* d_in, const int* in_sizes, int n_in,
                              void* d_out, int out_size)
{
    const float* x      = (const float*)d_in[0];
    const float* qkv_w  = (const float*)d_in[1];
    const float* proj_w = (const float*)d_in[2];
    const float* proj_b = (const float*)d_in[3];
    const float* randm  = (const float*)d_in[4];
    float* out = (float*)d_out;

    float *p_qkv;
    cudaGetSymbolAddress((void**)&p_qkv, g_qkv);
    __half *p_xh, *p_qwh, *p_qwl, *p_pwh, *p_pwl, *p_oh;
    cudaGetSymbolAddress((void**)&p_xh,  g_xh);
    cudaGetSymbolAddress((void**)&p_qwh, g_qwh);
    cudaGetSymbolAddress((void**)&p_qwl, g_qwl);
    cudaGetSymbolAddress((void**)&p_pwh, g_pwh);
    cudaGetSymbolAddress((void**)&p_pwl, g_pwl);
    cudaGetSymbolAddress((void**)&p_oh,  g_oh);

    cudaFuncSetAttribute(out_kernel, cudaFuncAttributeMaxDynamicSharedMemorySize,
                         OUT_SMEM_FLOATS * 4);
    cudaFuncSetAttribute(mma_gemm<false>, cudaFuncAttributeMaxDynamicSharedMemorySize,
                         GEMM_DYN_SMEM);
    cudaFuncSetAttribute(mma_gemm<true>, cudaFuncAttributeMaxDynamicSharedMemorySize,
                         GEMM_DYN_SMEM);
    cudaFuncSetAttribute(feat_mma, cudaFuncAttributeMaxDynamicSharedMemorySize,
                         FEAT_DYN_SMEM);

    // 0) conversions: x -> fp16; weights -> fp16 hi/lo; R -> Rt hi/lo
    {
        const int n4x = BNTOK * CDIM / 4;
        tohalf_kernel<<<(n4x + 255) / 256, 256>>>(
            (const float4*)x, (uint32_t*)p_xh, n4x);
        const int n4q = 3 * CDIM * CDIM / 4;
        splith_kernel<<<(n4q + 255) / 256, 256>>>(
            (const float4*)qkv_w, (uint32_t*)p_qwh, (uint32_t*)p_qwl, n4q);
        const int n4p = CDIM * CDIM / 4;
        splith_kernel<<<(n4p + 255) / 256, 256>>>(
            (const float4*)proj_w, (uint32_t*)p_pwh, (uint32_t*)p_pwl, n4p);
        rt_split_kernel<<<HDIM, 256>>>(randm);
    }
    // 1) qkv = x @ qkv_w^T : [8192, 2304] via fp16x2 mma.sync
    {
        dim3 grid(3 * CDIM / 128, BNTOK / 128);
        mma_gemm<false><<<grid, 256, GEMM_DYN_SMEM>>>(
            p_xh, p_qwh, p_qwl, nullptr, p_qkv, 3 * CDIM, CDIM);
    }
    // 2) feature maps: split q,k to fp16 hi/lo + sqnorm, then MMA + exp
    {
        qk_split_kernel<<<BH * NSEQ / 8, 256>>>();
        dim3 grid(BH, NSEQ / 128, 2);
        feat_mma<<<grid, 256, FEAT_DYN_SMEM>>>();
    }
    // 3) KV + S partial reduction, then merge
    {
        dim3 grid(BH, NSPLIT);
        kv_kernel<<<grid, 256>>>();
        kv_reduce<<<(BH * KVSZ + 255) / 256, 256>>>();
    }
    // 4) normalized output -> fp16 [b, n, c]
    {
        dim3 grid(BH, NSEQ / 64);
        out_kernel<<<grid, 256, OUT_SMEM_FLOATS * 4>>>();
    }
    // 5) final projection + bias -> d_out via fp16x2 mma.sync
    {
        dim3 grid(CDIM / 128, BNTOK / 128);
        mma_gemm<true><<<grid, 256, GEMM_DYN_SMEM>>>(
            p_oh, p_pwh, p_pwl, proj_b, out, CDIM, CDIM);
    }
}

// round 16
// speedup vs baseline: 3.5128x; 1.0018x over previous
#include <cuda_runtime.h>
#include <cuda_bf16.h>
#include <cuda_fp16.h>
#include <math.h>
#include <stdint.h>

#define BATCH 8
#define NSEQ  1024
#define CDIM  768
#define HDIM  12
#define DDIM  64
#define MDIM  128
#define BNTOK (BATCH*NSEQ)          // 8192
#define KVSZ  (MDIM*DDIM + MDIM)    // 8320 floats per (b,h): KV + S
#define NSPLIT 8
#define BH    (BATCH*HDIM)          // 96

typedef unsigned long long ull;

// ---- packed fp32x2 helpers (kv/out kernels) -------------------------------
__device__ __forceinline__ ull pack_dup(float x) {
    ull r; asm("mov.b64 %0, {%1, %1};" : "=l"(r) : "f"(x)); return r;
}
__device__ __forceinline__ void ffma2(ull& acc, ull a, ull b) {
    asm("fma.rn.f32x2 %0, %1, %2, %0;" : "+l"(acc) : "l"(a), "l"(b));
}
__device__ __forceinline__ float2 unpack2(ull v) {
    float2 r; asm("mov.b64 {%0, %1}, %2;" : "=f"(r.x), "=f"(r.y) : "l"(v)); return r;
}

// ---- baseline-PTX tensor-core helpers (sm_80+, valid on compute_103) ------
__device__ __forceinline__ uint32_t smem_to_u32(const void* p) {
    uint32_t a;
    asm("{ .reg .u64 t; cvta.to.shared.u64 t, %1; cvt.u32.u64 %0, t; }" : "=r"(a) : "l"(p));
    return a;
}
__device__ __forceinline__ void cp16(uint32_t dst, const void* src) {
    asm volatile("cp.async.cg.shared.global [%0], [%1], 16;" :: "r"(dst), "l"(src));
}
#define CP_COMMIT() asm volatile("cp.async.commit_group;" ::: "memory")
#define CP_WAIT(n)  asm volatile("cp.async.wait_group %0;" :: "n"(n) : "memory")

__device__ __forceinline__ void ldsm4(uint32_t& r0, uint32_t& r1, uint32_t& r2,
                                      uint32_t& r3, uint32_t a) {
    asm volatile("ldmatrix.sync.aligned.m8n8.x4.shared.b16 {%0,%1,%2,%3}, [%4];"
                 : "=r"(r0), "=r"(r1), "=r"(r2), "=r"(r3) : "r"(a));
}
// fp16 MMA, fp32 accumulate
__device__ __forceinline__ void mma16816(float* c, const uint32_t* a, const uint32_t* b) {
    asm volatile("mma.sync.aligned.m16n8k16.row.col.f32.f16.f16.f32 "
        "{%0,%1,%2,%3}, {%4,%5,%6,%7}, {%8,%9}, {%0,%1,%2,%3};"
        : "+f"(c[0]), "+f"(c[1]), "+f"(c[2]), "+f"(c[3])
        : "r"(a[0]), "r"(a[1]), "r"(a[2]), "r"(a[3]), "r"(b[0]), "r"(b[1]));
}

// ---- fp16 split helpers ----------------------------------------------------
__device__ __forceinline__ void split1h(float v, __half& h, __half& l) {
    h = __float2half_rn(v);
    l = __float2half_rn(v - __half2float(h));
}

// ---------------- scratch (device globals; no allocation allowed) ----------
__device__ float g_qkv[BNTOK * 3 * CDIM];                     // 75.5 MB
__device__ float g_qf [BH * NSEQ * MDIM];                     // 50.3 MB
__device__ float g_kf [BH * NSEQ * MDIM];                     // 50.3 MB
__device__ float g_kvp[NSPLIT * BH * KVSZ];                   // 25.5 MB
__device__ float g_kv [BH * KVSZ];                            // 3.2 MB
__device__ __half g_xh [BNTOK * CDIM];                        // A fp16
__device__ __half g_qwh[3 * CDIM * CDIM];                     // weights hi
__device__ __half g_qwl[3 * CDIM * CDIM];                     // weights lo
__device__ __half g_pwh[CDIM * CDIM];
__device__ __half g_pwl[CDIM * CDIM];
__device__ __half g_oh [BNTOK * CDIM];                        // o fp16
// feat-mma scratch
__device__ __half g_zqh[BH * NSEQ * DDIM];                    // 12.6 MB each
__device__ __half g_zql[BH * NSEQ * DDIM];
__device__ __half g_zkh[BH * NSEQ * DDIM];
__device__ __half g_zkl[BH * NSEQ * DDIM];
__device__ float  g_sqq[BH * NSEQ];
__device__ float  g_sqk[BH * NSEQ];
__device__ __half g_rth[HDIM * MDIM * DDIM];                  // R^T hi [h][m][d]
__device__ __half g_rtl[HDIM * MDIM * DDIM];                  // R^T lo

extern __shared__ float dyn_smem[];

// ---------------------------------------------------------------------------
// fp32 -> fp16 (single), vectorized by 4
// ---------------------------------------------------------------------------
__global__ __launch_bounds__(256) void tohalf_kernel(
    const float4* __restrict__ src, uint32_t* __restrict__ dst, int n4)
{
    const int i = blockIdx.x * 256 + threadIdx.x;
    if (i >= n4) return;
    const float4 v = src[i];
    __half2 p0 = __floats2half2_rn(v.x, v.y);
    __half2 p1 = __floats2half2_rn(v.z, v.w);
    dst[2*i]   = *reinterpret_cast<uint32_t*>(&p0);
    dst[2*i+1] = *reinterpret_cast<uint32_t*>(&p1);
}

// ---------------------------------------------------------------------------
// fp32 -> fp16 hi + fp16 residual, vectorized by 4 (weights)
// ---------------------------------------------------------------------------
__global__ __launch_bounds__(256) void splith_kernel(
    const float4* __restrict__ src, uint32_t* __restrict__ hi,
    uint32_t* __restrict__ lo, int n4)
{
    const int i = blockIdx.x * 256 + threadIdx.x;
    if (i >= n4) return;
    const float4 v = src[i];
    __half h0,h1,h2,h3, l0,l1,l2,l3;
    split1h(v.x, h0, l0); split1h(v.y, h1, l1);
    split1h(v.z, h2, l2); split1h(v.w, h3, l3);
    __half2 ph0 = __halves2half2(h0, h1), ph1 = __halves2half2(h2, h3);
    __half2 pl0 = __halves2half2(l0, l1), pl1 = __halves2half2(l2, l3);
    hi[2*i]   = *reinterpret_cast<uint32_t*>(&ph0);
    hi[2*i+1] = *reinterpret_cast<uint32_t*>(&ph1);
    lo[2*i]   = *reinterpret_cast<uint32_t*>(&pl0);
    lo[2*i+1] = *reinterpret_cast<uint32_t*>(&pl1);
}

// ---------------------------------------------------------------------------
// R[h][d][m] fp32 -> Rt[h][m][d] fp16 hi/lo
// ---------------------------------------------------------------------------
__global__ __launch_bounds__(256) void rt_split_kernel(const float* __restrict__ R)
{
    const int h = blockIdx.x;
    for (int i = threadIdx.x; i < DDIM * MDIM; i += 256) {
        const int d = i >> 7, m = i & 127;
        const float v = R[h * DDIM * MDIM + d * MDIM + m];
        __half hh, hl;
        split1h(v, hh, hl);
        g_rth[h * MDIM * DDIM + m * DDIM + d] = hh;
        g_rtl[h * MDIM * DDIM + m * DDIM + d] = hl;
    }
}

// ---------------------------------------------------------------------------
// q,k -> z = v*sq: fp16 hi/lo in [bh][n][d] layout + 0.5*||z||^2 per row.
// One warp per (bh, n); lane covers 2 d.
// ---------------------------------------------------------------------------
__global__ __launch_bounds__(256) void qk_split_kernel()
{
    const int row  = blockIdx.x * 8 + (threadIdx.x >> 5);   // bh*1024+n
    const int lane = threadIdx.x & 31;
    const int bh = row >> 10, n = row & 1023;
    const int b = bh / HDIM, h = bh % HDIM;
    const float sq = 0.3535533905932738f;   // 64^-0.25

    const size_t base = (size_t)(b * NSEQ + n) * (3 * CDIM) + h * DDIM + lane * 2;
    float2 q2 = *reinterpret_cast<const float2*>(&g_qkv[base]);
    float2 k2 = *reinterpret_cast<const float2*>(&g_qkv[base + CDIM]);
    q2.x *= sq; q2.y *= sq; k2.x *= sq; k2.y *= sq;

    float sumq = q2.x * q2.x + q2.y * q2.y;
    float sumk = k2.x * k2.x + k2.y * k2.y;
    #pragma unroll
    for (int s = 16; s > 0; s >>= 1) {
        sumq += __shfl_xor_sync(0xFFFFFFFFu, sumq, s);
        sumk += __shfl_xor_sync(0xFFFFFFFFu, sumk, s);
    }
    if (lane == 0) {
        g_sqq[row] = 0.5f * sumq;
        g_sqk[row] = 0.5f * sumk;
    }

    __half qh0,ql0,qh1,ql1, kh0,kl0,kh1,kl1;
    split1h(q2.x, qh0, ql0); split1h(q2.y, qh1, ql1);
    split1h(k2.x, kh0, kl0); split1h(k2.y, kh1, kl1);
    const size_t o = (size_t)row * DDIM + lane * 2;
    *reinterpret_cast<__half2*>(&g_zqh[o]) = __halves2half2(qh0, qh1);
    *reinterpret_cast<__half2*>(&g_zql[o]) = __halves2half2(ql0, ql1);
    *reinterpret_cast<__half2*>(&g_zkh[o]) = __halves2half2(kh0, kh1);
    *reinterpret_cast<__half2*>(&g_zkl[o]) = __halves2half2(kl0, kl1);
}

// ---------------------------------------------------------------------------
// GEMM smem tiling constants (shared by mma_gemm and feat_mma)
// ---------------------------------------------------------------------------
#define PITCHB   80                          // bytes per 32-fp16 row in smem
#define TILE_B   (128 * PITCHB)              // 10240 B per operand tile
#define STAGE_B  (3 * TILE_B)                // A BH BL
#define OFF_A    0
#define OFF_BH   TILE_B
#define OFF_BL   (2 * TILE_B)
#define GEMM_DYN_SMEM (2 * STAGE_B)          // 61440 B

__device__ __forceinline__ void stage_tile(uint32_t sdst,
    const __half* __restrict__ g, int ld, int k0, int tid)
{
    // 128 rows x 32 fp16 = 512 x 16B chunks; 256 threads x 2
    #pragma unroll
    for (int i = 0; i < 2; i++) {
        const int c   = tid + i * 256;
        const int row = c >> 2, c16 = c & 3;
        cp16(sdst + row * PITCHB + c16 * 16,
             g + (size_t)row * ld + k0 + c16 * 8);
    }
}

// ---------------------------------------------------------------------------
// fp16x2 tensor-core GEMM via mma.sync: C[M,N] = A[M,K] @ Bw[N,K]^T (+bias).
// ---------------------------------------------------------------------------
template<bool ADD_BIAS>
__global__ __launch_bounds__(256) void mma_gemm(
    const __half* __restrict__ A16,
    const __half* __restrict__ Bh, const __half* __restrict__ Bl,
    const float* __restrict__ bias, float* __restrict__ C, int Nd, int Kd)
{
    const uint32_t sb = smem_to_u32(dyn_smem);
    const int tid  = threadIdx.x;
    const int wid  = tid >> 5, lane = tid & 31;
    const int wm   = wid & 1;
    const int wn   = wid >> 1;
    const int row0 = blockIdx.y * 128, col0 = blockIdx.x * 128;

    const int t8   = lane & 7;
    const int g01  = (lane >> 3) & 1;
    const int g2   = lane >> 4;
    const int mrow = g01 * 8 + t8;
    const int kofw = g2 * 8;

    const __half* gA  = A16 + (size_t)row0 * Kd;
    const __half* gBh = Bh  + (size_t)col0 * Kd;
    const __half* gBl = Bl  + (size_t)col0 * Kd;

    float acc[4][4][4];
    #pragma unroll
    for (int i = 0; i < 4; i++)
        #pragma unroll
        for (int j = 0; j < 4; j++)
            #pragma unroll
            for (int r = 0; r < 4; r++) acc[i][j][r] = 0.f;

    const int nchunk = Kd >> 5;

    stage_tile(sb + OFF_A,  gA,  Kd, 0, tid);
    stage_tile(sb + OFF_BH, gBh, Kd, 0, tid);
    stage_tile(sb + OFF_BL, gBl, Kd, 0, tid);
    CP_COMMIT();

    for (int c = 0; c < nchunk; c++) {
        CP_WAIT(0);
        __syncthreads();
        if (c + 1 < nchunk) {
            const uint32_t nb = sb + ((c + 1) & 1) * STAGE_B;
            const int k0 = (c + 1) << 5;
            stage_tile(nb + OFF_A,  gA,  Kd, k0, tid);
            stage_tile(nb + OFF_BH, gBh, Kd, k0, tid);
            stage_tile(nb + OFF_BL, gBl, Kd, k0, tid);
            CP_COMMIT();
        }

        const uint32_t st = sb + (c & 1) * STAGE_B;
        #pragma unroll
        for (int ks = 0; ks < 2; ks++) {
            const uint32_t kb = ks * 32 + kofw * 2;
            uint32_t ah[4][4];
            #pragma unroll
            for (int mf = 0; mf < 4; mf++) {
                const uint32_t ra = (wm * 64 + mf * 16 + mrow) * PITCHB + kb;
                ldsm4(ah[mf][0], ah[mf][1], ah[mf][2], ah[mf][3], st + OFF_A + ra);
            }
            uint32_t bh[4][2], bl[4][2];
            #pragma unroll
            for (int nf2 = 0; nf2 < 2; nf2++) {
                const uint32_t rb = (wn * 32 + nf2 * 16 + mrow) * PITCHB + kb;
                uint32_t r0, r1, r2, r3;
                ldsm4(r0, r1, r2, r3, st + OFF_BH + rb);
                bh[nf2*2][0] = r0; bh[nf2*2+1][0] = r1;
                bh[nf2*2][1] = r2; bh[nf2*2+1][1] = r3;
                ldsm4(r0, r1, r2, r3, st + OFF_BL + rb);
                bl[nf2*2][0] = r0; bl[nf2*2+1][0] = r1;
                bl[nf2*2][1] = r2; bl[nf2*2+1][1] = r3;
            }
            #pragma unroll
            for (int mf = 0; mf < 4; mf++)
                #pragma unroll
                for (int nf = 0; nf < 4; nf++)
                    mma16816(acc[mf][nf], ah[mf], bh[nf]);   // A*Bh
            #pragma unroll
            for (int mf = 0; mf < 4; mf++)
                #pragma unroll
                for (int nf = 0; nf < 4; nf++)
                    mma16816(acc[mf][nf], ah[mf], bl[nf]);   // A*Bl
        }
    }

    const int rg = lane >> 2;
    const int cp = (lane & 3) * 2;
    #pragma unroll
    for (int mf = 0; mf < 4; mf++) {
        #pragma unroll
        for (int nf = 0; nf < 4; nf++) {
            const int col = col0 + wn * 32 + nf * 8 + cp;
            float b0 = 0.f, b1 = 0.f;
            if (ADD_BIAS) { b0 = bias[col]; b1 = bias[col + 1]; }
            const int r0 = row0 + wm * 64 + mf * 16 + rg;
            *reinterpret_cast<float2*>(&C[(size_t)r0 * Nd + col]) =
                make_float2(acc[mf][nf][0] + b0, acc[mf][nf][1] + b1);
            *reinterpret_cast<float2*>(&C[(size_t)(r0 + 8) * Nd + col]) =
                make_float2(acc[mf][nf][2] + b0, acc[mf][nf][3] + b1);
        }
    }
}

// ---------------------------------------------------------------------------
// feat via mma.sync: logits[128n x 128m] = z[128 x 64] @ Rt[128m x 64]^T,
// z & Rt fp16 hi/lo (3 product passes), then phi = exp(logit - sqn)*minv.
// Grid: (BH, NSEQ/128, 2) — z=0: q, z=1: k.
// ---------------------------------------------------------------------------
#define FEAT_DYN_SMEM (8 * TILE_B + 512)     // 2 chunks x {zh,zl,rh,rl} + sqs

__global__ __launch_bounds__(256) void feat_mma()
{
    const uint32_t sb = smem_to_u32(dyn_smem);
    float* sqs = dyn_smem + (8 * TILE_B) / 4;
    const int tid  = threadIdx.x;
    const int wid  = tid >> 5, lane = tid & 31;
    const int wm   = wid & 1;
    const int wn   = wid >> 1;
    const int bh = blockIdx.x, h = bh % HDIM;
    const int n0 = blockIdx.y * 128;
    const int isk = blockIdx.z;

    const __half* zh = (isk ? g_zkh : g_zqh) + ((size_t)bh * NSEQ + n0) * DDIM;
    const __half* zl = (isk ? g_zkl : g_zql) + ((size_t)bh * NSEQ + n0) * DDIM;
    const __half* rh = g_rth + (size_t)h * MDIM * DDIM;
    const __half* rl = g_rtl + (size_t)h * MDIM * DDIM;
    const float* sqp = (isk ? g_sqk : g_sqq) + bh * NSEQ + n0;
    float* outp = (isk ? g_kf : g_qf) + ((size_t)bh * NSEQ + n0) * MDIM;

    const int t8   = lane & 7;
    const int g01  = (lane >> 3) & 1;
    const int g2   = lane >> 4;
    const int mrow = g01 * 8 + t8;
    const int kofw = g2 * 8;

    // load both k-chunks (K=64) up front: chunk c at sb + c*4*TILE_B
    #pragma unroll
    for (int c = 0; c < 2; c++) {
        const uint32_t st = sb + c * 4 * TILE_B;
        const int k0 = c * 32;
        stage_tile(st + 0 * TILE_B, zh, DDIM, k0, tid);
        stage_tile(st + 1 * TILE_B, zl, DDIM, k0, tid);
        stage_tile(st + 2 * TILE_B, rh, DDIM, k0, tid);
        stage_tile(st + 3 * TILE_B, rl, DDIM, k0, tid);
    }
    CP_COMMIT();
    for (int i = tid; i < 128; i += 256) sqs[i] = sqp[i];
    CP_WAIT(0);
    __syncthreads();

    float acc[4][4][4];
    #pragma unroll
    for (int i = 0; i < 4; i++)
        #pragma unroll
        for (int j = 0; j < 4; j++)
            #pragma unroll
            for (int r = 0; r < 4; r++) acc[i][j][r] = 0.f;

    #pragma unroll
    for (int c = 0; c < 2; c++) {
        const uint32_t st = sb + c * 4 * TILE_B;
        #pragma unroll
        for (int ks = 0; ks < 2; ks++) {
            const uint32_t kb = ks * 32 + kofw * 2;
            uint32_t ah[4][4], al[4][4];
            #pragma unroll
            for (int mf = 0; mf < 4; mf++) {
                const uint32_t ra = (wm * 64 + mf * 16 + mrow) * PITCHB + kb;
                ldsm4(ah[mf][0], ah[mf][1], ah[mf][2], ah[mf][3], st + 0 * TILE_B + ra);
                ldsm4(al[mf][0], al[mf][1], al[mf][2], al[mf][3], st + 1 * TILE_B + ra);
            }
            uint32_t bh2[4][2], bl2[4][2];
            #pragma unroll
            for (int nf2 = 0; nf2 < 2; nf2++) {
                const uint32_t rb = (wn * 32 + nf2 * 16 + mrow) * PITCHB + kb;
                uint32_t r0, r1, r2, r3;
                ldsm4(r0, r1, r2, r3, st + 2 * TILE_B + rb);
                bh2[nf2*2][0] = r0; bh2[nf2*2+1][0] = r1;
                bh2[nf2*2][1] = r2; bh2[nf2*2+1][1] = r3;
                ldsm4(r0, r1, r2, r3, st + 3 * TILE_B + rb);
                bl2[nf2*2][0] = r0; bl2[nf2*2+1][0] = r1;
                bl2[nf2*2][1] = r2; bl2[nf2*2+1][1] = r3;
            }
            #pragma unroll
            for (int mf = 0; mf < 4; mf++)
                #pragma unroll
                for (int nf = 0; nf < 4; nf++)
                    mma16816(acc[mf][nf], ah[mf], bh2[nf]);  // zh*Rh
            #pragma unroll
            for (int mf = 0; mf < 4; mf++)
                #pragma unroll
                for (int nf = 0; nf < 4; nf++)
                    mma16816(acc[mf][nf], ah[mf], bl2[nf]);  // zh*Rl
            #pragma unroll
            for (int mf = 0; mf < 4; mf++)
                #pragma unroll
                for (int nf = 0; nf < 4; nf++)
                    mma16816(acc[mf][nf], al[mf], bh2[nf]);  // zl*Rh
        }
    }

    const float minv = 0.08838834764831845f;   // 128^-0.5
    const int rg = lane >> 2;
    const int cp = (lane & 3) * 2;
    #pragma unroll
    for (int mf = 0; mf < 4; mf++) {
        const int r0 = wm * 64 + mf * 16 + rg;
        const float s0 = sqs[r0], s1 = sqs[r0 + 8];
        #pragma unroll
        for (int nf = 0; nf < 4; nf++) {
            const int col = wn * 32 + nf * 8 + cp;
            *reinterpret_cast<float2*>(&outp[(size_t)r0 * MDIM + col]) =
                make_float2(expf(acc[mf][nf][0] - s0) * minv,
                            expf(acc[mf][nf][1] - s0) * minv);
            *reinterpret_cast<float2*>(&outp[(size_t)(r0 + 8) * MDIM + col]) =
                make_float2(expf(acc[mf][nf][2] - s1) * minv,
                            expf(acc[mf][nf][3] - s1) * minv);
        }
    }
}

// ---------------------------------------------------------------------------
// Partial KV + S (unchanged)
// ---------------------------------------------------------------------------
__global__ __launch_bounds__(256) void kv_kernel()
{
    const int bh = blockIdx.x;
    const int b  = bh / HDIM, h = bh % HDIM;
    const int p  = blockIdx.y;
    const int tm = threadIdx.x >> 4;
    const int td = threadIdx.x & 15;

    __shared__ float kfs[32][MDIM];
    __shared__ float vs [32][DDIM];

    ull acc[8][2];
    float s[8];
    #pragma unroll
    for (int i = 0; i < 8; i++) { s[i] = 0.f; acc[i][0] = acc[i][1] = 0ULL; }

    const int nbase = p * (NSEQ / NSPLIT);
    for (int n0 = nbase; n0 < nbase + NSEQ / NSPLIT; n0 += 32) {
        __syncthreads();
        #pragma unroll
        for (int i = threadIdx.x; i < 32 * MDIM / 4; i += 256) {
            const int nn = i >> 5, m4 = (i & 31) * 4;
            *reinterpret_cast<float4*>(&kfs[nn][m4]) =
                *reinterpret_cast<const float4*>(&g_kf[((size_t)bh * NSEQ + n0 + nn) * MDIM + m4]);
        }
        #pragma unroll
        for (int i = threadIdx.x; i < 32 * DDIM / 4; i += 256) {
            const int nn = i >> 4, d4 = (i & 15) * 4;
            *reinterpret_cast<float4*>(&vs[nn][d4]) =
                *reinterpret_cast<const float4*>(
                    &g_qkv[(size_t)(b * NSEQ + n0 + nn) * (3 * CDIM) + 2 * CDIM + h * DDIM + d4]);
        }
        __syncthreads();
        #pragma unroll 4
        for (int nn = 0; nn < 32; nn++) {
            float a[8];
            #pragma unroll
            for (int i = 0; i < 8; i++) a[i] = kfs[nn][tm * 8 + i];
            longlong2 bp = *reinterpret_cast<const longlong2*>(&vs[nn][td * 4]);
            #pragma unroll
            for (int i = 0; i < 8; i++) {
                const ull ad = pack_dup(a[i]);
                ffma2(acc[i][0], ad, (ull)bp.x);
                ffma2(acc[i][1], ad, (ull)bp.y);
                s[i] += a[i];
            }
        }
    }

    float* kvb = g_kvp + ((size_t)p * BH + bh) * KVSZ;
    #pragma unroll
    for (int i = 0; i < 8; i++) {
        const int m = tm * 8 + i;
        float2 p0 = unpack2(acc[i][0]), p1 = unpack2(acc[i][1]);
        *reinterpret_cast<float4*>(&kvb[m * DDIM + td * 4]) =
            make_float4(p0.x, p0.y, p1.x, p1.y);
        if (td == 0) kvb[MDIM * DDIM + m] = s[i];
    }
}

__global__ __launch_bounds__(256) void kv_reduce()
{
    const int i = blockIdx.x * 256 + threadIdx.x;
    if (i < BH * KVSZ) {
        float s = 0.f;
        #pragma unroll
        for (int pp = 0; pp < NSPLIT; pp++)
            s += g_kvp[(size_t)pp * (BH * KVSZ) + i];
        g_kv[i] = s;
    }
}

// ---------------------------------------------------------------------------
// out kernel: writes fp16 o directly (feeds proj GEMM)
// ---------------------------------------------------------------------------
#define QF_PITCH 132
#define OUT_SMEM_FLOATS (KVSZ + 64 * QF_PITCH)

__global__ __launch_bounds__(256) void out_kernel()
{
    float* osm = dyn_smem;   // [0,8192): KV  [8192,8320): S  [8320,..): qf
    const int bh = blockIdx.x;
    const int b  = bh / HDIM, h = bh % HDIM;
    const int n0 = blockIdx.y * 64;
    const int tr = threadIdx.x >> 4;
    const int tc = threadIdx.x & 15;

    const float* kvb = g_kv + (size_t)bh * KVSZ;
    #pragma unroll
    for (int i = threadIdx.x; i < KVSZ / 4; i += 256)
        *reinterpret_cast<float4*>(&osm[i * 4]) =
            *reinterpret_cast<const float4*>(&kvb[i * 4]);
    #pragma unroll
    for (int i = threadIdx.x; i < 64 * 32; i += 256) {
        const int r = i >> 5, d4 = (i & 31) * 4;
        *reinterpret_cast<float4*>(&osm[KVSZ + r * QF_PITCH + d4]) =
            *reinterpret_cast<const float4*>(&g_qf[((size_t)bh * NSEQ + n0 + r) * MDIM + d4]);
    }
    __syncthreads();

    ull acc[4][2];
    float den[4];
    #pragma unroll
    for (int i = 0; i < 4; i++) { den[i] = 0.f; acc[i][0] = acc[i][1] = 0ULL; }

    #pragma unroll 4
    for (int m = 0; m < MDIM; m++) {
        longlong2 kvp = *reinterpret_cast<const longlong2*>(&osm[m * DDIM + tc * 4]);
        const float sv = osm[MDIM * DDIM + m];
        #pragma unroll
        for (int i = 0; i < 4; i++) {
            const float q = osm[KVSZ + (tr * 4 + i) * QF_PITCH + m];
            const ull qd = pack_dup(q);
            ffma2(acc[i][0], qd, (ull)kvp.x);
            ffma2(acc[i][1], qd, (ull)kvp.y);
            den[i] += q * sv;
        }
    }

    #pragma unroll
    for (int i = 0; i < 4; i++) {
        const float inv = 1.0f / fmaxf(den[i], 1e-12f);
        const int n = n0 + tr * 4 + i;
        float2 p0 = unpack2(acc[i][0]), p1 = unpack2(acc[i][1]);
        __half2 o0 = __floats2half2_rn(p0.x * inv, p0.y * inv);
        __half2 o1 = __floats2half2_rn(p1.x * inv, p1.y * inv);
        const size_t o = (size_t)(b * NSEQ + n) * CDIM + h * DDIM + tc * 4;
        uint32_t* op = reinterpret_cast<uint32_t*>(&g_oh[o]);
        op[0] = *reinterpret_cast<uint32_t*>(&o0);
        op[1] = *reinterpret_cast<uint32_t*>(&o1);
    }
}

// ---------------------------------------------------------------------------
extern "C" void kernel_launch(void* const* d_in, const int* in_sizes, int n_in,
                              void* d_out, int out_size)
{
    const float* x      = (const float*)d_in[0];
    const float* qkv_w  = (const float*)d_in[1];
    const float* proj_w = (const float*)d_in[2];
    const float* proj_b = (const float*)d_in[3];
    const float* randm  = (const float*)d_in[4];
    float* out = (float*)d_out;

    float *p_qkv;
    cudaGetSymbolAddress((void**)&p_qkv, g_qkv);
    __half *p_xh, *p_qwh, *p_qwl, *p_pwh, *p_pwl, *p_oh;
    cudaGetSymbolAddress((void**)&p_xh,  g_xh);
    cudaGetSymbolAddress((void**)&p_qwh, g_qwh);
    cudaGetSymbolAddress((void**)&p_qwl, g_qwl);
    cudaGetSymbolAddress((void**)&p_pwh, g_pwh);
    cudaGetSymbolAddress((void**)&p_pwl, g_pwl);
    cudaGetSymbolAddress((void**)&p_oh,  g_oh);

    cudaFuncSetAttribute(out_kernel, cudaFuncAttributeMaxDynamicSharedMemorySize,
                         OUT_SMEM_FLOATS * 4);
    cudaFuncSetAttribute(mma_gemm<false>, cudaFuncAttributeMaxDynamicSharedMemorySize,
                         GEMM_DYN_SMEM);
    cudaFuncSetAttribute(mma_gemm<true>, cudaFuncAttributeMaxDynamicSharedMemorySize,
                         GEMM_DYN_SMEM);
    cudaFuncSetAttribute(feat_mma, cudaFuncAttributeMaxDynamicSharedMemorySize,
                         FEAT_DYN_SMEM);

    // 0) conversions: x -> fp16; weights -> fp16 hi/lo; R -> Rt hi/lo
    {
        const int n4x = BNTOK * CDIM / 4;
        tohalf_kernel<<<(n4x + 255) / 256, 256>>>(
            (const float4*)x, (uint32_t*)p_xh, n4x);
        const int n4q = 3 * CDIM * CDIM / 4;
        splith_kernel<<<(n4q + 255) / 256, 256>>>(
            (const float4*)qkv_w, (uint32_t*)p_qwh, (uint32_t*)p_qwl, n4q);
        const int n4p = CDIM * CDIM / 4;
        splith_kernel<<<(n4p + 255) / 256, 256>>>(
            (const float4*)proj_w, (uint32_t*)p_pwh, (uint32_t*)p_pwl, n4p);
        rt_split_kernel<<<HDIM, 256>>>(randm);
    }
    // 1) qkv = x @ qkv_w^T : [8192, 2304] via fp16x2 mma.sync
    {
        dim3 grid(3 * CDIM / 128, BNTOK / 128);
        mma_gemm<false><<<grid, 256, GEMM_DYN_SMEM>>>(
            p_xh, p_qwh, p_qwl, nullptr, p_qkv, 3 * CDIM, CDIM);
    }
    // 2) feature maps: split q,k to fp16 hi/lo + sqnorm, then MMA + exp
    {
        qk_split_kernel<<<BH * NSEQ / 8, 256>>>();
        dim3 grid(BH, NSEQ / 128, 2);
        feat_mma<<<grid, 256, FEAT_DYN_SMEM>>>();
    }
    // 3) KV + S partial reduction, then merge
    {
        dim3 grid(BH, NSPLIT);
        kv_kernel<<<grid, 256>>>();
        kv_reduce<<<(BH * KVSZ + 255) / 256, 256>>>();
    }
    // 4) normalized output -> fp16 [b, n, c]
    {
        dim3 grid(BH, NSEQ / 64);
        out_kernel<<<grid, 256, OUT_SMEM_FLOATS * 4>>>();
    }
    // 5) final projection + bias -> d_out via fp16x2 mma.sync
    {
        dim3 grid(CDIM / 128, BNTOK / 128);
        mma_gemm<true><<<grid, 256, GEMM_DYN_SMEM>>>(
            p_oh, p_pwh, p_pwl, proj_b, out, CDIM, CDIM);
    }
}

// round 17
// speedup vs baseline: 3.7447x; 1.0660x over previous
#include <cuda_runtime.h>
#include <cuda_bf16.h>
#include <cuda_fp16.h>
#include <math.h>
#include <stdint.h>

#define BATCH 8
#define NSEQ  1024
#define CDIM  768
#define HDIM  12
#define DDIM  64
#define MDIM  128
#define BNTOK (BATCH*NSEQ)          // 8192
#define KVSZ  (MDIM*DDIM + MDIM)    // 8320 floats per (b,h): KV + S
#define NSPLIT 8
#define BH    (BATCH*HDIM)          // 96

typedef unsigned long long ull;

// ---- packed fp32x2 helpers (kv/out kernels) -------------------------------
__device__ __forceinline__ ull pack_dup(float x) {
    ull r; asm("mov.b64 %0, {%1, %1};" : "=l"(r) : "f"(x)); return r;
}
__device__ __forceinline__ void ffma2(ull& acc, ull a, ull b) {
    asm("fma.rn.f32x2 %0, %1, %2, %0;" : "+l"(acc) : "l"(a), "l"(b));
}
__device__ __forceinline__ float2 unpack2(ull v) {
    float2 r; asm("mov.b64 {%0, %1}, %2;" : "=f"(r.x), "=f"(r.y) : "l"(v)); return r;
}

// ---- baseline-PTX tensor-core helpers (sm_80+, valid on compute_103) ------
__device__ __forceinline__ uint32_t smem_to_u32(const void* p) {
    uint32_t a;
    asm("{ .reg .u64 t; cvta.to.shared.u64 t, %1; cvt.u32.u64 %0, t; }" : "=r"(a) : "l"(p));
    return a;
}
__device__ __forceinline__ void cp16(uint32_t dst, const void* src) {
    asm volatile("cp.async.cg.shared.global [%0], [%1], 16;" :: "r"(dst), "l"(src));
}
#define CP_COMMIT() asm volatile("cp.async.commit_group;" ::: "memory")
#define CP_WAIT(n)  asm volatile("cp.async.wait_group %0;" :: "n"(n) : "memory")

__device__ __forceinline__ void ldsm4(uint32_t& r0, uint32_t& r1, uint32_t& r2,
                                      uint32_t& r3, uint32_t a) {
    asm volatile("ldmatrix.sync.aligned.m8n8.x4.shared.b16 {%0,%1,%2,%3}, [%4];"
                 : "=r"(r0), "=r"(r1), "=r"(r2), "=r"(r3) : "r"(a));
}
// fp16 MMA, fp32 accumulate
__device__ __forceinline__ void mma16816(float* c, const uint32_t* a, const uint32_t* b) {
    asm volatile("mma.sync.aligned.m16n8k16.row.col.f32.f16.f16.f32 "
        "{%0,%1,%2,%3}, {%4,%5,%6,%7}, {%8,%9}, {%0,%1,%2,%3};"
        : "+f"(c[0]), "+f"(c[1]), "+f"(c[2]), "+f"(c[3])
        : "r"(a[0]), "r"(a[1]), "r"(a[2]), "r"(a[3]), "r"(b[0]), "r"(b[1]));
}

// ---- fp16 split helpers ----------------------------------------------------
__device__ __forceinline__ void split1h(float v, __half& h, __half& l) {
    h = __float2half_rn(v);
    l = __float2half_rn(v - __half2float(h));
}

// ---------------- scratch (device globals; no allocation allowed) ----------
__device__ float g_qkv[BNTOK * 3 * CDIM];                     // 75.5 MB
__device__ float g_qf [BH * NSEQ * MDIM];                     // 50.3 MB
__device__ float g_kf [BH * NSEQ * MDIM];                     // 50.3 MB
__device__ float g_kvp[NSPLIT * BH * KVSZ];                   // 25.5 MB
__device__ float g_kv [BH * KVSZ];                            // 3.2 MB
__device__ __half g_xh [BNTOK * CDIM];                        // A fp16
__device__ __half g_qwh[3 * CDIM * CDIM];                     // weights hi
__device__ __half g_qwl[3 * CDIM * CDIM];                     // weights lo
__device__ __half g_pwh[CDIM * CDIM];
__device__ __half g_pwl[CDIM * CDIM];
__device__ __half g_oh [BNTOK * CDIM];                        // o fp16
__device__ __half g_rth[HDIM * MDIM * DDIM];                  // R^T hi [h][m][d]
__device__ __half g_rtl[HDIM * MDIM * DDIM];                  // R^T lo

extern __shared__ float dyn_smem[];

// ---------------------------------------------------------------------------
// fp32 -> fp16 (single), vectorized by 4
// ---------------------------------------------------------------------------
__global__ __launch_bounds__(256) void tohalf_kernel(
    const float4* __restrict__ src, uint32_t* __restrict__ dst, int n4)
{
    const int i = blockIdx.x * 256 + threadIdx.x;
    if (i >= n4) return;
    const float4 v = src[i];
    __half2 p0 = __floats2half2_rn(v.x, v.y);
    __half2 p1 = __floats2half2_rn(v.z, v.w);
    dst[2*i]   = *reinterpret_cast<uint32_t*>(&p0);
    dst[2*i+1] = *reinterpret_cast<uint32_t*>(&p1);
}

// ---------------------------------------------------------------------------
// fp32 -> fp16 hi + fp16 residual, vectorized by 4 (weights)
// ---------------------------------------------------------------------------
__global__ __launch_bounds__(256) void splith_kernel(
    const float4* __restrict__ src, uint32_t* __restrict__ hi,
    uint32_t* __restrict__ lo, int n4)
{
    const int i = blockIdx.x * 256 + threadIdx.x;
    if (i >= n4) return;
    const float4 v = src[i];
    __half h0,h1,h2,h3, l0,l1,l2,l3;
    split1h(v.x, h0, l0); split1h(v.y, h1, l1);
    split1h(v.z, h2, l2); split1h(v.w, h3, l3);
    __half2 ph0 = __halves2half2(h0, h1), ph1 = __halves2half2(h2, h3);
    __half2 pl0 = __halves2half2(l0, l1), pl1 = __halves2half2(l2, l3);
    hi[2*i]   = *reinterpret_cast<uint32_t*>(&ph0);
    hi[2*i+1] = *reinterpret_cast<uint32_t*>(&ph1);
    lo[2*i]   = *reinterpret_cast<uint32_t*>(&pl0);
    lo[2*i+1] = *reinterpret_cast<uint32_t*>(&pl1);
}

// ---------------------------------------------------------------------------
// R[h][d][m] fp32 -> Rt[h][m][d] fp16 hi/lo.  Grid (HDIM, 8): 96 blocks,
// one float4 per thread (was 12 blocks / 22us -> latency bound).
// ---------------------------------------------------------------------------
__global__ __launch_bounds__(256) void rt_split_kernel(const float* __restrict__ R)
{
    const int h  = blockIdx.x;
    const int i4 = blockIdx.y * 256 + threadIdx.x;   // 2048 float4 per head
    const int flat = i4 * 4;                         // (d, m) flattened, m fastest
    const int d = flat >> 7, m0 = flat & 127;
    const float4 v = *reinterpret_cast<const float4*>(&R[h * DDIM * MDIM + flat]);
    const float vv[4] = { v.x, v.y, v.z, v.w };
    #pragma unroll
    for (int j = 0; j < 4; j++) {
        __half hh, hl;
        split1h(vv[j], hh, hl);
        g_rth[h * MDIM * DDIM + (m0 + j) * DDIM + d] = hh;
        g_rtl[h * MDIM * DDIM + (m0 + j) * DDIM + d] = hl;
    }
}

// ---------------------------------------------------------------------------
// GEMM smem tiling constants
// ---------------------------------------------------------------------------
#define PITCHB   80                          // bytes per 32-fp16 row in smem
#define TILE_B   (128 * PITCHB)              // 10240 B per operand tile
#define STAGE_B  (3 * TILE_B)                // A BH BL
#define OFF_A    0
#define OFF_BH   TILE_B
#define OFF_BL   (2 * TILE_B)
#define GEMM_DYN_SMEM (2 * STAGE_B)          // 61440 B

__device__ __forceinline__ void stage_tile(uint32_t sdst,
    const __half* __restrict__ g, int ld, int k0, int tid)
{
    #pragma unroll
    for (int i = 0; i < 2; i++) {
        const int c   = tid + i * 256;
        const int row = c >> 2, c16 = c & 3;
        cp16(sdst + row * PITCHB + c16 * 16,
             g + (size_t)row * ld + k0 + c16 * 8);
    }
}

// ---------------------------------------------------------------------------
// fp16x2 tensor-core GEMM via mma.sync: C[M,N] = A[M,K] @ Bw[N,K]^T (+bias).
// ---------------------------------------------------------------------------
template<bool ADD_BIAS>
__global__ __launch_bounds__(256) void mma_gemm(
    const __half* __restrict__ A16,
    const __half* __restrict__ Bh, const __half* __restrict__ Bl,
    const float* __restrict__ bias, float* __restrict__ C, int Nd, int Kd)
{
    const uint32_t sb = smem_to_u32(dyn_smem);
    const int tid  = threadIdx.x;
    const int wid  = tid >> 5, lane = tid & 31;
    const int wm   = wid & 1;
    const int wn   = wid >> 1;
    const int row0 = blockIdx.y * 128, col0 = blockIdx.x * 128;

    const int t8   = lane & 7;
    const int g01  = (lane >> 3) & 1;
    const int g2   = lane >> 4;
    const int mrow = g01 * 8 + t8;
    const int kofw = g2 * 8;

    const __half* gA  = A16 + (size_t)row0 * Kd;
    const __half* gBh = Bh  + (size_t)col0 * Kd;
    const __half* gBl = Bl  + (size_t)col0 * Kd;

    float acc[4][4][4];
    #pragma unroll
    for (int i = 0; i < 4; i++)
        #pragma unroll
        for (int j = 0; j < 4; j++)
            #pragma unroll
            for (int r = 0; r < 4; r++) acc[i][j][r] = 0.f;

    const int nchunk = Kd >> 5;

    stage_tile(sb + OFF_A,  gA,  Kd, 0, tid);
    stage_tile(sb + OFF_BH, gBh, Kd, 0, tid);
    stage_tile(sb + OFF_BL, gBl, Kd, 0, tid);
    CP_COMMIT();

    for (int c = 0; c < nchunk; c++) {
        CP_WAIT(0);
        __syncthreads();
        if (c + 1 < nchunk) {
            const uint32_t nb = sb + ((c + 1) & 1) * STAGE_B;
            const int k0 = (c + 1) << 5;
            stage_tile(nb + OFF_A,  gA,  Kd, k0, tid);
            stage_tile(nb + OFF_BH, gBh, Kd, k0, tid);
            stage_tile(nb + OFF_BL, gBl, Kd, k0, tid);
            CP_COMMIT();
        }

        const uint32_t st = sb + (c & 1) * STAGE_B;
        #pragma unroll
        for (int ks = 0; ks < 2; ks++) {
            const uint32_t kb = ks * 32 + kofw * 2;
            uint32_t ah[4][4];
            #pragma unroll
            for (int mf = 0; mf < 4; mf++) {
                const uint32_t ra = (wm * 64 + mf * 16 + mrow) * PITCHB + kb;
                ldsm4(ah[mf][0], ah[mf][1], ah[mf][2], ah[mf][3], st + OFF_A + ra);
            }
            uint32_t bh[4][2], bl[4][2];
            #pragma unroll
            for (int nf2 = 0; nf2 < 2; nf2++) {
                const uint32_t rb = (wn * 32 + nf2 * 16 + mrow) * PITCHB + kb;
                uint32_t r0, r1, r2, r3;
                ldsm4(r0, r1, r2, r3, st + OFF_BH + rb);
                bh[nf2*2][0] = r0; bh[nf2*2+1][0] = r1;
                bh[nf2*2][1] = r2; bh[nf2*2+1][1] = r3;
                ldsm4(r0, r1, r2, r3, st + OFF_BL + rb);
                bl[nf2*2][0] = r0; bl[nf2*2+1][0] = r1;
                bl[nf2*2][1] = r2; bl[nf2*2+1][1] = r3;
            }
            #pragma unroll
            for (int mf = 0; mf < 4; mf++)
                #pragma unroll
                for (int nf = 0; nf < 4; nf++)
                    mma16816(acc[mf][nf], ah[mf], bh[nf]);   // A*Bh
            #pragma unroll
            for (int mf = 0; mf < 4; mf++)
                #pragma unroll
                for (int nf = 0; nf < 4; nf++)
                    mma16816(acc[mf][nf], ah[mf], bl[nf]);   // A*Bl
        }
    }

    const int rg = lane >> 2;
    const int cp = (lane & 3) * 2;
    #pragma unroll
    for (int mf = 0; mf < 4; mf++) {
        #pragma unroll
        for (int nf = 0; nf < 4; nf++) {
            const int col = col0 + wn * 32 + nf * 8 + cp;
            float b0 = 0.f, b1 = 0.f;
            if (ADD_BIAS) { b0 = bias[col]; b1 = bias[col + 1]; }
            const int r0 = row0 + wm * 64 + mf * 16 + rg;
            *reinterpret_cast<float2*>(&C[(size_t)r0 * Nd + col]) =
                make_float2(acc[mf][nf][0] + b0, acc[mf][nf][1] + b1);
            *reinterpret_cast<float2*>(&C[(size_t)(r0 + 8) * Nd + col]) =
                make_float2(acc[mf][nf][2] + b0, acc[mf][nf][3] + b1);
        }
    }
}

// ---------------------------------------------------------------------------
// feat via mma.sync, FUSED z-split: loads q/k fp32 tile straight from g_qkv,
// computes sqnorm + fp16 hi/lo split in-kernel (no global z round-trip).
// logits[128n x 128m] = z[128 x 64] @ Rt[128m x 64]^T (3 product passes),
// phi = exp(logit - sqn) * minv.  Grid: (BH, NSEQ/128, 2) — z=0: q, 1: k.
// smem chunk c (c=0,1 over K=64): sb + c*4*TILE_B, order {zh, zl, rh, rl}.
// ---------------------------------------------------------------------------
#define FEAT_DYN_SMEM (8 * TILE_B + 512)

__global__ __launch_bounds__(256) void feat_mma()
{
    const uint32_t sb = smem_to_u32(dyn_smem);
    float* sqs = dyn_smem + (8 * TILE_B) / 4;
    const int tid  = threadIdx.x;
    const int wid  = tid >> 5, lane = tid & 31;
    const int wm   = wid & 1;
    const int wn   = wid >> 1;
    const int bh = blockIdx.x, b = bh / HDIM, h = bh % HDIM;
    const int n0 = blockIdx.y * 128;
    const int isk = blockIdx.z;

    const __half* rh = g_rth + (size_t)h * MDIM * DDIM;
    const __half* rl = g_rtl + (size_t)h * MDIM * DDIM;
    float* outp = (isk ? g_kf : g_qf) + ((size_t)bh * NSEQ + n0) * MDIM;

    // R tiles via cp.async (both K-chunks)
    #pragma unroll
    for (int c = 0; c < 2; c++) {
        const uint32_t st = sb + c * 4 * TILE_B;
        stage_tile(st + 2 * TILE_B, rh, DDIM, c * 32, tid);
        stage_tile(st + 3 * TILE_B, rl, DDIM, c * 32, tid);
    }
    CP_COMMIT();

    // z tiles: load fp32 q/k from g_qkv, sqnorm + split, write smem directly.
    // thread t covers (row r = pass*16 + t/16, d4 = (t%16)*4); 8 passes.
    {
        const int tr16 = tid >> 4, td4 = (tid & 15) * 4;
        const float sq = 0.3535533905932738f;   // 64^-0.25
        #pragma unroll
        for (int pass = 0; pass < 8; pass++) {
            const int r = pass * 16 + tr16;
            const size_t base = (size_t)(b * NSEQ + n0 + r) * (3 * CDIM)
                              + (size_t)isk * CDIM + h * DDIM + td4;
            float4 v = *reinterpret_cast<const float4*>(&g_qkv[base]);
            v.x *= sq; v.y *= sq; v.z *= sq; v.w *= sq;
            float ss = v.x * v.x + v.y * v.y + v.z * v.z + v.w * v.w;
            #pragma unroll
            for (int s = 8; s > 0; s >>= 1)
                ss += __shfl_xor_sync(0xFFFFFFFFu, ss, s);
            if ((lane & 15) == 0) sqs[r] = 0.5f * ss;

            __half h0,l0,h1,l1,h2,l2,h3,l3;
            split1h(v.x, h0, l0); split1h(v.y, h1, l1);
            split1h(v.z, h2, l2); split1h(v.w, h3, l3);
            const int cidx = td4 >> 5, col = td4 & 31;
            const uint32_t zb = sb + cidx * 4 * TILE_B + r * PITCHB + col * 2;
            __half2 ph0 = __halves2half2(h0, h1), ph1 = __halves2half2(h2, h3);
            __half2 pl0 = __halves2half2(l0, l1), pl1 = __halves2half2(l2, l3);
            asm volatile("st.shared.v2.b32 [%0], {%1, %2};"
                :: "r"(zb), "r"(*reinterpret_cast<uint32_t*>(&ph0)),
                   "r"(*reinterpret_cast<uint32_t*>(&ph1)));
            asm volatile("st.shared.v2.b32 [%0], {%1, %2};"
                :: "r"(zb + TILE_B), "r"(*reinterpret_cast<uint32_t*>(&pl0)),
                   "r"(*reinterpret_cast<uint32_t*>(&pl1)));
        }
    }
    CP_WAIT(0);
    __syncthreads();

    const int t8   = lane & 7;
    const int g01  = (lane >> 3) & 1;
    const int g2   = lane >> 4;
    const int mrow = g01 * 8 + t8;
    const int kofw = g2 * 8;

    float acc[4][4][4];
    #pragma unroll
    for (int i = 0; i < 4; i++)
        #pragma unroll
        for (int j = 0; j < 4; j++)
            #pragma unroll
            for (int r = 0; r < 4; r++) acc[i][j][r] = 0.f;

    #pragma unroll
    for (int c = 0; c < 2; c++) {
        const uint32_t st = sb + c * 4 * TILE_B;
        #pragma unroll
        for (int ks = 0; ks < 2; ks++) {
            const uint32_t kb = ks * 32 + kofw * 2;
            uint32_t ah[4][4], al[4][4];
            #pragma unroll
            for (int mf = 0; mf < 4; mf++) {
                const uint32_t ra = (wm * 64 + mf * 16 + mrow) * PITCHB + kb;
                ldsm4(ah[mf][0], ah[mf][1], ah[mf][2], ah[mf][3], st + 0 * TILE_B + ra);
                ldsm4(al[mf][0], al[mf][1], al[mf][2], al[mf][3], st + 1 * TILE_B + ra);
            }
            uint32_t bh2[4][2], bl2[4][2];
            #pragma unroll
            for (int nf2 = 0; nf2 < 2; nf2++) {
                const uint32_t rb = (wn * 32 + nf2 * 16 + mrow) * PITCHB + kb;
                uint32_t r0, r1, r2, r3;
                ldsm4(r0, r1, r2, r3, st + 2 * TILE_B + rb);
                bh2[nf2*2][0] = r0; bh2[nf2*2+1][0] = r1;
                bh2[nf2*2][1] = r2; bh2[nf2*2+1][1] = r3;
                ldsm4(r0, r1, r2, r3, st + 3 * TILE_B + rb);
                bl2[nf2*2][0] = r0; bl2[nf2*2+1][0] = r1;
                bl2[nf2*2][1] = r2; bl2[nf2*2+1][1] = r3;
            }
            #pragma unroll
            for (int mf = 0; mf < 4; mf++)
                #pragma unroll
                for (int nf = 0; nf < 4; nf++)
                    mma16816(acc[mf][nf], ah[mf], bh2[nf]);  // zh*Rh
            #pragma unroll
            for (int mf = 0; mf < 4; mf++)
                #pragma unroll
                for (int nf = 0; nf < 4; nf++)
                    mma16816(acc[mf][nf], ah[mf], bl2[nf]);  // zh*Rl
            #pragma unroll
            for (int mf = 0; mf < 4; mf++)
                #pragma unroll
                for (int nf = 0; nf < 4; nf++)
                    mma16816(acc[mf][nf], al[mf], bh2[nf]);  // zl*Rh
        }
    }

    const float minv = 0.08838834764831845f;   // 128^-0.5
    const int rg = lane >> 2;
    const int cp = (lane & 3) * 2;
    #pragma unroll
    for (int mf = 0; mf < 4; mf++) {
        const int r0 = wm * 64 + mf * 16 + rg;
        const float s0 = sqs[r0], s1 = sqs[r0 + 8];
        #pragma unroll
        for (int nf = 0; nf < 4; nf++) {
            const int col = wn * 32 + nf * 8 + cp;
            *reinterpret_cast<float2*>(&outp[(size_t)r0 * MDIM + col]) =
                make_float2(expf(acc[mf][nf][0] - s0) * minv,
                            expf(acc[mf][nf][1] - s0) * minv);
            *reinterpret_cast<float2*>(&outp[(size_t)(r0 + 8) * MDIM + col]) =
                make_float2(expf(acc[mf][nf][2] - s1) * minv,
                            expf(acc[mf][nf][3] - s1) * minv);
        }
    }
}

// ---------------------------------------------------------------------------
// Partial KV + S (unchanged)
// ---------------------------------------------------------------------------
__global__ __launch_bounds__(256) void kv_kernel()
{
    const int bh = blockIdx.x;
    const int b  = bh / HDIM, h = bh % HDIM;
    const int p  = blockIdx.y;
    const int tm = threadIdx.x >> 4;
    const int td = threadIdx.x & 15;

    __shared__ float kfs[32][MDIM];
    __shared__ float vs [32][DDIM];

    ull acc[8][2];
    float s[8];
    #pragma unroll
    for (int i = 0; i < 8; i++) { s[i] = 0.f; acc[i][0] = acc[i][1] = 0ULL; }

    const int nbase = p * (NSEQ / NSPLIT);
    for (int n0 = nbase; n0 < nbase + NSEQ / NSPLIT; n0 += 32) {
        __syncthreads();
        #pragma unroll
        for (int i = threadIdx.x; i < 32 * MDIM / 4; i += 256) {
            const int nn = i >> 5, m4 = (i & 31) * 4;
            *reinterpret_cast<float4*>(&kfs[nn][m4]) =
                *reinterpret_cast<const float4*>(&g_kf[((size_t)bh * NSEQ + n0 + nn) * MDIM + m4]);
        }
        #pragma unroll
        for (int i = threadIdx.x; i < 32 * DDIM / 4; i += 256) {
            const int nn = i >> 4, d4 = (i & 15) * 4;
            *reinterpret_cast<float4*>(&vs[nn][d4]) =
                *reinterpret_cast<const float4*>(
                    &g_qkv[(size_t)(b * NSEQ + n0 + nn) * (3 * CDIM) + 2 * CDIM + h * DDIM + d4]);
        }
        __syncthreads();
        #pragma unroll 4
        for (int nn = 0; nn < 32; nn++) {
            float a[8];
            #pragma unroll
            for (int i = 0; i < 8; i++) a[i] = kfs[nn][tm * 8 + i];
            longlong2 bp = *reinterpret_cast<const longlong2*>(&vs[nn][td * 4]);
            #pragma unroll
            for (int i = 0; i < 8; i++) {
                const ull ad = pack_dup(a[i]);
                ffma2(acc[i][0], ad, (ull)bp.x);
                ffma2(acc[i][1], ad, (ull)bp.y);
                s[i] += a[i];
            }
        }
    }

    float* kvb = g_kvp + ((size_t)p * BH + bh) * KVSZ;
    #pragma unroll
    for (int i = 0; i < 8; i++) {
        const int m = tm * 8 + i;
        float2 p0 = unpack2(acc[i][0]), p1 = unpack2(acc[i][1]);
        *reinterpret_cast<float4*>(&kvb[m * DDIM + td * 4]) =
            make_float4(p0.x, p0.y, p1.x, p1.y);
        if (td == 0) kvb[MDIM * DDIM + m] = s[i];
    }
}

__global__ __launch_bounds__(256) void kv_reduce()
{
    const int i = blockIdx.x * 256 + threadIdx.x;
    if (i < BH * KVSZ) {
        float s = 0.f;
        #pragma unroll
        for (int pp = 0; pp < NSPLIT; pp++)
            s += g_kvp[(size_t)pp * (BH * KVSZ) + i];
        g_kv[i] = s;
    }
}

// ---------------------------------------------------------------------------
// out kernel: writes fp16 o directly (feeds proj GEMM)
// ---------------------------------------------------------------------------
#define QF_PITCH 132
#define OUT_SMEM_FLOATS (KVSZ + 64 * QF_PITCH)

__global__ __launch_bounds__(256) void out_kernel()
{
    float* osm = dyn_smem;   // [0,8192): KV  [8192,8320): S  [8320,..): qf
    const int bh = blockIdx.x;
    const int b  = bh / HDIM, h = bh % HDIM;
    const int n0 = blockIdx.y * 64;
    const int tr = threadIdx.x >> 4;
    const int tc = threadIdx.x & 15;

    const float* kvb = g_kv + (size_t)bh * KVSZ;
    #pragma unroll
    for (int i = threadIdx.x; i < KVSZ / 4; i += 256)
        *reinterpret_cast<float4*>(&osm[i * 4]) =
            *reinterpret_cast<const float4*>(&kvb[i * 4]);
    #pragma unroll
    for (int i = threadIdx.x; i < 64 * 32; i += 256) {
        const int r = i >> 5, d4 = (i & 31) * 4;
        *reinterpret_cast<float4*>(&osm[KVSZ + r * QF_PITCH + d4]) =
            *reinterpret_cast<const float4*>(&g_qf[((size_t)bh * NSEQ + n0 + r) * MDIM + d4]);
    }
    __syncthreads();

    ull acc[4][2];
    float den[4];
    #pragma unroll
    for (int i = 0; i < 4; i++) { den[i] = 0.f; acc[i][0] = acc[i][1] = 0ULL; }

    #pragma unroll 4
    for (int m = 0; m < MDIM; m++) {
        longlong2 kvp = *reinterpret_cast<const longlong2*>(&osm[m * DDIM + tc * 4]);
        const float sv = osm[MDIM * DDIM + m];
        #pragma unroll
        for (int i = 0; i < 4; i++) {
            const float q = osm[KVSZ + (tr * 4 + i) * QF_PITCH + m];
            const ull qd = pack_dup(q);
            ffma2(acc[i][0], qd, (ull)kvp.x);
            ffma2(acc[i][1], qd, (ull)kvp.y);
            den[i] += q * sv;
        }
    }

    #pragma unroll
    for (int i = 0; i < 4; i++) {
        const float inv = 1.0f / fmaxf(den[i], 1e-12f);
        const int n = n0 + tr * 4 + i;
        float2 p0 = unpack2(acc[i][0]), p1 = unpack2(acc[i][1]);
        __half2 o0 = __floats2half2_rn(p0.x * inv, p0.y * inv);
        __half2 o1 = __floats2half2_rn(p1.x * inv, p1.y * inv);
        const size_t o = (size_t)(b * NSEQ + n) * CDIM + h * DDIM + tc * 4;
        uint32_t* op = reinterpret_cast<uint32_t*>(&g_oh[o]);
        op[0] = *reinterpret_cast<uint32_t*>(&o0);
        op[1] = *reinterpret_cast<uint32_t*>(&o1);
    }
}

// ---------------------------------------------------------------------------
extern "C" void kernel_launch(void* const* d_in, const int* in_sizes, int n_in,
                              void* d_out, int out_size)
{
    const float* x      = (const float*)d_in[0];
    const float* qkv_w  = (const float*)d_in[1];
    const float* proj_w = (const float*)d_in[2];
    const float* proj_b = (const float*)d_in[3];
    const float* randm  = (const float*)d_in[4];
    float* out = (float*)d_out;

    float *p_qkv;
    cudaGetSymbolAddress((void**)&p_qkv, g_qkv);
    __half *p_xh, *p_qwh, *p_qwl, *p_pwh, *p_pwl, *p_oh;
    cudaGetSymbolAddress((void**)&p_xh,  g_xh);
    cudaGetSymbolAddress((void**)&p_qwh, g_qwh);
    cudaGetSymbolAddress((void**)&p_qwl, g_qwl);
    cudaGetSymbolAddress((void**)&p_pwh, g_pwh);
    cudaGetSymbolAddress((void**)&p_pwl, g_pwl);
    cudaGetSymbolAddress((void**)&p_oh,  g_oh);

    cudaFuncSetAttribute(out_kernel, cudaFuncAttributeMaxDynamicSharedMemorySize,
                         OUT_SMEM_FLOATS * 4);
    cudaFuncSetAttribute(mma_gemm<false>, cudaFuncAttributeMaxDynamicSharedMemorySize,
                         GEMM_DYN_SMEM);
    cudaFuncSetAttribute(mma_gemm<true>, cudaFuncAttributeMaxDynamicSharedMemorySize,
                         GEMM_DYN_SMEM);
    cudaFuncSetAttribute(feat_mma, cudaFuncAttributeMaxDynamicSharedMemorySize,
                         FEAT_DYN_SMEM);

    // 0) conversions: x -> fp16; weights -> fp16 hi/lo; R -> Rt hi/lo
    {
        const int n4x = BNTOK * CDIM / 4;
        tohalf_kernel<<<(n4x + 255) / 256, 256>>>(
            (const float4*)x, (uint32_t*)p_xh, n4x);
        const int n4q = 3 * CDIM * CDIM / 4;
        splith_kernel<<<(n4q + 255) / 256, 256>>>(
            (const float4*)qkv_w, (uint32_t*)p_qwh, (uint32_t*)p_qwl, n4q);
        const int n4p = CDIM * CDIM / 4;
        splith_kernel<<<(n4p + 255) / 256, 256>>>(
            (const float4*)proj_w, (uint32_t*)p_pwh, (uint32_t*)p_pwl, n4p);
        dim3 rg(HDIM, 8);
        rt_split_kernel<<<rg, 256>>>(randm);
    }
    // 1) qkv = x @ qkv_w^T : [8192, 2304] via fp16x2 mma.sync
    {
        dim3 grid(3 * CDIM / 128, BNTOK / 128);
        mma_gemm<false><<<grid, 256, GEMM_DYN_SMEM>>>(
            p_xh, p_qwh, p_qwl, nullptr, p_qkv, 3 * CDIM, CDIM);
    }
    // 2) feature maps: fused z-split + MMA + exp
    {
        dim3 grid(BH, NSEQ / 128, 2);
        feat_mma<<<grid, 256, FEAT_DYN_SMEM>>>();
    }
    // 3) KV + S partial reduction, then merge
    {
        dim3 grid(BH, NSPLIT);
        kv_kernel<<<grid, 256>>>();
        kv_reduce<<<(BH * KVSZ + 255) / 256, 256>>>();
    }
    // 4) normalized output -> fp16 [b, n, c]
    {
        dim3 grid(BH, NSEQ / 64);
        out_kernel<<<grid, 256, OUT_SMEM_FLOATS * 4>>>();
    }
    // 5) final projection + bias -> d_out via fp16x2 mma.sync
    {
        dim3 grid(CDIM / 128, BNTOK / 128);
        mma_gemm<true><<<grid, 256, GEMM_DYN_SMEM>>>(
            p_oh, p_pwh, p_pwl, proj_b, out, CDIM, CDIM);
    }
}